// round 2
// baseline (speedup 1.0000x reference)
#include <cuda_runtime.h>
#include <math.h>

#define HH 76
#define WW 120
#define HW 9120
#define AA 9
#define NANCH 82080
#define CIN 1024
#define KC 9216
#define TOPN 300
#define FCD 2048
#define KFC 50176
#define SPLITK 8
#define NB_RED 256

__device__ float g_rpn[512 * HW];
__device__ float g_cls[18 * HW];
__device__ float g_bbox[36 * HW];
__device__ unsigned int g_key[NANCH];
__device__ float g_boxes[NANCH * 4];
__device__ int g_hist[65536];
__device__ int g_thr_bin;
__device__ int g_cand_cnt;
__device__ unsigned int g_ckey[NANCH];
__device__ int g_cidx[NANCH];
__device__ float g_rois[TOPN * 4];
__device__ float g_feat_t[HW * CIN];
__device__ float g_pooled[TOPN * KFC];
__device__ float g_fcp[SPLITK * 384 * FCD];
__device__ float g_fc7[TOPN * FCD];
__device__ float g_ce2[TOPN];
__device__ float g_lbrow[TOPN];
__device__ float g_red_ce[NB_RED];
__device__ float g_red_cnt[NB_RED];
__device__ float g_red_lb[NB_RED];

__global__ void k_zero() {
    int i = blockIdx.x * blockDim.x + threadIdx.x;
    if (i < 65536) g_hist[i] = 0;
    if (i == 0) g_cand_cnt = 0;
}

__global__ void __launch_bounds__(256) k_conv3x3(const float* __restrict__ X,
                                                 const float* __restrict__ Wt,
                                                 const float* __restrict__ bias) {
    __shared__ float As[16][128];
    __shared__ float Bs[16][128];
    int tid = threadIdx.x;
    int m0 = blockIdx.y * 128, n0 = blockIdx.x * 128;
    int bn = tid & 127, bk8 = tid >> 7;
    int p = n0 + bn;
    bool pv = p < HW;
    int py = p / WW, px = p - (p / WW) * WW;
    int tm = tid >> 4, tn = tid & 15;
    float acc[8][8];
#pragma unroll
    for (int i = 0; i < 8; i++)
#pragma unroll
        for (int j = 0; j < 8; j++) acc[i][j] = 0.f;
    for (int k0 = 0; k0 < KC; k0 += 16) {
#pragma unroll
        for (int i = 0; i < 2; i++) {
            int s = tid * 2 + i, m = s >> 2, k = (s & 3) * 4;
            float4 v = *reinterpret_cast<const float4*>(&Wt[(size_t)(m0 + m) * KC + k0 + k]);
            As[k][m] = v.x; As[k + 1][m] = v.y; As[k + 2][m] = v.z; As[k + 3][m] = v.w;
        }
#pragma unroll
        for (int j = 0; j < 8; j++) {
            int k = bk8 * 8 + j, kg = k0 + k;
            int ci = kg / 9, t9 = kg - ci * 9, t3 = t9 / 3;
            int yy = py + t3 - 1, xx = px + (t9 - t3 * 3 - 1);
            float v = 0.f;
            if (pv && (unsigned)yy < HH && (unsigned)xx < WW)
                v = X[(size_t)ci * HW + yy * WW + xx];
            Bs[k][bn] = v;
        }
        __syncthreads();
#pragma unroll
        for (int kk = 0; kk < 16; kk++) {
            float a[8], b[8];
#pragma unroll
            for (int i = 0; i < 8; i++) a[i] = As[kk][tm * 8 + i];
#pragma unroll
            for (int j = 0; j < 8; j++) b[j] = Bs[kk][tn * 8 + j];
#pragma unroll
            for (int i = 0; i < 8; i++)
#pragma unroll
                for (int j = 0; j < 8; j++) acc[i][j] = fmaf(a[i], b[j], acc[i][j]);
        }
        __syncthreads();
    }
#pragma unroll
    for (int i = 0; i < 8; i++) {
        int m = m0 + tm * 8 + i;
        float bv = bias[m];
#pragma unroll
        for (int j = 0; j < 8; j++) {
            int pp = n0 + tn * 8 + j;
            if (pp < HW) {
                float v = acc[i][j] + bv;
                g_rpn[(size_t)m * HW + pp] = v > 0.f ? v : 0.f;
            }
        }
    }
}

__global__ void __launch_bounds__(128) k_conv1x1(const float* __restrict__ cw,
                                                 const float* __restrict__ cb,
                                                 const float* __restrict__ bw,
                                                 const float* __restrict__ bb) {
    __shared__ float ws[27 * 128];
    int tid = threadIdx.x;
    int p = blockIdx.x * 128 + tid;
    bool pv = p < HW;
    int half = blockIdx.y;
    float acc[27];
#pragma unroll
    for (int c = 0; c < 27; c++) {
        int oc = half * 27 + c;
        acc[c] = (oc < 18) ? cb[oc] : bb[oc - 18];
    }
    for (int kc = 0; kc < 512; kc += 128) {
        __syncthreads();
#pragma unroll
        for (int c = 0; c < 27; c++) {
            int oc = half * 27 + c;
            ws[c * 128 + tid] = (oc < 18) ? cw[oc * 512 + kc + tid] : bw[(oc - 18) * 512 + kc + tid];
        }
        __syncthreads();
        for (int k = 0; k < 128; k++) {
            float rv = pv ? g_rpn[(size_t)(kc + k) * HW + p] : 0.f;
#pragma unroll
            for (int c = 0; c < 27; c++) acc[c] = fmaf(rv, ws[c * 128 + k], acc[c]);
        }
    }
    if (pv) {
#pragma unroll
        for (int c = 0; c < 27; c++) {
            int oc = half * 27 + c;
            if (oc < 18) g_cls[oc * HW + p] = acc[c];
            else g_bbox[(oc - 18) * HW + p] = acc[c];
        }
    }
}

__global__ void k_fgboxes(const float* __restrict__ anchors) {
    int i = blockIdx.x * blockDim.x + threadIdx.x;
    if (i >= NANCH) return;
    int p = i / AA, a = i - p * AA;
    float s0 = g_cls[a * HW + p], s1 = g_cls[(9 + a) * HW + p];
    float m = fmaxf(s0, s1);
    float e0 = expf(s0 - m), e1 = expf(s1 - m);
    float fg = e1 / (e0 + e1);
    unsigned int u = __float_as_uint(fg);
    u = (u & 0x80000000u) ? ~u : (u | 0x80000000u);
    g_key[i] = u;
    atomicAdd(&g_hist[u >> 16], 1);
    float ax1 = anchors[i * 4], ay1 = anchors[i * 4 + 1];
    float ax2 = anchors[i * 4 + 2], ay2 = anchors[i * 4 + 3];
    float aw = ax2 - ax1 + 1.f, ah = ay2 - ay1 + 1.f;
    float acx = ax1 + 0.5f * aw, acy = ay1 + 0.5f * ah;
    float dx = g_bbox[(4 * a) * HW + p], dy = g_bbox[(4 * a + 1) * HW + p];
    float dw = g_bbox[(4 * a + 2) * HW + p], dh = g_bbox[(4 * a + 3) * HW + p];
    float pcx = dx * aw + acx, pcy = dy * ah + acy;
    float pw = expf(dw) * aw, ph = expf(dh) * ah;
    g_boxes[i * 4 + 0] = fminf(fmaxf(pcx - 0.5f * pw, 0.f), 1919.f);
    g_boxes[i * 4 + 1] = fminf(fmaxf(pcy - 0.5f * ph, 0.f), 1215.f);
    g_boxes[i * 4 + 2] = fminf(fmaxf(pcx + 0.5f * pw, 0.f), 1919.f);
    g_boxes[i * 4 + 3] = fminf(fmaxf(pcy + 0.5f * ph, 0.f), 1215.f);
}

__global__ void k_scan() {
    __shared__ int cs[256];
    int t = threadIdx.x;
    int s = 0;
    for (int j = 0; j < 256; j++) s += g_hist[t * 256 + j];
    cs[t] = s;
    __syncthreads();
    if (t == 0) {
        int acc = 0, chunk = 0;
        for (int i = 255; i >= 0; i--) {
            if (acc + cs[i] >= TOPN) { chunk = i; break; }
            acc += cs[i];
        }
        int T = chunk * 256;
        for (int b = chunk * 256 + 255; b >= chunk * 256; b--) {
            if (acc + g_hist[b] >= TOPN) { T = b; break; }
            acc += g_hist[b];
        }
        g_thr_bin = T;
    }
}

__global__ void k_compact() {
    int i = blockIdx.x * blockDim.x + threadIdx.x;
    if (i >= NANCH) return;
    unsigned int u = g_key[i];
    if ((int)(u >> 16) >= g_thr_bin) {
        int pos = atomicAdd(&g_cand_cnt, 1);
        g_ckey[pos] = u;
        g_cidx[pos] = i;
    }
}

__global__ void k_rank() {
    int c = g_cand_cnt;
    int i = blockIdx.x * blockDim.x + threadIdx.x;
    if (i >= c) return;
    unsigned int ki = g_ckey[i];
    int di = g_cidx[i];
    int rank = 0;
    for (int j = 0; j < c; j++) {
        unsigned int kj = g_ckey[j];
        if (kj > ki || (kj == ki && g_cidx[j] < di)) rank++;
    }
    if (rank < TOPN) {
        g_rois[rank * 4 + 0] = g_boxes[di * 4 + 0];
        g_rois[rank * 4 + 1] = g_boxes[di * 4 + 1];
        g_rois[rank * 4 + 2] = g_boxes[di * 4 + 2];
        g_rois[rank * 4 + 3] = g_boxes[di * 4 + 3];
    }
}

__global__ void k_transpose(const float* __restrict__ X) {
    __shared__ float tile[32][33];
    int tx = threadIdx.x, ty = threadIdx.y;
    int p0 = blockIdx.x * 32, c0 = blockIdx.y * 32;
#pragma unroll
    for (int j = 0; j < 32; j += 8) tile[ty + j][tx] = X[(size_t)(c0 + ty + j) * HW + p0 + tx];
    __syncthreads();
#pragma unroll
    for (int j = 0; j < 32; j += 8)
        g_feat_t[(size_t)(p0 + ty + j) * CIN + c0 + tx] = tile[tx][ty + j];
}

__global__ void __launch_bounds__(256) k_roialign() {
    int r = blockIdx.y, q = blockIdx.x;
    int pyy = q / 7, pxx = q - pyy * 7;
    float x1 = g_rois[r * 4 + 0] * 0.0625f, y1 = g_rois[r * 4 + 1] * 0.0625f;
    float x2 = g_rois[r * 4 + 2] * 0.0625f, y2 = g_rois[r * 4 + 3] * 0.0625f;
    float xs = fminf(fmaxf(x1 + (x2 - x1) * ((pxx + 0.5f) / 7.f), 0.f), 119.f);
    float ys = fminf(fmaxf(y1 + (y2 - y1) * ((pyy + 0.5f) / 7.f), 0.f), 75.f);
    float x0f = floorf(xs), y0f = floorf(ys);
    int x0i = (int)x0f, y0i = (int)y0f;
    int x1i = min(x0i + 1, 119), y1i = min(y0i + 1, 75);
    float wx = xs - x0f, wy = ys - y0f;
    float w00 = (1.f - wy) * (1.f - wx), w01 = (1.f - wy) * wx;
    float w10 = wy * (1.f - wx), w11 = wy * wx;
    const float* f00 = &g_feat_t[(size_t)(y0i * WW + x0i) * CIN];
    const float* f01 = &g_feat_t[(size_t)(y0i * WW + x1i) * CIN];
    const float* f10 = &g_feat_t[(size_t)(y1i * WW + x0i) * CIN];
    const float* f11 = &g_feat_t[(size_t)(y1i * WW + x1i) * CIN];
    float* outp = &g_pooled[(size_t)r * KFC + q];
    for (int c = threadIdx.x; c < CIN; c += 256)
        outp[c * 49] = f00[c] * w00 + f01[c] * w01 + f10[c] * w10 + f11[c] * w11;
}

__global__ void __launch_bounds__(256) k_fcgemm(const float* __restrict__ Bw) {
    __shared__ float As[16][128];
    __shared__ float Bs[16][128];
    int tid = threadIdx.x;
    int n0 = blockIdx.x * 128, m0 = blockIdx.y * 128;
    int kb = blockIdx.z * (KFC / SPLITK), ke = kb + KFC / SPLITK;
    int tm = tid >> 4, tn = tid & 15;
    float acc[8][8];
#pragma unroll
    for (int i = 0; i < 8; i++)
#pragma unroll
        for (int j = 0; j < 8; j++) acc[i][j] = 0.f;
    for (int k0 = kb; k0 < ke; k0 += 16) {
#pragma unroll
        for (int i = 0; i < 2; i++) {
            int s = tid * 2 + i, m = s >> 2, k = (s & 3) * 4;
            int gm = m0 + m;
            float4 v = make_float4(0.f, 0.f, 0.f, 0.f);
            if (gm < TOPN) v = *reinterpret_cast<const float4*>(&g_pooled[(size_t)gm * KFC + k0 + k]);
            As[k][m] = v.x; As[k + 1][m] = v.y; As[k + 2][m] = v.z; As[k + 3][m] = v.w;
        }
#pragma unroll
        for (int i = 0; i < 2; i++) {
            int s = tid + i * 256, k = s >> 5, nq = (s & 31) * 4;
            *reinterpret_cast<float4*>(&Bs[k][nq]) =
                *reinterpret_cast<const float4*>(&Bw[(size_t)(k0 + k) * FCD + n0 + nq]);
        }
        __syncthreads();
#pragma unroll
        for (int kk = 0; kk < 16; kk++) {
            float a[8], b[8];
#pragma unroll
            for (int i = 0; i < 8; i++) a[i] = As[kk][tm * 8 + i];
#pragma unroll
            for (int j = 0; j < 8; j++) b[j] = Bs[kk][tn * 8 + j];
#pragma unroll
            for (int i = 0; i < 8; i++)
#pragma unroll
                for (int j = 0; j < 8; j++) acc[i][j] = fmaf(a[i], b[j], acc[i][j]);
        }
        __syncthreads();
    }
#pragma unroll
    for (int i = 0; i < 8; i++) {
        int m = m0 + tm * 8 + i;
        if (m < TOPN) {
#pragma unroll
            for (int j = 0; j < 8; j++)
                g_fcp[((size_t)blockIdx.z * 384 + m) * FCD + n0 + tn * 8 + j] = acc[i][j];
        }
    }
}

__global__ void k_fcreduce(const float* __restrict__ fb) {
    int i = blockIdx.x * blockDim.x + threadIdx.x;
    if (i >= TOPN * FCD) return;
    int m = i / FCD, n = i - m * FCD;
    float s = fb[n];
#pragma unroll
    for (int z = 0; z < SPLITK; z++) s += g_fcp[((size_t)z * 384 + m) * FCD + n];
    g_fc7[i] = s > 0.f ? s : 0.f;
}

__global__ void __launch_bounds__(128) k_heads(const float* __restrict__ cw, const float* __restrict__ cb,
                                               const float* __restrict__ bw, const float* __restrict__ bb,
                                               const float* __restrict__ tgt, const float* __restrict__ biw,
                                               const float* __restrict__ bow, const int* __restrict__ lab) {
    __shared__ float sf[FCD];
    __shared__ float so[105];
    int r = blockIdx.x, t = threadIdx.x;
    for (int k = t; k < FCD; k += 128) sf[k] = g_fc7[(size_t)r * FCD + k];
    __syncthreads();
    if (t < 105) {
        float acc = (t < 21) ? cb[t] : bb[t - 21];
        if (t < 21) {
            for (int k = 0; k < FCD; k++) acc = fmaf(sf[k], cw[k * 21 + t], acc);
        } else {
            int o = t - 21;
            for (int k = 0; k < FCD; k++) acc = fmaf(sf[k], bw[k * 84 + o], acc);
        }
        so[t] = acc;
    }
    __syncthreads();
    if (t == 0) {
        float m = so[0];
        for (int c = 1; c < 21; c++) m = fmaxf(m, so[c]);
        float se = 0.f;
        for (int c = 0; c < 21; c++) se += expf(so[c] - m);
        float lse = m + logf(se);
        g_ce2[r] = lse - so[lab[r]];
        float lb = 0.f;
        for (int o = 0; o < 84; o++) {
            int idx = r * 84 + o;
            float d = biw[idx] * (so[21 + o] - tgt[idx]);
            float ad = fabsf(d);
            float loss = (ad < 1.f) ? d * d * 0.5f : (ad - 0.5f);
            lb += bow[idx] * loss;
        }
        g_lbrow[r] = lb;
    }
}

__global__ void __launch_bounds__(256) k_loss1(const int* __restrict__ lab, const float* __restrict__ tgt,
                                               const float* __restrict__ biw, const float* __restrict__ bow) {
    __shared__ float sce[256], scn[256], slb[256];
    int t = threadIdx.x;
    int gid = blockIdx.x * 256 + t;
    int stride = NB_RED * 256;
    float ce = 0.f, cn = 0.f, lb = 0.f;
    for (int e = gid; e < 36 * HW; e += stride) {
        int p = e / 36, c = e - p * 36;
        float d = biw[e] * (g_bbox[c * HW + p] - tgt[e]);
        float ad = fabsf(d);
        float loss = (ad < (1.f / 9.f)) ? d * d * 4.5f : (ad - 1.f / 18.f);
        lb += bow[e] * loss;
        if (e < NANCH) {
            int L = lab[e];
            if (L != -1) {
                int a = e / HW, pp = e - a * HW;
                float s0 = g_cls[a * HW + pp], s1 = g_cls[(9 + a) * HW + pp];
                float m = fmaxf(s0, s1);
                float lse = m + logf(expf(s0 - m) + expf(s1 - m));
                ce += lse - (L ? s1 : s0);
                cn += 1.f;
            }
        }
    }
    sce[t] = ce; scn[t] = cn; slb[t] = lb;
    __syncthreads();
    for (int o = 128; o > 0; o >>= 1) {
        if (t < o) { sce[t] += sce[t + o]; scn[t] += scn[t + o]; slb[t] += slb[t + o]; }
        __syncthreads();
    }
    if (t == 0) {
        g_red_ce[blockIdx.x] = sce[0];
        g_red_cnt[blockIdx.x] = scn[0];
        g_red_lb[blockIdx.x] = slb[0];
    }
}

__global__ void k_final(float* out) {
    if (threadIdx.x != 0) return;
    float ce = 0.f, cn = 0.f, lb = 0.f;
    for (int i = 0; i < NB_RED; i++) { ce += g_red_ce[i]; cn += g_red_cnt[i]; lb += g_red_lb[i]; }
    float ce2 = 0.f, lb2 = 0.f;
    for (int r = 0; r < TOPN; r++) { ce2 += g_ce2[r]; lb2 += g_lbrow[r]; }
    out[0] = ce / fmaxf(cn, 1.f) + lb + ce2 / TOPN + lb2 / TOPN;
}

extern "C" void kernel_launch(void* const* d_in, const int* in_sizes, int n_in,
                              void* d_out, int out_size) {
    const float* net_conv = (const float*)d_in[0];
    const float* rpn_w = (const float*)d_in[1];
    const float* rpn_b = (const float*)d_in[2];
    const float* rpn_cls_w = (const float*)d_in[3];
    const float* rpn_cls_b = (const float*)d_in[4];
    const float* rpn_bbox_w = (const float*)d_in[5];
    const float* rpn_bbox_b = (const float*)d_in[6];
    const float* fc_w = (const float*)d_in[7];
    const float* fc_b = (const float*)d_in[8];
    const float* cls_w = (const float*)d_in[9];
    const float* cls_b = (const float*)d_in[10];
    const float* bbox_w = (const float*)d_in[11];
    const float* bbox_b = (const float*)d_in[12];
    const float* anchors = (const float*)d_in[13];
    const float* rpn_tgt = (const float*)d_in[14];
    const float* rpn_biw = (const float*)d_in[15];
    const float* rpn_bow = (const float*)d_in[16];
    const float* roi_tgt = (const float*)d_in[17];
    const float* roi_biw = (const float*)d_in[18];
    const float* roi_bow = (const float*)d_in[19];
    const int* rpn_lab = (const int*)d_in[20];
    const int* roi_lab = (const int*)d_in[21];
    float* out = (float*)d_out;

    k_zero<<<256, 256>>>();
    k_conv3x3<<<dim3(72, 4), 256>>>(net_conv, rpn_w, rpn_b);
    k_conv1x1<<<dim3(72, 2), 128>>>(rpn_cls_w, rpn_cls_b, rpn_bbox_w, rpn_bbox_b);
    k_fgboxes<<<321, 256>>>(anchors);
    k_scan<<<1, 256>>>();
    k_compact<<<321, 256>>>();
    k_rank<<<321, 256>>>();
    k_transpose<<<dim3(285, 32), dim3(32, 8)>>>(net_conv);
    k_roialign<<<dim3(49, TOPN), 256>>>();
    k_fcgemm<<<dim3(16, 3, SPLITK), 256>>>(fc_w);
    k_fcreduce<<<(TOPN * FCD + 255) / 256, 256>>>(fc_b);
    k_heads<<<TOPN, 128>>>(cls_w, cls_b, bbox_w, bbox_b, roi_tgt, roi_biw, roi_bow, roi_lab);
    k_loss1<<<NB_RED, 256>>>(rpn_lab, rpn_tgt, rpn_biw, rpn_bow);
    k_final<<<1, 32>>>(out);
}

// round 3
// speedup vs baseline: 1.5043x; 1.5043x over previous
#include <cuda_runtime.h>
#include <cuda_bf16.h>
#include <math.h>

#define HH 76
#define WW 120
#define HW 9120
#define AA 9
#define NANCH 82080
#define CIN 1024
#define KC 9216
#define TOPN 300
#define FCD 2048
#define KFC 50176
#define ZSPLIT 4
#define KPZ (KFC / ZSPLIT)
#define NB_RED 256

__device__ float g_rpn[512 * HW];
__device__ float g_cls[18 * HW];
__device__ float g_bbox[36 * HW];
__device__ unsigned int g_key[NANCH];
__device__ float g_boxes[NANCH * 4];
__device__ int g_hist[65536];
__device__ int g_thr_bin;
__device__ int g_cand_cnt;
__device__ unsigned int g_ckey[NANCH];
__device__ int g_cidx[NANCH];
__device__ float g_rois[TOPN * 4];
__device__ float g_feat_t[HW * CIN];
__device__ __nv_bfloat16 g_pooledh[TOPN * KFC];
__device__ float g_fcp[ZSPLIT * 384 * FCD];
__device__ float g_fc7[TOPN * FCD];
__device__ float g_ce2[TOPN];
__device__ float g_lbrow[TOPN];
__device__ float g_red_ce[NB_RED];
__device__ float g_red_cnt[NB_RED];
__device__ float g_red_lb[NB_RED];

__global__ void k_zero() {
    int i = blockIdx.x * blockDim.x + threadIdx.x;
    if (i < 65536) g_hist[i] = 0;
    if (i == 0) g_cand_cnt = 0;
}

__global__ void __launch_bounds__(256) k_conv3x3(const float* __restrict__ X,
                                                 const float* __restrict__ Wt,
                                                 const float* __restrict__ bias) {
    __shared__ float As[16][128];
    __shared__ float Bs[16][128];
    int tid = threadIdx.x;
    int m0 = blockIdx.y * 128, n0 = blockIdx.x * 128;
    int bn = tid & 127, bk8 = tid >> 7;
    int p = n0 + bn;
    bool pv = p < HW;
    int py = p / WW, px = p - (p / WW) * WW;
    int tm = tid >> 4, tn = tid & 15;
    float acc[8][8];
#pragma unroll
    for (int i = 0; i < 8; i++)
#pragma unroll
        for (int j = 0; j < 8; j++) acc[i][j] = 0.f;
    for (int k0 = 0; k0 < KC; k0 += 16) {
#pragma unroll
        for (int i = 0; i < 2; i++) {
            int s = tid * 2 + i, m = s >> 2, k = (s & 3) * 4;
            float4 v = *reinterpret_cast<const float4*>(&Wt[(size_t)(m0 + m) * KC + k0 + k]);
            As[k][m] = v.x; As[k + 1][m] = v.y; As[k + 2][m] = v.z; As[k + 3][m] = v.w;
        }
#pragma unroll
        for (int j = 0; j < 8; j++) {
            int k = bk8 * 8 + j, kg = k0 + k;
            int ci = kg / 9, t9 = kg - ci * 9, t3 = t9 / 3;
            int yy = py + t3 - 1, xx = px + (t9 - t3 * 3 - 1);
            float v = 0.f;
            if (pv && (unsigned)yy < HH && (unsigned)xx < WW)
                v = X[(size_t)ci * HW + yy * WW + xx];
            Bs[k][bn] = v;
        }
        __syncthreads();
#pragma unroll
        for (int kk = 0; kk < 16; kk++) {
            float a[8], b[8];
#pragma unroll
            for (int i = 0; i < 8; i++) a[i] = As[kk][tm * 8 + i];
#pragma unroll
            for (int j = 0; j < 8; j++) b[j] = Bs[kk][tn * 8 + j];
#pragma unroll
            for (int i = 0; i < 8; i++)
#pragma unroll
                for (int j = 0; j < 8; j++) acc[i][j] = fmaf(a[i], b[j], acc[i][j]);
        }
        __syncthreads();
    }
#pragma unroll
    for (int i = 0; i < 8; i++) {
        int m = m0 + tm * 8 + i;
        float bv = bias[m];
#pragma unroll
        for (int j = 0; j < 8; j++) {
            int pp = n0 + tn * 8 + j;
            if (pp < HW) {
                float v = acc[i][j] + bv;
                g_rpn[(size_t)m * HW + pp] = v > 0.f ? v : 0.f;
            }
        }
    }
}

__global__ void __launch_bounds__(128) k_conv1x1(const float* __restrict__ cw,
                                                 const float* __restrict__ cb,
                                                 const float* __restrict__ bw,
                                                 const float* __restrict__ bb) {
    __shared__ float ws[27 * 128];
    int tid = threadIdx.x;
    int p = blockIdx.x * 128 + tid;
    bool pv = p < HW;
    int half = blockIdx.y;
    float acc[27];
#pragma unroll
    for (int c = 0; c < 27; c++) {
        int oc = half * 27 + c;
        acc[c] = (oc < 18) ? cb[oc] : bb[oc - 18];
    }
    for (int kc = 0; kc < 512; kc += 128) {
        __syncthreads();
#pragma unroll
        for (int c = 0; c < 27; c++) {
            int oc = half * 27 + c;
            ws[c * 128 + tid] = (oc < 18) ? cw[oc * 512 + kc + tid] : bw[(oc - 18) * 512 + kc + tid];
        }
        __syncthreads();
        for (int k = 0; k < 128; k++) {
            float rv = pv ? g_rpn[(size_t)(kc + k) * HW + p] : 0.f;
#pragma unroll
            for (int c = 0; c < 27; c++) acc[c] = fmaf(rv, ws[c * 128 + k], acc[c]);
        }
    }
    if (pv) {
#pragma unroll
        for (int c = 0; c < 27; c++) {
            int oc = half * 27 + c;
            if (oc < 18) g_cls[oc * HW + p] = acc[c];
            else g_bbox[(oc - 18) * HW + p] = acc[c];
        }
    }
}

__global__ void k_fgboxes(const float* __restrict__ anchors) {
    int i = blockIdx.x * blockDim.x + threadIdx.x;
    if (i >= NANCH) return;
    int p = i / AA, a = i - p * AA;
    float s0 = g_cls[a * HW + p], s1 = g_cls[(9 + a) * HW + p];
    float m = fmaxf(s0, s1);
    float e0 = expf(s0 - m), e1 = expf(s1 - m);
    float fg = e1 / (e0 + e1);
    unsigned int u = __float_as_uint(fg);
    u = (u & 0x80000000u) ? ~u : (u | 0x80000000u);
    g_key[i] = u;
    atomicAdd(&g_hist[u >> 16], 1);
    float ax1 = anchors[i * 4], ay1 = anchors[i * 4 + 1];
    float ax2 = anchors[i * 4 + 2], ay2 = anchors[i * 4 + 3];
    float aw = ax2 - ax1 + 1.f, ah = ay2 - ay1 + 1.f;
    float acx = ax1 + 0.5f * aw, acy = ay1 + 0.5f * ah;
    float dx = g_bbox[(4 * a) * HW + p], dy = g_bbox[(4 * a + 1) * HW + p];
    float dw = g_bbox[(4 * a + 2) * HW + p], dh = g_bbox[(4 * a + 3) * HW + p];
    float pcx = dx * aw + acx, pcy = dy * ah + acy;
    float pw = expf(dw) * aw, ph = expf(dh) * ah;
    g_boxes[i * 4 + 0] = fminf(fmaxf(pcx - 0.5f * pw, 0.f), 1919.f);
    g_boxes[i * 4 + 1] = fminf(fmaxf(pcy - 0.5f * ph, 0.f), 1215.f);
    g_boxes[i * 4 + 2] = fminf(fmaxf(pcx + 0.5f * pw, 0.f), 1919.f);
    g_boxes[i * 4 + 3] = fminf(fmaxf(pcy + 0.5f * ph, 0.f), 1215.f);
}

__global__ void k_scan() {
    __shared__ int cs[256];
    int t = threadIdx.x;
    int s = 0;
    for (int j = 0; j < 256; j++) s += g_hist[t * 256 + j];
    cs[t] = s;
    __syncthreads();
    if (t == 0) {
        int acc = 0, chunk = 0;
        for (int i = 255; i >= 0; i--) {
            if (acc + cs[i] >= TOPN) { chunk = i; break; }
            acc += cs[i];
        }
        int T = chunk * 256;
        for (int b = chunk * 256 + 255; b >= chunk * 256; b--) {
            if (acc + g_hist[b] >= TOPN) { T = b; break; }
            acc += g_hist[b];
        }
        g_thr_bin = T;
    }
}

__global__ void k_compact() {
    int i = blockIdx.x * blockDim.x + threadIdx.x;
    if (i >= NANCH) return;
    unsigned int u = g_key[i];
    if ((int)(u >> 16) >= g_thr_bin) {
        int pos = atomicAdd(&g_cand_cnt, 1);
        g_ckey[pos] = u;
        g_cidx[pos] = i;
    }
}

__global__ void k_rank() {
    int c = g_cand_cnt;
    int i = blockIdx.x * blockDim.x + threadIdx.x;
    if (i >= c) return;
    unsigned int ki = g_ckey[i];
    int di = g_cidx[i];
    int rank = 0;
    for (int j = 0; j < c; j++) {
        unsigned int kj = g_ckey[j];
        if (kj > ki || (kj == ki && g_cidx[j] < di)) rank++;
    }
    if (rank < TOPN) {
        g_rois[rank * 4 + 0] = g_boxes[di * 4 + 0];
        g_rois[rank * 4 + 1] = g_boxes[di * 4 + 1];
        g_rois[rank * 4 + 2] = g_boxes[di * 4 + 2];
        g_rois[rank * 4 + 3] = g_boxes[di * 4 + 3];
    }
}

__global__ void k_transpose(const float* __restrict__ X) {
    __shared__ float tile[32][33];
    int tx = threadIdx.x, ty = threadIdx.y;
    int p0 = blockIdx.x * 32, c0 = blockIdx.y * 32;
#pragma unroll
    for (int j = 0; j < 32; j += 8) tile[ty + j][tx] = X[(size_t)(c0 + ty + j) * HW + p0 + tx];
    __syncthreads();
#pragma unroll
    for (int j = 0; j < 32; j += 8)
        g_feat_t[(size_t)(p0 + ty + j) * CIN + c0 + tx] = tile[tx][ty + j];
}

__global__ void __launch_bounds__(256) k_roialign() {
    int r = blockIdx.y, q = blockIdx.x;
    int pyy = q / 7, pxx = q - pyy * 7;
    float x1 = g_rois[r * 4 + 0] * 0.0625f, y1 = g_rois[r * 4 + 1] * 0.0625f;
    float x2 = g_rois[r * 4 + 2] * 0.0625f, y2 = g_rois[r * 4 + 3] * 0.0625f;
    float xs = fminf(fmaxf(x1 + (x2 - x1) * ((pxx + 0.5f) / 7.f), 0.f), 119.f);
    float ys = fminf(fmaxf(y1 + (y2 - y1) * ((pyy + 0.5f) / 7.f), 0.f), 75.f);
    float x0f = floorf(xs), y0f = floorf(ys);
    int x0i = (int)x0f, y0i = (int)y0f;
    int x1i = min(x0i + 1, 119), y1i = min(y0i + 1, 75);
    float wx = xs - x0f, wy = ys - y0f;
    float w00 = (1.f - wy) * (1.f - wx), w01 = (1.f - wy) * wx;
    float w10 = wy * (1.f - wx), w11 = wy * wx;
    const float* f00 = &g_feat_t[(size_t)(y0i * WW + x0i) * CIN];
    const float* f01 = &g_feat_t[(size_t)(y0i * WW + x1i) * CIN];
    const float* f10 = &g_feat_t[(size_t)(y1i * WW + x0i) * CIN];
    const float* f11 = &g_feat_t[(size_t)(y1i * WW + x1i) * CIN];
    __nv_bfloat16* outp = &g_pooledh[(size_t)r * KFC + q];
    for (int c = threadIdx.x; c < CIN; c += 256) {
        float v = f00[c] * w00 + f01[c] * w01 + f10[c] * w10 + f11[c] * w11;
        outp[c * 49] = __float2bfloat16_rn(v);
    }
}

// FC GEMM: bf16 mma.sync, block tile 128(M)x128(N), warp tile 64x32, split-K=4
__global__ void __launch_bounds__(256) k_fcgemm(const float* __restrict__ Bw) {
    __shared__ __nv_bfloat16 Asm[128 * 40];   // [m][k] stride 40
    __shared__ __nv_bfloat16 Bks[32 * 132];   // [k][n] stride 132
    int tid = threadIdx.x;
    int lane = tid & 31, warp = tid >> 5;
    int n0 = blockIdx.x * 128, m0 = blockIdx.y * 128;
    int kz = blockIdx.z * KPZ;
    int wm = (warp >> 2) * 64;
    int wn = (warp & 3) * 32;
    int g = lane >> 2, tq = lane & 3;
    float c[4][4][4];
#pragma unroll
    for (int mt = 0; mt < 4; mt++)
#pragma unroll
        for (int nt = 0; nt < 4; nt++)
#pragma unroll
            for (int u = 0; u < 4; u++) c[mt][nt][u] = 0.f;

    for (int ks = 0; ks < KPZ; ks += 32) {
        // A fill: 128 rows x 32 bf16
#pragma unroll
        for (int u = 0; u < 2; u++) {
            int idx = tid * 2 + u;
            int r = idx >> 2, c8 = idx & 3;
            uint4 v = make_uint4(0, 0, 0, 0);
            int m = m0 + r;
            if (m < TOPN)
                v = *reinterpret_cast<const uint4*>(&g_pooledh[(size_t)m * KFC + kz + ks + c8 * 8]);
            *reinterpret_cast<uint4*>(&Asm[r * 40 + c8 * 8]) = v;
        }
        // B fill: 32 k-rows x 128 n (fp32 -> bf16)
#pragma unroll
        for (int i = 0; i < 4; i++) {
            int idx = i * 256 + tid;
            int k = idx >> 5, cc = idx & 31;
            float4 v = *reinterpret_cast<const float4*>(&Bw[(size_t)(kz + ks + k) * FCD + n0 + cc * 4]);
            __nv_bfloat162 p0 = __floats2bfloat162_rn(v.x, v.y);
            __nv_bfloat162 p1 = __floats2bfloat162_rn(v.z, v.w);
            uint2 st;
            st.x = *reinterpret_cast<unsigned*>(&p0);
            st.y = *reinterpret_cast<unsigned*>(&p1);
            *reinterpret_cast<uint2*>(&Bks[k * 132 + cc * 4]) = st;
        }
        __syncthreads();
#pragma unroll
        for (int ko = 0; ko < 32; ko += 16) {
            unsigned a[4][4];
#pragma unroll
            for (int mt = 0; mt < 4; mt++) {
                const __nv_bfloat16* ap = &Asm[(wm + mt * 16 + g) * 40 + ko + tq * 2];
                a[mt][0] = *reinterpret_cast<const unsigned*>(ap);
                a[mt][1] = *reinterpret_cast<const unsigned*>(ap + 8 * 40);
                a[mt][2] = *reinterpret_cast<const unsigned*>(ap + 8);
                a[mt][3] = *reinterpret_cast<const unsigned*>(ap + 8 * 40 + 8);
            }
            unsigned b[4][2];
#pragma unroll
            for (int nt = 0; nt < 4; nt++) {
                int n = wn + nt * 8 + g;
                unsigned lo0 = *reinterpret_cast<const unsigned short*>(&Bks[(ko + tq * 2) * 132 + n]);
                unsigned hi0 = *reinterpret_cast<const unsigned short*>(&Bks[(ko + tq * 2 + 1) * 132 + n]);
                b[nt][0] = lo0 | (hi0 << 16);
                unsigned lo1 = *reinterpret_cast<const unsigned short*>(&Bks[(ko + tq * 2 + 8) * 132 + n]);
                unsigned hi1 = *reinterpret_cast<const unsigned short*>(&Bks[(ko + tq * 2 + 9) * 132 + n]);
                b[nt][1] = lo1 | (hi1 << 16);
            }
#pragma unroll
            for (int mt = 0; mt < 4; mt++)
#pragma unroll
                for (int nt = 0; nt < 4; nt++) {
                    asm volatile(
                        "mma.sync.aligned.m16n8k16.row.col.f32.bf16.bf16.f32 "
                        "{%0,%1,%2,%3}, {%4,%5,%6,%7}, {%8,%9}, {%0,%1,%2,%3};"
                        : "+f"(c[mt][nt][0]), "+f"(c[mt][nt][1]),
                          "+f"(c[mt][nt][2]), "+f"(c[mt][nt][3])
                        : "r"(a[mt][0]), "r"(a[mt][1]), "r"(a[mt][2]), "r"(a[mt][3]),
                          "r"(b[nt][0]), "r"(b[nt][1]));
                }
        }
        __syncthreads();
    }
#pragma unroll
    for (int mt = 0; mt < 4; mt++) {
#pragma unroll
        for (int nt = 0; nt < 4; nt++) {
            int m = m0 + wm + mt * 16 + g;
            int n = n0 + wn + nt * 8 + tq * 2;
            if (m < TOPN) {
                float2 v = make_float2(c[mt][nt][0], c[mt][nt][1]);
                *reinterpret_cast<float2*>(&g_fcp[((size_t)blockIdx.z * 384 + m) * FCD + n]) = v;
            }
            if (m + 8 < TOPN) {
                float2 v = make_float2(c[mt][nt][2], c[mt][nt][3]);
                *reinterpret_cast<float2*>(&g_fcp[((size_t)blockIdx.z * 384 + m + 8) * FCD + n]) = v;
            }
        }
    }
}

__global__ void k_fcreduce(const float* __restrict__ fb) {
    int i = blockIdx.x * blockDim.x + threadIdx.x;
    if (i >= TOPN * FCD) return;
    int m = i / FCD, n = i - m * FCD;
    float s = fb[n];
#pragma unroll
    for (int z = 0; z < ZSPLIT; z++) s += g_fcp[((size_t)z * 384 + m) * FCD + n];
    g_fc7[i] = s > 0.f ? s : 0.f;
}

__global__ void __launch_bounds__(128) k_heads(const float* __restrict__ cw, const float* __restrict__ cb,
                                               const float* __restrict__ bw, const float* __restrict__ bb,
                                               const float* __restrict__ tgt, const float* __restrict__ biw,
                                               const float* __restrict__ bow, const int* __restrict__ lab) {
    __shared__ float sf[FCD];
    __shared__ float so[105];
    int r = blockIdx.x, t = threadIdx.x;
    for (int k = t; k < FCD; k += 128) sf[k] = g_fc7[(size_t)r * FCD + k];
    __syncthreads();
    if (t < 105) {
        float acc = (t < 21) ? cb[t] : bb[t - 21];
        if (t < 21) {
            for (int k = 0; k < FCD; k++) acc = fmaf(sf[k], cw[k * 21 + t], acc);
        } else {
            int o = t - 21;
            for (int k = 0; k < FCD; k++) acc = fmaf(sf[k], bw[k * 84 + o], acc);
        }
        so[t] = acc;
    }
    __syncthreads();
    if (t == 0) {
        float m = so[0];
        for (int c = 1; c < 21; c++) m = fmaxf(m, so[c]);
        float se = 0.f;
        for (int c = 0; c < 21; c++) se += expf(so[c] - m);
        float lse = m + logf(se);
        g_ce2[r] = lse - so[lab[r]];
        float lb = 0.f;
        for (int o = 0; o < 84; o++) {
            int idx = r * 84 + o;
            float d = biw[idx] * (so[21 + o] - tgt[idx]);
            float ad = fabsf(d);
            float loss = (ad < 1.f) ? d * d * 0.5f : (ad - 0.5f);
            lb += bow[idx] * loss;
        }
        g_lbrow[r] = lb;
    }
}

__global__ void __launch_bounds__(256) k_loss1(const int* __restrict__ lab, const float* __restrict__ tgt,
                                               const float* __restrict__ biw, const float* __restrict__ bow) {
    __shared__ float sce[256], scn[256], slb[256];
    int t = threadIdx.x;
    int gid = blockIdx.x * 256 + t;
    int stride = NB_RED * 256;
    float ce = 0.f, cn = 0.f, lb = 0.f;
    for (int e = gid; e < 36 * HW; e += stride) {
        int p = e / 36, c = e - p * 36;
        float d = biw[e] * (g_bbox[c * HW + p] - tgt[e]);
        float ad = fabsf(d);
        float loss = (ad < (1.f / 9.f)) ? d * d * 4.5f : (ad - 1.f / 18.f);
        lb += bow[e] * loss;
        if (e < NANCH) {
            int L = lab[e];
            if (L != -1) {
                int a = e / HW, pp = e - a * HW;
                float s0 = g_cls[a * HW + pp], s1 = g_cls[(9 + a) * HW + pp];
                float m = fmaxf(s0, s1);
                float lse = m + logf(expf(s0 - m) + expf(s1 - m));
                ce += lse - (L ? s1 : s0);
                cn += 1.f;
            }
        }
    }
    sce[t] = ce; scn[t] = cn; slb[t] = lb;
    __syncthreads();
    for (int o = 128; o > 0; o >>= 1) {
        if (t < o) { sce[t] += sce[t + o]; scn[t] += scn[t + o]; slb[t] += slb[t + o]; }
        __syncthreads();
    }
    if (t == 0) {
        g_red_ce[blockIdx.x] = sce[0];
        g_red_cnt[blockIdx.x] = scn[0];
        g_red_lb[blockIdx.x] = slb[0];
    }
}

__global__ void k_final(float* out) {
    if (threadIdx.x != 0) return;
    float ce = 0.f, cn = 0.f, lb = 0.f;
    for (int i = 0; i < NB_RED; i++) { ce += g_red_ce[i]; cn += g_red_cnt[i]; lb += g_red_lb[i]; }
    float ce2 = 0.f, lb2 = 0.f;
    for (int r = 0; r < TOPN; r++) { ce2 += g_ce2[r]; lb2 += g_lbrow[r]; }
    out[0] = ce / fmaxf(cn, 1.f) + lb + ce2 / TOPN + lb2 / TOPN;
}

extern "C" void kernel_launch(void* const* d_in, const int* in_sizes, int n_in,
                              void* d_out, int out_size) {
    const float* net_conv = (const float*)d_in[0];
    const float* rpn_w = (const float*)d_in[1];
    const float* rpn_b = (const float*)d_in[2];
    const float* rpn_cls_w = (const float*)d_in[3];
    const float* rpn_cls_b = (const float*)d_in[4];
    const float* rpn_bbox_w = (const float*)d_in[5];
    const float* rpn_bbox_b = (const float*)d_in[6];
    const float* fc_w = (const float*)d_in[7];
    const float* fc_b = (const float*)d_in[8];
    const float* cls_w = (const float*)d_in[9];
    const float* cls_b = (const float*)d_in[10];
    const float* bbox_w = (const float*)d_in[11];
    const float* bbox_b = (const float*)d_in[12];
    const float* anchors = (const float*)d_in[13];
    const float* rpn_tgt = (const float*)d_in[14];
    const float* rpn_biw = (const float*)d_in[15];
    const float* rpn_bow = (const float*)d_in[16];
    const float* roi_tgt = (const float*)d_in[17];
    const float* roi_biw = (const float*)d_in[18];
    const float* roi_bow = (const float*)d_in[19];
    const int* rpn_lab = (const int*)d_in[20];
    const int* roi_lab = (const int*)d_in[21];
    float* out = (float*)d_out;

    k_zero<<<256, 256>>>();
    k_conv3x3<<<dim3(72, 4), 256>>>(net_conv, rpn_w, rpn_b);
    k_conv1x1<<<dim3(72, 2), 128>>>(rpn_cls_w, rpn_cls_b, rpn_bbox_w, rpn_bbox_b);
    k_fgboxes<<<321, 256>>>(anchors);
    k_scan<<<1, 256>>>();
    k_compact<<<321, 256>>>();
    k_rank<<<321, 256>>>();
    k_transpose<<<dim3(285, 32), dim3(32, 8)>>>(net_conv);
    k_roialign<<<dim3(49, TOPN), 256>>>();
    k_fcgemm<<<dim3(16, 3, ZSPLIT), 256>>>(fc_w);
    k_fcreduce<<<(TOPN * FCD + 255) / 256, 256>>>(fc_b);
    k_heads<<<TOPN, 128>>>(cls_w, cls_b, bbox_w, bbox_b, roi_tgt, roi_biw, roi_bow, roi_lab);
    k_loss1<<<NB_RED, 256>>>(rpn_lab, rpn_tgt, rpn_biw, rpn_bow);
    k_final<<<1, 32>>>(out);
}

// round 4
// speedup vs baseline: 1.6766x; 1.1145x over previous
#include <cuda_runtime.h>
#include <cuda_bf16.h>
#include <math.h>

#define HH 76
#define WW 120
#define HW 9120
#define AA 9
#define NANCH 82080
#define CIN 1024
#define KC 9216
#define KE 27648
#define TOPN 300
#define FCD 2048
#define KFC 50176
#define ZSPLIT 4
#define KPZ (KFC / ZSPLIT)
#define NB_RED 256

__device__ float g_rpn[512 * HW];
__device__ float g_cls[18 * HW];
__device__ float g_bbox[36 * HW];
__device__ unsigned int g_key[NANCH];
__device__ float g_boxes[NANCH * 4];
__device__ int g_hist[65536];
__device__ int g_thr_bin;
__device__ int g_cand_cnt;
__device__ unsigned int g_ckey[NANCH];
__device__ int g_cidx[NANCH];
__device__ float g_rois[TOPN * 4];
__device__ float g_feat_t[HW * CIN];
__device__ __nv_bfloat16 g_pooledh[TOPN * KFC];
__device__ float g_fcp[ZSPLIT * 384 * FCD];
__device__ float g_fc7[TOPN * FCD];
__device__ float g_ce2[TOPN];
__device__ float g_lbrow[TOPN];
__device__ float g_red_ce[NB_RED];
__device__ float g_red_cnt[NB_RED];
__device__ float g_red_lb[NB_RED];
__device__ __nv_bfloat16 g_wsplit[512 * KE];
__device__ __nv_bfloat16 g_xhi[CIN * HW];
__device__ __nv_bfloat16 g_xlo[CIN * HW];

__global__ void k_zero() {
    int i = blockIdx.x * blockDim.x + threadIdx.x;
    if (i < 65536) g_hist[i] = 0;
    if (i == 0) g_cand_cnt = 0;
}

__global__ void k_prep_w(const float* __restrict__ Wt) {
    int i = blockIdx.x * blockDim.x + threadIdx.x;
    if (i >= 512 * KC) return;
    int m = i / KC, kk = i - m * KC;
    float w = Wt[i];
    __nv_bfloat16 hi = __float2bfloat16_rn(w);
    __nv_bfloat16 lo = __float2bfloat16_rn(w - __bfloat162float(hi));
    size_t base = (size_t)m * KE;
    g_wsplit[base + kk] = hi;
    g_wsplit[base + KC + kk] = lo;
    g_wsplit[base + 2 * KC + kk] = hi;
}

__global__ void k_prep_x(const float* __restrict__ X) {
    int i = blockIdx.x * blockDim.x + threadIdx.x;
    if (i >= CIN * HW) return;
    float x = X[i];
    __nv_bfloat16 hi = __float2bfloat16_rn(x);
    g_xhi[i] = hi;
    g_xlo[i] = __float2bfloat16_rn(x - __bfloat162float(hi));
}

// conv3x3 as implicit GEMM on bf16 mma with 3-term compensation (K_eff = 27648)
__global__ void __launch_bounds__(256) k_conv3x3_mma(const float* __restrict__ bias) {
    __shared__ __nv_bfloat16 Asm[128 * 40];
    __shared__ __nv_bfloat16 Bks[32 * 132];
    int tid = threadIdx.x;
    int lane = tid & 31, warp = tid >> 5;
    int n0 = blockIdx.x * 128, m0 = blockIdx.y * 128;
    int wm = (warp >> 2) * 64, wn = (warp & 3) * 32;
    int g = lane >> 2, tq = lane & 3;
    int bn = tid & 127, kb = tid >> 7;
    int p = n0 + bn;
    bool pv = p < HW;
    int py = p / WW, px = p - py * WW;
    float c[4][4][4];
#pragma unroll
    for (int mt = 0; mt < 4; mt++)
#pragma unroll
        for (int nt = 0; nt < 4; nt++)
#pragma unroll
            for (int u = 0; u < 4; u++) c[mt][nt][u] = 0.f;

    for (int ks = 0; ks < KE; ks += 32) {
        int slot = ks / KC;
        const __nv_bfloat16* Xp = (slot == 2) ? g_xlo : g_xhi;
        int kbase = ks - slot * KC;
#pragma unroll
        for (int u = 0; u < 2; u++) {
            int idx = tid * 2 + u;
            int r = idx >> 2, c8 = idx & 3;
            *reinterpret_cast<uint4*>(&Asm[r * 40 + c8 * 8]) =
                *reinterpret_cast<const uint4*>(&g_wsplit[(size_t)(m0 + r) * KE + ks + c8 * 8]);
        }
#pragma unroll
        for (int i = 0; i < 16; i++) {
            int k = 2 * i + kb;
            int kk = kbase + k;
            int ci = kk / 9, t9 = kk - ci * 9, t3 = t9 / 3;
            int yy = py + t3 - 1, xx = px + (t9 - t3 * 3 - 1);
            __nv_bfloat16 v = __float2bfloat16_rn(0.f);
            if (pv && (unsigned)yy < HH && (unsigned)xx < WW)
                v = Xp[(size_t)ci * HW + yy * WW + xx];
            Bks[k * 132 + bn] = v;
        }
        __syncthreads();
#pragma unroll
        for (int ko = 0; ko < 32; ko += 16) {
            unsigned a[4][4];
#pragma unroll
            for (int mt = 0; mt < 4; mt++) {
                const __nv_bfloat16* ap = &Asm[(wm + mt * 16 + g) * 40 + ko + tq * 2];
                a[mt][0] = *reinterpret_cast<const unsigned*>(ap);
                a[mt][1] = *reinterpret_cast<const unsigned*>(ap + 8 * 40);
                a[mt][2] = *reinterpret_cast<const unsigned*>(ap + 8);
                a[mt][3] = *reinterpret_cast<const unsigned*>(ap + 8 * 40 + 8);
            }
            unsigned b[4][2];
#pragma unroll
            for (int nt = 0; nt < 4; nt++) {
                int n = wn + nt * 8 + g;
                unsigned lo0 = *reinterpret_cast<const unsigned short*>(&Bks[(ko + tq * 2) * 132 + n]);
                unsigned hi0 = *reinterpret_cast<const unsigned short*>(&Bks[(ko + tq * 2 + 1) * 132 + n]);
                b[nt][0] = lo0 | (hi0 << 16);
                unsigned lo1 = *reinterpret_cast<const unsigned short*>(&Bks[(ko + tq * 2 + 8) * 132 + n]);
                unsigned hi1 = *reinterpret_cast<const unsigned short*>(&Bks[(ko + tq * 2 + 9) * 132 + n]);
                b[nt][1] = lo1 | (hi1 << 16);
            }
#pragma unroll
            for (int mt = 0; mt < 4; mt++)
#pragma unroll
                for (int nt = 0; nt < 4; nt++) {
                    asm volatile(
                        "mma.sync.aligned.m16n8k16.row.col.f32.bf16.bf16.f32 "
                        "{%0,%1,%2,%3}, {%4,%5,%6,%7}, {%8,%9}, {%0,%1,%2,%3};"
                        : "+f"(c[mt][nt][0]), "+f"(c[mt][nt][1]),
                          "+f"(c[mt][nt][2]), "+f"(c[mt][nt][3])
                        : "r"(a[mt][0]), "r"(a[mt][1]), "r"(a[mt][2]), "r"(a[mt][3]),
                          "r"(b[nt][0]), "r"(b[nt][1]));
                }
        }
        __syncthreads();
    }
#pragma unroll
    for (int mt = 0; mt < 4; mt++) {
#pragma unroll
        for (int nt = 0; nt < 4; nt++) {
            int m = m0 + wm + mt * 16 + g;
            int pp = n0 + wn + nt * 8 + tq * 2;
            float bv0 = bias[m], bv1 = bias[m + 8];
            float v0 = fmaxf(c[mt][nt][0] + bv0, 0.f);
            float v1 = fmaxf(c[mt][nt][1] + bv0, 0.f);
            float v2 = fmaxf(c[mt][nt][2] + bv1, 0.f);
            float v3 = fmaxf(c[mt][nt][3] + bv1, 0.f);
            if (pp + 1 < HW) {
                *reinterpret_cast<float2*>(&g_rpn[(size_t)m * HW + pp]) = make_float2(v0, v1);
                *reinterpret_cast<float2*>(&g_rpn[(size_t)(m + 8) * HW + pp]) = make_float2(v2, v3);
            } else if (pp < HW) {
                g_rpn[(size_t)m * HW + pp] = v0;
                g_rpn[(size_t)(m + 8) * HW + pp] = v2;
            }
        }
    }
}

__global__ void __launch_bounds__(128) k_conv1x1(const float* __restrict__ cw,
                                                 const float* __restrict__ cb,
                                                 const float* __restrict__ bw,
                                                 const float* __restrict__ bb) {
    __shared__ float ws[27 * 128];
    int tid = threadIdx.x;
    int p = blockIdx.x * 128 + tid;
    bool pv = p < HW;
    int half = blockIdx.y;
    float acc[27];
#pragma unroll
    for (int c = 0; c < 27; c++) {
        int oc = half * 27 + c;
        acc[c] = (oc < 18) ? cb[oc] : bb[oc - 18];
    }
    for (int kc = 0; kc < 512; kc += 128) {
        __syncthreads();
#pragma unroll
        for (int c = 0; c < 27; c++) {
            int oc = half * 27 + c;
            ws[c * 128 + tid] = (oc < 18) ? cw[oc * 512 + kc + tid] : bw[(oc - 18) * 512 + kc + tid];
        }
        __syncthreads();
        for (int k = 0; k < 128; k++) {
            float rv = pv ? g_rpn[(size_t)(kc + k) * HW + p] : 0.f;
#pragma unroll
            for (int c = 0; c < 27; c++) acc[c] = fmaf(rv, ws[c * 128 + k], acc[c]);
        }
    }
    if (pv) {
#pragma unroll
        for (int c = 0; c < 27; c++) {
            int oc = half * 27 + c;
            if (oc < 18) g_cls[oc * HW + p] = acc[c];
            else g_bbox[(oc - 18) * HW + p] = acc[c];
        }
    }
}

__global__ void k_fgboxes(const float* __restrict__ anchors) {
    int i = blockIdx.x * blockDim.x + threadIdx.x;
    if (i >= NANCH) return;
    int p = i / AA, a = i - p * AA;
    float s0 = g_cls[a * HW + p], s1 = g_cls[(9 + a) * HW + p];
    float m = fmaxf(s0, s1);
    float e0 = expf(s0 - m), e1 = expf(s1 - m);
    float fg = e1 / (e0 + e1);
    unsigned int u = __float_as_uint(fg);
    u = (u & 0x80000000u) ? ~u : (u | 0x80000000u);
    g_key[i] = u;
    atomicAdd(&g_hist[u >> 16], 1);
    float ax1 = anchors[i * 4], ay1 = anchors[i * 4 + 1];
    float ax2 = anchors[i * 4 + 2], ay2 = anchors[i * 4 + 3];
    float aw = ax2 - ax1 + 1.f, ah = ay2 - ay1 + 1.f;
    float acx = ax1 + 0.5f * aw, acy = ay1 + 0.5f * ah;
    float dx = g_bbox[(4 * a) * HW + p], dy = g_bbox[(4 * a + 1) * HW + p];
    float dw = g_bbox[(4 * a + 2) * HW + p], dh = g_bbox[(4 * a + 3) * HW + p];
    float pcx = dx * aw + acx, pcy = dy * ah + acy;
    float pw = expf(dw) * aw, ph = expf(dh) * ah;
    g_boxes[i * 4 + 0] = fminf(fmaxf(pcx - 0.5f * pw, 0.f), 1919.f);
    g_boxes[i * 4 + 1] = fminf(fmaxf(pcy - 0.5f * ph, 0.f), 1215.f);
    g_boxes[i * 4 + 2] = fminf(fmaxf(pcx + 0.5f * pw, 0.f), 1919.f);
    g_boxes[i * 4 + 3] = fminf(fmaxf(pcy + 0.5f * ph, 0.f), 1215.f);
}

__global__ void k_scan() {
    __shared__ int cs[256];
    int t = threadIdx.x;
    int s = 0;
    for (int j = 0; j < 256; j++) s += g_hist[t * 256 + j];
    cs[t] = s;
    __syncthreads();
    if (t == 0) {
        int acc = 0, chunk = 0;
        for (int i = 255; i >= 0; i--) {
            if (acc + cs[i] >= TOPN) { chunk = i; break; }
            acc += cs[i];
        }
        int T = chunk * 256;
        for (int b = chunk * 256 + 255; b >= chunk * 256; b--) {
            if (acc + g_hist[b] >= TOPN) { T = b; break; }
            acc += g_hist[b];
        }
        g_thr_bin = T;
    }
}

__global__ void k_compact() {
    int i = blockIdx.x * blockDim.x + threadIdx.x;
    if (i >= NANCH) return;
    unsigned int u = g_key[i];
    if ((int)(u >> 16) >= g_thr_bin) {
        int pos = atomicAdd(&g_cand_cnt, 1);
        g_ckey[pos] = u;
        g_cidx[pos] = i;
    }
}

__global__ void k_rank() {
    int c = g_cand_cnt;
    int i = blockIdx.x * blockDim.x + threadIdx.x;
    if (i >= c) return;
    unsigned int ki = g_ckey[i];
    int di = g_cidx[i];
    int rank = 0;
    for (int j = 0; j < c; j++) {
        unsigned int kj = g_ckey[j];
        if (kj > ki || (kj == ki && g_cidx[j] < di)) rank++;
    }
    if (rank < TOPN) {
        g_rois[rank * 4 + 0] = g_boxes[di * 4 + 0];
        g_rois[rank * 4 + 1] = g_boxes[di * 4 + 1];
        g_rois[rank * 4 + 2] = g_boxes[di * 4 + 2];
        g_rois[rank * 4 + 3] = g_boxes[di * 4 + 3];
    }
}

__global__ void k_transpose(const float* __restrict__ X) {
    __shared__ float tile[32][33];
    int tx = threadIdx.x, ty = threadIdx.y;
    int p0 = blockIdx.x * 32, c0 = blockIdx.y * 32;
#pragma unroll
    for (int j = 0; j < 32; j += 8) tile[ty + j][tx] = X[(size_t)(c0 + ty + j) * HW + p0 + tx];
    __syncthreads();
#pragma unroll
    for (int j = 0; j < 32; j += 8)
        g_feat_t[(size_t)(p0 + ty + j) * CIN + c0 + tx] = tile[tx][ty + j];
}

__global__ void __launch_bounds__(256) k_roialign() {
    int r = blockIdx.y, q = blockIdx.x;
    int pyy = q / 7, pxx = q - pyy * 7;
    float x1 = g_rois[r * 4 + 0] * 0.0625f, y1 = g_rois[r * 4 + 1] * 0.0625f;
    float x2 = g_rois[r * 4 + 2] * 0.0625f, y2 = g_rois[r * 4 + 3] * 0.0625f;
    float xs = fminf(fmaxf(x1 + (x2 - x1) * ((pxx + 0.5f) / 7.f), 0.f), 119.f);
    float ys = fminf(fmaxf(y1 + (y2 - y1) * ((pyy + 0.5f) / 7.f), 0.f), 75.f);
    float x0f = floorf(xs), y0f = floorf(ys);
    int x0i = (int)x0f, y0i = (int)y0f;
    int x1i = min(x0i + 1, 119), y1i = min(y0i + 1, 75);
    float wx = xs - x0f, wy = ys - y0f;
    float w00 = (1.f - wy) * (1.f - wx), w01 = (1.f - wy) * wx;
    float w10 = wy * (1.f - wx), w11 = wy * wx;
    const float* f00 = &g_feat_t[(size_t)(y0i * WW + x0i) * CIN];
    const float* f01 = &g_feat_t[(size_t)(y0i * WW + x1i) * CIN];
    const float* f10 = &g_feat_t[(size_t)(y1i * WW + x0i) * CIN];
    const float* f11 = &g_feat_t[(size_t)(y1i * WW + x1i) * CIN];
    __nv_bfloat16* outp = &g_pooledh[(size_t)r * KFC + q];
    for (int c = threadIdx.x; c < CIN; c += 256) {
        float v = f00[c] * w00 + f01[c] * w01 + f10[c] * w10 + f11[c] * w11;
        outp[c * 49] = __float2bfloat16_rn(v);
    }
}

__global__ void __launch_bounds__(256) k_fcgemm(const float* __restrict__ Bw) {
    __shared__ __nv_bfloat16 Asm[128 * 40];
    __shared__ __nv_bfloat16 Bks[32 * 132];
    int tid = threadIdx.x;
    int lane = tid & 31, warp = tid >> 5;
    int n0 = blockIdx.x * 128, m0 = blockIdx.y * 128;
    int kz = blockIdx.z * KPZ;
    int wm = (warp >> 2) * 64;
    int wn = (warp & 3) * 32;
    int g = lane >> 2, tq = lane & 3;
    float c[4][4][4];
#pragma unroll
    for (int mt = 0; mt < 4; mt++)
#pragma unroll
        for (int nt = 0; nt < 4; nt++)
#pragma unroll
            for (int u = 0; u < 4; u++) c[mt][nt][u] = 0.f;

    for (int ks = 0; ks < KPZ; ks += 32) {
#pragma unroll
        for (int u = 0; u < 2; u++) {
            int idx = tid * 2 + u;
            int r = idx >> 2, c8 = idx & 3;
            uint4 v = make_uint4(0, 0, 0, 0);
            int m = m0 + r;
            if (m < TOPN)
                v = *reinterpret_cast<const uint4*>(&g_pooledh[(size_t)m * KFC + kz + ks + c8 * 8]);
            *reinterpret_cast<uint4*>(&Asm[r * 40 + c8 * 8]) = v;
        }
#pragma unroll
        for (int i = 0; i < 4; i++) {
            int idx = i * 256 + tid;
            int k = idx >> 5, cc = idx & 31;
            float4 v = *reinterpret_cast<const float4*>(&Bw[(size_t)(kz + ks + k) * FCD + n0 + cc * 4]);
            __nv_bfloat162 p0 = __floats2bfloat162_rn(v.x, v.y);
            __nv_bfloat162 p1 = __floats2bfloat162_rn(v.z, v.w);
            uint2 st;
            st.x = *reinterpret_cast<unsigned*>(&p0);
            st.y = *reinterpret_cast<unsigned*>(&p1);
            *reinterpret_cast<uint2*>(&Bks[k * 132 + cc * 4]) = st;
        }
        __syncthreads();
#pragma unroll
        for (int ko = 0; ko < 32; ko += 16) {
            unsigned a[4][4];
#pragma unroll
            for (int mt = 0; mt < 4; mt++) {
                const __nv_bfloat16* ap = &Asm[(wm + mt * 16 + g) * 40 + ko + tq * 2];
                a[mt][0] = *reinterpret_cast<const unsigned*>(ap);
                a[mt][1] = *reinterpret_cast<const unsigned*>(ap + 8 * 40);
                a[mt][2] = *reinterpret_cast<const unsigned*>(ap + 8);
                a[mt][3] = *reinterpret_cast<const unsigned*>(ap + 8 * 40 + 8);
            }
            unsigned b[4][2];
#pragma unroll
            for (int nt = 0; nt < 4; nt++) {
                int n = wn + nt * 8 + g;
                unsigned lo0 = *reinterpret_cast<const unsigned short*>(&Bks[(ko + tq * 2) * 132 + n]);
                unsigned hi0 = *reinterpret_cast<const unsigned short*>(&Bks[(ko + tq * 2 + 1) * 132 + n]);
                b[nt][0] = lo0 | (hi0 << 16);
                unsigned lo1 = *reinterpret_cast<const unsigned short*>(&Bks[(ko + tq * 2 + 8) * 132 + n]);
                unsigned hi1 = *reinterpret_cast<const unsigned short*>(&Bks[(ko + tq * 2 + 9) * 132 + n]);
                b[nt][1] = lo1 | (hi1 << 16);
            }
#pragma unroll
            for (int mt = 0; mt < 4; mt++)
#pragma unroll
                for (int nt = 0; nt < 4; nt++) {
                    asm volatile(
                        "mma.sync.aligned.m16n8k16.row.col.f32.bf16.bf16.f32 "
                        "{%0,%1,%2,%3}, {%4,%5,%6,%7}, {%8,%9}, {%0,%1,%2,%3};"
                        : "+f"(c[mt][nt][0]), "+f"(c[mt][nt][1]),
                          "+f"(c[mt][nt][2]), "+f"(c[mt][nt][3])
                        : "r"(a[mt][0]), "r"(a[mt][1]), "r"(a[mt][2]), "r"(a[mt][3]),
                          "r"(b[nt][0]), "r"(b[nt][1]));
                }
        }
        __syncthreads();
    }
#pragma unroll
    for (int mt = 0; mt < 4; mt++) {
#pragma unroll
        for (int nt = 0; nt < 4; nt++) {
            int m = m0 + wm + mt * 16 + g;
            int n = n0 + wn + nt * 8 + tq * 2;
            if (m < TOPN) {
                float2 v = make_float2(c[mt][nt][0], c[mt][nt][1]);
                *reinterpret_cast<float2*>(&g_fcp[((size_t)blockIdx.z * 384 + m) * FCD + n]) = v;
            }
            if (m + 8 < TOPN) {
                float2 v = make_float2(c[mt][nt][2], c[mt][nt][3]);
                *reinterpret_cast<float2*>(&g_fcp[((size_t)blockIdx.z * 384 + m + 8) * FCD + n]) = v;
            }
        }
    }
}

__global__ void k_fcreduce(const float* __restrict__ fb) {
    int i = blockIdx.x * blockDim.x + threadIdx.x;
    if (i >= TOPN * FCD) return;
    int m = i / FCD, n = i - m * FCD;
    float s = fb[n];
#pragma unroll
    for (int z = 0; z < ZSPLIT; z++) s += g_fcp[((size_t)z * 384 + m) * FCD + n];
    g_fc7[i] = s > 0.f ? s : 0.f;
}

__global__ void __launch_bounds__(128) k_heads(const float* __restrict__ cw, const float* __restrict__ cb,
                                               const float* __restrict__ bw, const float* __restrict__ bb,
                                               const float* __restrict__ tgt, const float* __restrict__ biw,
                                               const float* __restrict__ bow, const int* __restrict__ lab) {
    __shared__ float sf[FCD];
    __shared__ float so[105];
    int r = blockIdx.x, t = threadIdx.x;
    for (int k = t; k < FCD; k += 128) sf[k] = g_fc7[(size_t)r * FCD + k];
    __syncthreads();
    if (t < 105) {
        float acc = (t < 21) ? cb[t] : bb[t - 21];
        if (t < 21) {
            for (int k = 0; k < FCD; k++) acc = fmaf(sf[k], cw[k * 21 + t], acc);
        } else {
            int o = t - 21;
            for (int k = 0; k < FCD; k++) acc = fmaf(sf[k], bw[k * 84 + o], acc);
        }
        so[t] = acc;
    }
    __syncthreads();
    if (t == 0) {
        float m = so[0];
        for (int c = 1; c < 21; c++) m = fmaxf(m, so[c]);
        float se = 0.f;
        for (int c = 0; c < 21; c++) se += expf(so[c] - m);
        float lse = m + logf(se);
        g_ce2[r] = lse - so[lab[r]];
        float lb = 0.f;
        for (int o = 0; o < 84; o++) {
            int idx = r * 84 + o;
            float d = biw[idx] * (so[21 + o] - tgt[idx]);
            float ad = fabsf(d);
            float loss = (ad < 1.f) ? d * d * 0.5f : (ad - 0.5f);
            lb += bow[idx] * loss;
        }
        g_lbrow[r] = lb;
    }
}

__global__ void __launch_bounds__(256) k_loss1(const int* __restrict__ lab, const float* __restrict__ tgt,
                                               const float* __restrict__ biw, const float* __restrict__ bow) {
    __shared__ float sce[256], scn[256], slb[256];
    int t = threadIdx.x;
    int gid = blockIdx.x * 256 + t;
    int stride = NB_RED * 256;
    float ce = 0.f, cn = 0.f, lb = 0.f;
    for (int e = gid; e < 36 * HW; e += stride) {
        int p = e / 36, c = e - p * 36;
        float d = biw[e] * (g_bbox[c * HW + p] - tgt[e]);
        float ad = fabsf(d);
        float loss = (ad < (1.f / 9.f)) ? d * d * 4.5f : (ad - 1.f / 18.f);
        lb += bow[e] * loss;
        if (e < NANCH) {
            int L = lab[e];
            if (L != -1) {
                int a = e / HW, pp = e - a * HW;
                float s0 = g_cls[a * HW + pp], s1 = g_cls[(9 + a) * HW + pp];
                float m = fmaxf(s0, s1);
                float lse = m + logf(expf(s0 - m) + expf(s1 - m));
                ce += lse - (L ? s1 : s0);
                cn += 1.f;
            }
        }
    }
    sce[t] = ce; scn[t] = cn; slb[t] = lb;
    __syncthreads();
    for (int o = 128; o > 0; o >>= 1) {
        if (t < o) { sce[t] += sce[t + o]; scn[t] += scn[t + o]; slb[t] += slb[t + o]; }
        __syncthreads();
    }
    if (t == 0) {
        g_red_ce[blockIdx.x] = sce[0];
        g_red_cnt[blockIdx.x] = scn[0];
        g_red_lb[blockIdx.x] = slb[0];
    }
}

__global__ void k_final(float* out) {
    if (threadIdx.x != 0) return;
    float ce = 0.f, cn = 0.f, lb = 0.f;
    for (int i = 0; i < NB_RED; i++) { ce += g_red_ce[i]; cn += g_red_cnt[i]; lb += g_red_lb[i]; }
    float ce2 = 0.f, lb2 = 0.f;
    for (int r = 0; r < TOPN; r++) { ce2 += g_ce2[r]; lb2 += g_lbrow[r]; }
    out[0] = ce / fmaxf(cn, 1.f) + lb + ce2 / TOPN + lb2 / TOPN;
}

extern "C" void kernel_launch(void* const* d_in, const int* in_sizes, int n_in,
                              void* d_out, int out_size) {
    const float* net_conv = (const float*)d_in[0];
    const float* rpn_w = (const float*)d_in[1];
    const float* rpn_b = (const float*)d_in[2];
    const float* rpn_cls_w = (const float*)d_in[3];
    const float* rpn_cls_b = (const float*)d_in[4];
    const float* rpn_bbox_w = (const float*)d_in[5];
    const float* rpn_bbox_b = (const float*)d_in[6];
    const float* fc_w = (const float*)d_in[7];
    const float* fc_b = (const float*)d_in[8];
    const float* cls_w = (const float*)d_in[9];
    const float* cls_b = (const float*)d_in[10];
    const float* bbox_w = (const float*)d_in[11];
    const float* bbox_b = (const float*)d_in[12];
    const float* anchors = (const float*)d_in[13];
    const float* rpn_tgt = (const float*)d_in[14];
    const float* rpn_biw = (const float*)d_in[15];
    const float* rpn_bow = (const float*)d_in[16];
    const float* roi_tgt = (const float*)d_in[17];
    const float* roi_biw = (const float*)d_in[18];
    const float* roi_bow = (const float*)d_in[19];
    const int* rpn_lab = (const int*)d_in[20];
    const int* roi_lab = (const int*)d_in[21];
    float* out = (float*)d_out;

    k_zero<<<256, 256>>>();
    k_prep_w<<<(512 * KC + 255) / 256, 256>>>(rpn_w);
    k_prep_x<<<(CIN * HW + 255) / 256, 256>>>(net_conv);
    k_conv3x3_mma<<<dim3(72, 4), 256>>>(rpn_b);
    k_conv1x1<<<dim3(72, 2), 128>>>(rpn_cls_w, rpn_cls_b, rpn_bbox_w, rpn_bbox_b);
    k_fgboxes<<<321, 256>>>(anchors);
    k_scan<<<1, 256>>>();
    k_compact<<<321, 256>>>();
    k_rank<<<321, 256>>>();
    k_transpose<<<dim3(285, 32), dim3(32, 8)>>>(net_conv);
    k_roialign<<<dim3(49, TOPN), 256>>>();
    k_fcgemm<<<dim3(16, 3, ZSPLIT), 256>>>(fc_w);
    k_fcreduce<<<(TOPN * FCD + 255) / 256, 256>>>(fc_b);
    k_heads<<<TOPN, 128>>>(cls_w, cls_b, bbox_w, bbox_b, roi_tgt, roi_biw, roi_bow, roi_lab);
    k_loss1<<<NB_RED, 256>>>(rpn_lab, rpn_tgt, rpn_biw, rpn_bow);
    k_final<<<1, 32>>>(out);
}

// round 5
// speedup vs baseline: 2.1128x; 1.2602x over previous
#include <cuda_runtime.h>
#include <cuda_bf16.h>
#include <math.h>

#define HH 76
#define WW 120
#define HW 9120
#define AA 9
#define NANCH 82080
#define CIN 1024
#define KC 9216
#define KE 27648
#define TOPN 300
#define FCD 2048
#define KFC 50176
#define ZSPLIT 4
#define KPZ (KFC / ZSPLIT)
#define NB_RED 256

__device__ float g_rpn[512 * HW];
__device__ float g_cls[18 * HW];
__device__ float g_bbox[36 * HW];
__device__ unsigned int g_key[NANCH];
__device__ float g_boxes[NANCH * 4];
__device__ int g_hist[65536];
__device__ int g_thr_bin;
__device__ int g_cand_cnt;
__device__ unsigned int g_ckey[NANCH];
__device__ int g_cidx[NANCH];
__device__ float g_rois[TOPN * 4];
__device__ float g_feat_t[HW * CIN];
__device__ __nv_bfloat16 g_pooledh[TOPN * KFC];
__device__ float g_fcp[ZSPLIT * 384 * FCD];
__device__ float g_fc7[TOPN * FCD];
__device__ float g_ce2[TOPN];
__device__ float g_lbrow[TOPN];
__device__ float g_red_ce[NB_RED];
__device__ float g_red_cnt[NB_RED];
__device__ float g_red_lb[NB_RED];
__device__ __nv_bfloat16 g_wsplit[512 * KE];
__device__ __nv_bfloat16 g_xhi_t[HW * CIN];
__device__ __nv_bfloat16 g_xlo_t[HW * CIN];

__global__ void k_zero() {
    int i = blockIdx.x * blockDim.x + threadIdx.x;
    if (i < 65536) g_hist[i] = 0;
    if (i == 0) g_cand_cnt = 0;
}

// weight split with tap-major K ordering: k = slot*KC + t9*CIN + ci
__global__ void k_prep_w(const float* __restrict__ Wt) {
    int i = blockIdx.x * blockDim.x + threadIdx.x;
    if (i >= 512 * KC) return;
    int m = i / KC, r = i - m * KC;
    int t9 = r >> 10, ci = r & 1023;
    float w = Wt[(size_t)m * KC + ci * 9 + t9];
    __nv_bfloat16 hi = __float2bfloat16_rn(w);
    __nv_bfloat16 lo = __float2bfloat16_rn(w - __bfloat162float(hi));
    size_t base = (size_t)m * KE;
    g_wsplit[base + r] = hi;
    g_wsplit[base + KC + r] = lo;
    g_wsplit[base + 2 * KC + r] = hi;
}

// fused transpose: X [c][p] -> g_feat_t fp32 [p][c], g_xhi_t/g_xlo_t bf16 [p][c]
__global__ void k_prep_x(const float* __restrict__ X) {
    __shared__ float tile[32][33];
    int tx = threadIdx.x, ty = threadIdx.y;
    int p0 = blockIdx.x * 32, c0 = blockIdx.y * 32;
#pragma unroll
    for (int j = 0; j < 32; j += 8) tile[ty + j][tx] = X[(size_t)(c0 + ty + j) * HW + p0 + tx];
    __syncthreads();
#pragma unroll
    for (int j = 0; j < 32; j += 8) {
        float v = tile[tx][ty + j];
        size_t o = (size_t)(p0 + ty + j) * CIN + c0 + tx;
        g_feat_t[o] = v;
        __nv_bfloat16 hi = __float2bfloat16_rn(v);
        g_xhi_t[o] = hi;
        g_xlo_t[o] = __float2bfloat16_rn(v - __bfloat162float(hi));
    }
}

// conv3x3 implicit GEMM, bf16 mma, 3-term compensation, tap-major K, BK=64
__global__ void __launch_bounds__(256) k_conv3x3_mma(const float* __restrict__ bias) {
    __shared__ __nv_bfloat16 Asm[128 * 72];
    __shared__ __nv_bfloat16 Bsm[128 * 72];
    int tid = threadIdx.x;
    int lane = tid & 31, warp = tid >> 5;
    int n0 = blockIdx.x * 128, m0 = blockIdx.y * 128;
    int wm = (warp >> 2) * 64, wn = (warp & 3) * 32;
    int g = lane >> 2, tq = lane & 3;
    int bn = tid & 127, kb = tid >> 7;
    int p = n0 + bn;
    bool pv = p < HW;
    int py = p / WW, px = p - py * WW;
    float c[4][4][4];
#pragma unroll
    for (int mt = 0; mt < 4; mt++)
#pragma unroll
        for (int nt = 0; nt < 4; nt++)
#pragma unroll
            for (int u = 0; u < 4; u++) c[mt][nt][u] = 0.f;

    for (int chunk = 0; chunk < KE / 64; chunk++) {
        int ks = chunk * 64;
        int slot = ks / KC;
        int kin = ks - slot * KC;
        int t9 = kin >> 10;
        int ci0 = kin & 1023;
        const __nv_bfloat16* Xp = (slot == 2) ? g_xlo_t : g_xhi_t;
        int dy = t9 / 3 - 1, dx = t9 - (t9 / 3) * 3 - 1;
        int yy = py + dy, xx = px + dx;
        bool v = pv && (unsigned)yy < HH && (unsigned)xx < WW;
        const __nv_bfloat16* src = &Xp[(size_t)(yy * WW + xx) * CIN + ci0 + kb * 32];
        // A fill: 128 rows x 64 bf16 = 1024 uint4
#pragma unroll
        for (int u = 0; u < 4; u++) {
            int idx = u * 256 + tid;
            int m = idx >> 3, oct = idx & 7;
            *reinterpret_cast<uint4*>(&Asm[m * 72 + oct * 8]) =
                *reinterpret_cast<const uint4*>(&g_wsplit[(size_t)(m0 + m) * KE + ks + oct * 8]);
        }
        // B fill: per thread 64 contiguous bytes from x plane
#pragma unroll
        for (int u = 0; u < 4; u++) {
            uint4 val = make_uint4(0, 0, 0, 0);
            if (v) val = *reinterpret_cast<const uint4*>(src + u * 8);
            *reinterpret_cast<uint4*>(&Bsm[bn * 72 + kb * 32 + u * 8]) = val;
        }
        __syncthreads();
#pragma unroll
        for (int ko = 0; ko < 64; ko += 16) {
            unsigned a[4][4];
#pragma unroll
            for (int mt = 0; mt < 4; mt++) {
                const __nv_bfloat16* ap = &Asm[(wm + mt * 16 + g) * 72 + ko + tq * 2];
                a[mt][0] = *reinterpret_cast<const unsigned*>(ap);
                a[mt][1] = *reinterpret_cast<const unsigned*>(ap + 8 * 72);
                a[mt][2] = *reinterpret_cast<const unsigned*>(ap + 8);
                a[mt][3] = *reinterpret_cast<const unsigned*>(ap + 8 * 72 + 8);
            }
            unsigned b[4][2];
#pragma unroll
            for (int nt = 0; nt < 4; nt++) {
                const __nv_bfloat16* bp = &Bsm[(wn + nt * 8 + g) * 72 + ko + tq * 2];
                b[nt][0] = *reinterpret_cast<const unsigned*>(bp);
                b[nt][1] = *reinterpret_cast<const unsigned*>(bp + 8);
            }
#pragma unroll
            for (int mt = 0; mt < 4; mt++)
#pragma unroll
                for (int nt = 0; nt < 4; nt++) {
                    asm volatile(
                        "mma.sync.aligned.m16n8k16.row.col.f32.bf16.bf16.f32 "
                        "{%0,%1,%2,%3}, {%4,%5,%6,%7}, {%8,%9}, {%0,%1,%2,%3};"
                        : "+f"(c[mt][nt][0]), "+f"(c[mt][nt][1]),
                          "+f"(c[mt][nt][2]), "+f"(c[mt][nt][3])
                        : "r"(a[mt][0]), "r"(a[mt][1]), "r"(a[mt][2]), "r"(a[mt][3]),
                          "r"(b[nt][0]), "r"(b[nt][1]));
                }
        }
        __syncthreads();
    }
#pragma unroll
    for (int mt = 0; mt < 4; mt++) {
#pragma unroll
        for (int nt = 0; nt < 4; nt++) {
            int m = m0 + wm + mt * 16 + g;
            int pp = n0 + wn + nt * 8 + tq * 2;
            float bv0 = bias[m], bv1 = bias[m + 8];
            float v0 = fmaxf(c[mt][nt][0] + bv0, 0.f);
            float v1 = fmaxf(c[mt][nt][1] + bv0, 0.f);
            float v2 = fmaxf(c[mt][nt][2] + bv1, 0.f);
            float v3 = fmaxf(c[mt][nt][3] + bv1, 0.f);
            if (pp + 1 < HW) {
                *reinterpret_cast<float2*>(&g_rpn[(size_t)m * HW + pp]) = make_float2(v0, v1);
                *reinterpret_cast<float2*>(&g_rpn[(size_t)(m + 8) * HW + pp]) = make_float2(v2, v3);
            } else if (pp < HW) {
                g_rpn[(size_t)m * HW + pp] = v0;
                g_rpn[(size_t)(m + 8) * HW + pp] = v2;
            }
        }
    }
}

__global__ void __launch_bounds__(128) k_conv1x1(const float* __restrict__ cw,
                                                 const float* __restrict__ cb,
                                                 const float* __restrict__ bw,
                                                 const float* __restrict__ bb) {
    __shared__ float ws[27 * 128];
    int tid = threadIdx.x;
    int p = blockIdx.x * 128 + tid;
    bool pv = p < HW;
    int half = blockIdx.y;
    float acc[27];
#pragma unroll
    for (int c = 0; c < 27; c++) {
        int oc = half * 27 + c;
        acc[c] = (oc < 18) ? cb[oc] : bb[oc - 18];
    }
    for (int kc = 0; kc < 512; kc += 128) {
        __syncthreads();
#pragma unroll
        for (int c = 0; c < 27; c++) {
            int oc = half * 27 + c;
            ws[c * 128 + tid] = (oc < 18) ? cw[oc * 512 + kc + tid] : bw[(oc - 18) * 512 + kc + tid];
        }
        __syncthreads();
        for (int k = 0; k < 128; k++) {
            float rv = pv ? g_rpn[(size_t)(kc + k) * HW + p] : 0.f;
#pragma unroll
            for (int c = 0; c < 27; c++) acc[c] = fmaf(rv, ws[c * 128 + k], acc[c]);
        }
    }
    if (pv) {
#pragma unroll
        for (int c = 0; c < 27; c++) {
            int oc = half * 27 + c;
            if (oc < 18) g_cls[oc * HW + p] = acc[c];
            else g_bbox[(oc - 18) * HW + p] = acc[c];
        }
    }
}

__global__ void k_fgboxes(const float* __restrict__ anchors) {
    int i = blockIdx.x * blockDim.x + threadIdx.x;
    if (i >= NANCH) return;
    int p = i / AA, a = i - p * AA;
    float s0 = g_cls[a * HW + p], s1 = g_cls[(9 + a) * HW + p];
    float m = fmaxf(s0, s1);
    float e0 = expf(s0 - m), e1 = expf(s1 - m);
    float fg = e1 / (e0 + e1);
    unsigned int u = __float_as_uint(fg);
    u = (u & 0x80000000u) ? ~u : (u | 0x80000000u);
    g_key[i] = u;
    atomicAdd(&g_hist[u >> 16], 1);
    float ax1 = anchors[i * 4], ay1 = anchors[i * 4 + 1];
    float ax2 = anchors[i * 4 + 2], ay2 = anchors[i * 4 + 3];
    float aw = ax2 - ax1 + 1.f, ah = ay2 - ay1 + 1.f;
    float acx = ax1 + 0.5f * aw, acy = ay1 + 0.5f * ah;
    float dx = g_bbox[(4 * a) * HW + p], dy = g_bbox[(4 * a + 1) * HW + p];
    float dw = g_bbox[(4 * a + 2) * HW + p], dh = g_bbox[(4 * a + 3) * HW + p];
    float pcx = dx * aw + acx, pcy = dy * ah + acy;
    float pw = expf(dw) * aw, ph = expf(dh) * ah;
    g_boxes[i * 4 + 0] = fminf(fmaxf(pcx - 0.5f * pw, 0.f), 1919.f);
    g_boxes[i * 4 + 1] = fminf(fmaxf(pcy - 0.5f * ph, 0.f), 1215.f);
    g_boxes[i * 4 + 2] = fminf(fmaxf(pcx + 0.5f * pw, 0.f), 1919.f);
    g_boxes[i * 4 + 3] = fminf(fmaxf(pcy + 0.5f * ph, 0.f), 1215.f);
}

__global__ void k_scan() {
    __shared__ int cs[256];
    int t = threadIdx.x;
    int s = 0;
    for (int j = 0; j < 256; j++) s += g_hist[t * 256 + j];
    cs[t] = s;
    __syncthreads();
    if (t == 0) {
        int acc = 0, chunk = 0;
        for (int i = 255; i >= 0; i--) {
            if (acc + cs[i] >= TOPN) { chunk = i; break; }
            acc += cs[i];
        }
        int T = chunk * 256;
        for (int b = chunk * 256 + 255; b >= chunk * 256; b--) {
            if (acc + g_hist[b] >= TOPN) { T = b; break; }
            acc += g_hist[b];
        }
        g_thr_bin = T;
    }
}

__global__ void k_compact() {
    int i = blockIdx.x * blockDim.x + threadIdx.x;
    if (i >= NANCH) return;
    unsigned int u = g_key[i];
    if ((int)(u >> 16) >= g_thr_bin) {
        int pos = atomicAdd(&g_cand_cnt, 1);
        g_ckey[pos] = u;
        g_cidx[pos] = i;
    }
}

__global__ void k_rank() {
    int c = g_cand_cnt;
    int i = blockIdx.x * blockDim.x + threadIdx.x;
    if (i >= c) return;
    unsigned int ki = g_ckey[i];
    int di = g_cidx[i];
    int rank = 0;
    for (int j = 0; j < c; j++) {
        unsigned int kj = g_ckey[j];
        if (kj > ki || (kj == ki && g_cidx[j] < di)) rank++;
    }
    if (rank < TOPN) {
        g_rois[rank * 4 + 0] = g_boxes[di * 4 + 0];
        g_rois[rank * 4 + 1] = g_boxes[di * 4 + 1];
        g_rois[rank * 4 + 2] = g_boxes[di * 4 + 2];
        g_rois[rank * 4 + 3] = g_boxes[di * 4 + 3];
    }
}

__global__ void __launch_bounds__(256) k_roialign() {
    int r = blockIdx.y, q = blockIdx.x;
    int pyy = q / 7, pxx = q - pyy * 7;
    float x1 = g_rois[r * 4 + 0] * 0.0625f, y1 = g_rois[r * 4 + 1] * 0.0625f;
    float x2 = g_rois[r * 4 + 2] * 0.0625f, y2 = g_rois[r * 4 + 3] * 0.0625f;
    float xs = fminf(fmaxf(x1 + (x2 - x1) * ((pxx + 0.5f) / 7.f), 0.f), 119.f);
    float ys = fminf(fmaxf(y1 + (y2 - y1) * ((pyy + 0.5f) / 7.f), 0.f), 75.f);
    float x0f = floorf(xs), y0f = floorf(ys);
    int x0i = (int)x0f, y0i = (int)y0f;
    int x1i = min(x0i + 1, 119), y1i = min(y0i + 1, 75);
    float wx = xs - x0f, wy = ys - y0f;
    float w00 = (1.f - wy) * (1.f - wx), w01 = (1.f - wy) * wx;
    float w10 = wy * (1.f - wx), w11 = wy * wx;
    const float* f00 = &g_feat_t[(size_t)(y0i * WW + x0i) * CIN];
    const float* f01 = &g_feat_t[(size_t)(y0i * WW + x1i) * CIN];
    const float* f10 = &g_feat_t[(size_t)(y1i * WW + x0i) * CIN];
    const float* f11 = &g_feat_t[(size_t)(y1i * WW + x1i) * CIN];
    __nv_bfloat16* outp = &g_pooledh[(size_t)r * KFC + q];
    for (int c = threadIdx.x; c < CIN; c += 256) {
        float v = f00[c] * w00 + f01[c] * w01 + f10[c] * w10 + f11[c] * w11;
        outp[c * 49] = __float2bfloat16_rn(v);
    }
}

__global__ void __launch_bounds__(256) k_fcgemm(const float* __restrict__ Bw) {
    __shared__ __nv_bfloat16 Asm[128 * 40];
    __shared__ __nv_bfloat16 Bks[32 * 132];
    int tid = threadIdx.x;
    int lane = tid & 31, warp = tid >> 5;
    int n0 = blockIdx.x * 128, m0 = blockIdx.y * 128;
    int kz = blockIdx.z * KPZ;
    int wm = (warp >> 2) * 64;
    int wn = (warp & 3) * 32;
    int g = lane >> 2, tq = lane & 3;
    float c[4][4][4];
#pragma unroll
    for (int mt = 0; mt < 4; mt++)
#pragma unroll
        for (int nt = 0; nt < 4; nt++)
#pragma unroll
            for (int u = 0; u < 4; u++) c[mt][nt][u] = 0.f;

    for (int ks = 0; ks < KPZ; ks += 32) {
#pragma unroll
        for (int u = 0; u < 2; u++) {
            int idx = tid * 2 + u;
            int r = idx >> 2, c8 = idx & 3;
            uint4 v = make_uint4(0, 0, 0, 0);
            int m = m0 + r;
            if (m < TOPN)
                v = *reinterpret_cast<const uint4*>(&g_pooledh[(size_t)m * KFC + kz + ks + c8 * 8]);
            *reinterpret_cast<uint4*>(&Asm[r * 40 + c8 * 8]) = v;
        }
#pragma unroll
        for (int i = 0; i < 4; i++) {
            int idx = i * 256 + tid;
            int k = idx >> 5, cc = idx & 31;
            float4 v = *reinterpret_cast<const float4*>(&Bw[(size_t)(kz + ks + k) * FCD + n0 + cc * 4]);
            __nv_bfloat162 p0 = __floats2bfloat162_rn(v.x, v.y);
            __nv_bfloat162 p1 = __floats2bfloat162_rn(v.z, v.w);
            uint2 st;
            st.x = *reinterpret_cast<unsigned*>(&p0);
            st.y = *reinterpret_cast<unsigned*>(&p1);
            *reinterpret_cast<uint2*>(&Bks[k * 132 + cc * 4]) = st;
        }
        __syncthreads();
#pragma unroll
        for (int ko = 0; ko < 32; ko += 16) {
            unsigned a[4][4];
#pragma unroll
            for (int mt = 0; mt < 4; mt++) {
                const __nv_bfloat16* ap = &Asm[(wm + mt * 16 + g) * 40 + ko + tq * 2];
                a[mt][0] = *reinterpret_cast<const unsigned*>(ap);
                a[mt][1] = *reinterpret_cast<const unsigned*>(ap + 8 * 40);
                a[mt][2] = *reinterpret_cast<const unsigned*>(ap + 8);
                a[mt][3] = *reinterpret_cast<const unsigned*>(ap + 8 * 40 + 8);
            }
            unsigned b[4][2];
#pragma unroll
            for (int nt = 0; nt < 4; nt++) {
                int n = wn + nt * 8 + g;
                unsigned lo0 = *reinterpret_cast<const unsigned short*>(&Bks[(ko + tq * 2) * 132 + n]);
                unsigned hi0 = *reinterpret_cast<const unsigned short*>(&Bks[(ko + tq * 2 + 1) * 132 + n]);
                b[nt][0] = lo0 | (hi0 << 16);
                unsigned lo1 = *reinterpret_cast<const unsigned short*>(&Bks[(ko + tq * 2 + 8) * 132 + n]);
                unsigned hi1 = *reinterpret_cast<const unsigned short*>(&Bks[(ko + tq * 2 + 9) * 132 + n]);
                b[nt][1] = lo1 | (hi1 << 16);
            }
#pragma unroll
            for (int mt = 0; mt < 4; mt++)
#pragma unroll
                for (int nt = 0; nt < 4; nt++) {
                    asm volatile(
                        "mma.sync.aligned.m16n8k16.row.col.f32.bf16.bf16.f32 "
                        "{%0,%1,%2,%3}, {%4,%5,%6,%7}, {%8,%9}, {%0,%1,%2,%3};"
                        : "+f"(c[mt][nt][0]), "+f"(c[mt][nt][1]),
                          "+f"(c[mt][nt][2]), "+f"(c[mt][nt][3])
                        : "r"(a[mt][0]), "r"(a[mt][1]), "r"(a[mt][2]), "r"(a[mt][3]),
                          "r"(b[nt][0]), "r"(b[nt][1]));
                }
        }
        __syncthreads();
    }
#pragma unroll
    for (int mt = 0; mt < 4; mt++) {
#pragma unroll
        for (int nt = 0; nt < 4; nt++) {
            int m = m0 + wm + mt * 16 + g;
            int n = n0 + wn + nt * 8 + tq * 2;
            if (m < TOPN) {
                float2 v = make_float2(c[mt][nt][0], c[mt][nt][1]);
                *reinterpret_cast<float2*>(&g_fcp[((size_t)blockIdx.z * 384 + m) * FCD + n]) = v;
            }
            if (m + 8 < TOPN) {
                float2 v = make_float2(c[mt][nt][2], c[mt][nt][3]);
                *reinterpret_cast<float2*>(&g_fcp[((size_t)blockIdx.z * 384 + m + 8) * FCD + n]) = v;
            }
        }
    }
}

__global__ void k_fcreduce(const float* __restrict__ fb) {
    int i = blockIdx.x * blockDim.x + threadIdx.x;
    if (i >= TOPN * FCD) return;
    int m = i / FCD, n = i - m * FCD;
    float s = fb[n];
#pragma unroll
    for (int z = 0; z < ZSPLIT; z++) s += g_fcp[((size_t)z * 384 + m) * FCD + n];
    g_fc7[i] = s > 0.f ? s : 0.f;
}

__global__ void __launch_bounds__(128) k_heads(const float* __restrict__ cw, const float* __restrict__ cb,
                                               const float* __restrict__ bw, const float* __restrict__ bb,
                                               const float* __restrict__ tgt, const float* __restrict__ biw,
                                               const float* __restrict__ bow, const int* __restrict__ lab) {
    __shared__ float sf[FCD];
    __shared__ float so[105];
    int r = blockIdx.x, t = threadIdx.x;
    for (int k = t; k < FCD; k += 128) sf[k] = g_fc7[(size_t)r * FCD + k];
    __syncthreads();
    if (t < 105) {
        float acc = (t < 21) ? cb[t] : bb[t - 21];
        if (t < 21) {
            for (int k = 0; k < FCD; k++) acc = fmaf(sf[k], cw[k * 21 + t], acc);
        } else {
            int o = t - 21;
            for (int k = 0; k < FCD; k++) acc = fmaf(sf[k], bw[k * 84 + o], acc);
        }
        so[t] = acc;
    }
    __syncthreads();
    if (t == 0) {
        float m = so[0];
        for (int c = 1; c < 21; c++) m = fmaxf(m, so[c]);
        float se = 0.f;
        for (int c = 0; c < 21; c++) se += expf(so[c] - m);
        float lse = m + logf(se);
        g_ce2[r] = lse - so[lab[r]];
        float lb = 0.f;
        for (int o = 0; o < 84; o++) {
            int idx = r * 84 + o;
            float d = biw[idx] * (so[21 + o] - tgt[idx]);
            float ad = fabsf(d);
            float loss = (ad < 1.f) ? d * d * 0.5f : (ad - 0.5f);
            lb += bow[idx] * loss;
        }
        g_lbrow[r] = lb;
    }
}

__global__ void __launch_bounds__(256) k_loss1(const int* __restrict__ lab, const float* __restrict__ tgt,
                                               const float* __restrict__ biw, const float* __restrict__ bow) {
    __shared__ float sce[256], scn[256], slb[256];
    int t = threadIdx.x;
    int gid = blockIdx.x * 256 + t;
    int stride = NB_RED * 256;
    float ce = 0.f, cn = 0.f, lb = 0.f;
    for (int e = gid; e < 36 * HW; e += stride) {
        int p = e / 36, c = e - p * 36;
        float d = biw[e] * (g_bbox[c * HW + p] - tgt[e]);
        float ad = fabsf(d);
        float loss = (ad < (1.f / 9.f)) ? d * d * 4.5f : (ad - 1.f / 18.f);
        lb += bow[e] * loss;
        if (e < NANCH) {
            int L = lab[e];
            if (L != -1) {
                int a = e / HW, pp = e - a * HW;
                float s0 = g_cls[a * HW + pp], s1 = g_cls[(9 + a) * HW + pp];
                float m = fmaxf(s0, s1);
                float lse = m + logf(expf(s0 - m) + expf(s1 - m));
                ce += lse - (L ? s1 : s0);
                cn += 1.f;
            }
        }
    }
    sce[t] = ce; scn[t] = cn; slb[t] = lb;
    __syncthreads();
    for (int o = 128; o > 0; o >>= 1) {
        if (t < o) { sce[t] += sce[t + o]; scn[t] += scn[t + o]; slb[t] += slb[t + o]; }
        __syncthreads();
    }
    if (t == 0) {
        g_red_ce[blockIdx.x] = sce[0];
        g_red_cnt[blockIdx.x] = scn[0];
        g_red_lb[blockIdx.x] = slb[0];
    }
}

__global__ void k_final(float* out) {
    if (threadIdx.x != 0) return;
    float ce = 0.f, cn = 0.f, lb = 0.f;
    for (int i = 0; i < NB_RED; i++) { ce += g_red_ce[i]; cn += g_red_cnt[i]; lb += g_red_lb[i]; }
    float ce2 = 0.f, lb2 = 0.f;
    for (int r = 0; r < TOPN; r++) { ce2 += g_ce2[r]; lb2 += g_lbrow[r]; }
    out[0] = ce / fmaxf(cn, 1.f) + lb + ce2 / TOPN + lb2 / TOPN;
}

extern "C" void kernel_launch(void* const* d_in, const int* in_sizes, int n_in,
                              void* d_out, int out_size) {
    const float* net_conv = (const float*)d_in[0];
    const float* rpn_w = (const float*)d_in[1];
    const float* rpn_b = (const float*)d_in[2];
    const float* rpn_cls_w = (const float*)d_in[3];
    const float* rpn_cls_b = (const float*)d_in[4];
    const float* rpn_bbox_w = (const float*)d_in[5];
    const float* rpn_bbox_b = (const float*)d_in[6];
    const float* fc_w = (const float*)d_in[7];
    const float* fc_b = (const float*)d_in[8];
    const float* cls_w = (const float*)d_in[9];
    const float* cls_b = (const float*)d_in[10];
    const float* bbox_w = (const float*)d_in[11];
    const float* bbox_b = (const float*)d_in[12];
    const float* anchors = (const float*)d_in[13];
    const float* rpn_tgt = (const float*)d_in[14];
    const float* rpn_biw = (const float*)d_in[15];
    const float* rpn_bow = (const float*)d_in[16];
    const float* roi_tgt = (const float*)d_in[17];
    const float* roi_biw = (const float*)d_in[18];
    const float* roi_bow = (const float*)d_in[19];
    const int* rpn_lab = (const int*)d_in[20];
    const int* roi_lab = (const int*)d_in[21];
    float* out = (float*)d_out;

    k_zero<<<256, 256>>>();
    k_prep_w<<<(512 * KC + 255) / 256, 256>>>(rpn_w);
    k_prep_x<<<dim3(285, 32), dim3(32, 8)>>>(net_conv);
    k_conv3x3_mma<<<dim3(72, 4), 256>>>(rpn_b);
    k_conv1x1<<<dim3(72, 2), 128>>>(rpn_cls_w, rpn_cls_b, rpn_bbox_w, rpn_bbox_b);
    k_fgboxes<<<321, 256>>>(anchors);
    k_scan<<<1, 256>>>();
    k_compact<<<321, 256>>>();
    k_rank<<<321, 256>>>();
    k_roialign<<<dim3(49, TOPN), 256>>>();
    k_fcgemm<<<dim3(16, 3, ZSPLIT), 256>>>(fc_w);
    k_fcreduce<<<(TOPN * FCD + 255) / 256, 256>>>(fc_b);
    k_heads<<<TOPN, 128>>>(cls_w, cls_b, bbox_w, bbox_b, roi_tgt, roi_biw, roi_bow, roi_lab);
    k_loss1<<<NB_RED, 256>>>(rpn_lab, rpn_tgt, rpn_biw, rpn_bow);
    k_final<<<1, 32>>>(out);
}

// round 7
// speedup vs baseline: 2.2173x; 1.0495x over previous
#include <cuda_runtime.h>
#include <cuda_bf16.h>
#include <math.h>

#define HH 76
#define WW 120
#define HW 9120
#define AA 9
#define NANCH 82080
#define CIN 1024
#define KC 9216
#define KE 27648
#define TOPN 300
#define FCD 2048
#define KFC 50176
#define ZSPLIT 4
#define KPZ (KFC / ZSPLIT)
#define NB_RED 256
#define CSTR 72
#define STG ((128 + 256) * CSTR)
#define CONV_SMEM (2 * STG * 2)

__device__ float g_rpn[512 * HW];
__device__ float g_cls[18 * HW];
__device__ float g_bbox[36 * HW];
__device__ unsigned int g_key[NANCH];
__device__ float g_boxes[NANCH * 4];
__device__ int g_hist[65536];
__device__ int g_thr_bin;
__device__ int g_cand_cnt;
__device__ unsigned int g_ckey[NANCH];
__device__ int g_cidx[NANCH];
__device__ float g_rois[TOPN * 4];
__device__ float g_feat_t[HW * CIN];
__device__ __nv_bfloat16 g_pooledh[TOPN * KFC];
__device__ float g_fcp[ZSPLIT * 384 * FCD];
__device__ float g_fc7[TOPN * FCD];
__device__ float g_ce2[TOPN];
__device__ float g_lbrow[TOPN];
__device__ float g_red_ce[NB_RED];
__device__ float g_red_cnt[NB_RED];
__device__ float g_red_lb[NB_RED];
__device__ __nv_bfloat16 g_wsplit[512 * KE];
__device__ __nv_bfloat16 g_xhi_t[HW * CIN];
__device__ __nv_bfloat16 g_xlo_t[HW * CIN];

__device__ __forceinline__ void cp16(unsigned dst, const void* src, int srcsize) {
    asm volatile("cp.async.cg.shared.global [%0], [%1], 16, %2;" :: "r"(dst), "l"(src), "r"(srcsize));
}

__global__ void k_zero() {
    int i = blockIdx.x * blockDim.x + threadIdx.x;
    if (i < 65536) g_hist[i] = 0;
    if (i == 0) g_cand_cnt = 0;
}

// weight split, tap-major K: k = slot*KC + t9*CIN + ci
__global__ void k_prep_w(const float* __restrict__ Wt) {
    int i = blockIdx.x * blockDim.x + threadIdx.x;
    if (i >= 512 * KC) return;
    int m = i / KC, r = i - m * KC;
    int t9 = r >> 10, ci = r & 1023;
    float w = Wt[(size_t)m * KC + ci * 9 + t9];
    __nv_bfloat16 hi = __float2bfloat16_rn(w);
    __nv_bfloat16 lo = __float2bfloat16_rn(w - __bfloat162float(hi));
    size_t base = (size_t)m * KE;
    g_wsplit[base + r] = hi;
    g_wsplit[base + KC + r] = lo;
    g_wsplit[base + 2 * KC + r] = hi;
}

__global__ void k_prep_x(const float* __restrict__ X) {
    __shared__ float tile[32][33];
    int tx = threadIdx.x, ty = threadIdx.y;
    int p0 = blockIdx.x * 32, c0 = blockIdx.y * 32;
#pragma unroll
    for (int j = 0; j < 32; j += 8) tile[ty + j][tx] = X[(size_t)(c0 + ty + j) * HW + p0 + tx];
    __syncthreads();
#pragma unroll
    for (int j = 0; j < 32; j += 8) {
        float v = tile[tx][ty + j];
        size_t o = (size_t)(p0 + ty + j) * CIN + c0 + tx;
        g_feat_t[o] = v;
        __nv_bfloat16 hi = __float2bfloat16_rn(v);
        g_xhi_t[o] = hi;
        g_xlo_t[o] = __float2bfloat16_rn(v - __bfloat162float(hi));
    }
}

// conv3x3 implicit GEMM: block 128x256, warp 64x64, BK=64, cp.async 2-stage
__global__ void __launch_bounds__(256, 1) k_conv3x3_mma(const float* __restrict__ bias) {
    extern __shared__ __nv_bfloat16 sm[];
    unsigned smb = (unsigned)__cvta_generic_to_shared(sm);
    int tid = threadIdx.x;
    int lane = tid & 31, warp = tid >> 5;
    int n0 = blockIdx.x * 256, m0 = blockIdx.y * 128;
    int wm = (warp & 1) * 64, wn = (warp >> 1) * 64;
    int g = lane >> 2, tq = lane & 3;
    int p = n0 + tid;
    bool pv = p < HW;
    int py = p / WW, px = p - py * WW;
    float c[4][8][4];
#pragma unroll
    for (int mt = 0; mt < 4; mt++)
#pragma unroll
        for (int nt = 0; nt < 8; nt++)
#pragma unroll
            for (int u = 0; u < 4; u++) c[mt][nt][u] = 0.f;

    const int NCH = KE / 64;  // 432

    auto prefetch = [&](int ch, int st) {
        int ks = ch * 64;
        int slot = ch / 144;
        int rem = ch - slot * 144;
        int tap = rem >> 4;
        int ci0 = (rem & 15) << 6;
        unsigned abase = smb + (unsigned)(st * STG) * 2;
        unsigned bbase = abase + 128 * CSTR * 2;
        // A: 128 rows x 64 bf16 = 16KB
#pragma unroll
        for (int u = 0; u < 4; u++) {
            int idx = u * 256 + tid;
            int m = idx >> 3, oct = idx & 7;
            cp16(abase + (unsigned)(m * CSTR + oct * 8) * 2,
                 &g_wsplit[(size_t)(m0 + m) * KE + ks + oct * 8], 16);
        }
        // B: 256 pixels x 64 bf16 (128 bytes/pixel, one pixel per thread)
        const __nv_bfloat16* Xp = (slot == 2) ? g_xlo_t : g_xhi_t;
        int t3 = tap / 3;
        int yy = py + t3 - 1, xx = px + (tap - t3 * 3 - 1);
        bool v = pv && (unsigned)yy < HH && (unsigned)xx < WW;
        const __nv_bfloat16* src = v ? &Xp[(size_t)(yy * WW + xx) * CIN + ci0] : Xp;
        int sz = v ? 16 : 0;
        unsigned bdst = bbase + (unsigned)(tid * CSTR) * 2;
#pragma unroll
        for (int u = 0; u < 8; u++) cp16(bdst + u * 16, src + u * 8, sz);
    };

    prefetch(0, 0);
    asm volatile("cp.async.commit_group;");

    for (int ch = 0; ch < NCH; ch++) {
        int st = ch & 1;
        if (ch + 1 < NCH) {
            prefetch(ch + 1, st ^ 1);
            asm volatile("cp.async.commit_group;");
            asm volatile("cp.async.wait_group 1;");
        } else {
            asm volatile("cp.async.wait_group 0;");
        }
        __syncthreads();
        const __nv_bfloat16* As = sm + st * STG;
        const __nv_bfloat16* Bs = As + 128 * CSTR;
#pragma unroll
        for (int ko = 0; ko < 64; ko += 16) {
            unsigned a[4][4];
#pragma unroll
            for (int mt = 0; mt < 4; mt++) {
                const __nv_bfloat16* ap = &As[(wm + mt * 16 + g) * CSTR + ko + tq * 2];
                a[mt][0] = *reinterpret_cast<const unsigned*>(ap);
                a[mt][1] = *reinterpret_cast<const unsigned*>(ap + 8 * CSTR);
                a[mt][2] = *reinterpret_cast<const unsigned*>(ap + 8);
                a[mt][3] = *reinterpret_cast<const unsigned*>(ap + 8 * CSTR + 8);
            }
            unsigned b[8][2];
#pragma unroll
            for (int nt = 0; nt < 8; nt++) {
                const __nv_bfloat16* bp = &Bs[(wn + nt * 8 + g) * CSTR + ko + tq * 2];
                b[nt][0] = *reinterpret_cast<const unsigned*>(bp);
                b[nt][1] = *reinterpret_cast<const unsigned*>(bp + 8);
            }
#pragma unroll
            for (int mt = 0; mt < 4; mt++)
#pragma unroll
                for (int nt = 0; nt < 8; nt++) {
                    asm volatile(
                        "mma.sync.aligned.m16n8k16.row.col.f32.bf16.bf16.f32 "
                        "{%0,%1,%2,%3}, {%4,%5,%6,%7}, {%8,%9}, {%0,%1,%2,%3};"
                        : "+f"(c[mt][nt][0]), "+f"(c[mt][nt][1]),
                          "+f"(c[mt][nt][2]), "+f"(c[mt][nt][3])
                        : "r"(a[mt][0]), "r"(a[mt][1]), "r"(a[mt][2]), "r"(a[mt][3]),
                          "r"(b[nt][0]), "r"(b[nt][1]));
                }
        }
        __syncthreads();
    }
#pragma unroll
    for (int mt = 0; mt < 4; mt++) {
#pragma unroll
        for (int nt = 0; nt < 8; nt++) {
            int m = m0 + wm + mt * 16 + g;
            int pp = n0 + wn + nt * 8 + tq * 2;
            float bv0 = bias[m], bv1 = bias[m + 8];
            float v0 = fmaxf(c[mt][nt][0] + bv0, 0.f);
            float v1 = fmaxf(c[mt][nt][1] + bv0, 0.f);
            float v2 = fmaxf(c[mt][nt][2] + bv1, 0.f);
            float v3 = fmaxf(c[mt][nt][3] + bv1, 0.f);
            if (pp + 1 < HW) {
                *reinterpret_cast<float2*>(&g_rpn[(size_t)m * HW + pp]) = make_float2(v0, v1);
                *reinterpret_cast<float2*>(&g_rpn[(size_t)(m + 8) * HW + pp]) = make_float2(v2, v3);
            } else if (pp < HW) {
                g_rpn[(size_t)m * HW + pp] = v0;
                g_rpn[(size_t)(m + 8) * HW + pp] = v2;
            }
        }
    }
}

__global__ void __launch_bounds__(128) k_conv1x1(const float* __restrict__ cw,
                                                 const float* __restrict__ cb,
                                                 const float* __restrict__ bw,
                                                 const float* __restrict__ bb) {
    __shared__ float ws[27 * 128];
    int tid = threadIdx.x;
    int p = blockIdx.x * 128 + tid;
    bool pv = p < HW;
    int half = blockIdx.y;
    float acc[27];
#pragma unroll
    for (int c = 0; c < 27; c++) {
        int oc = half * 27 + c;
        acc[c] = (oc < 18) ? cb[oc] : bb[oc - 18];
    }
    for (int kc = 0; kc < 512; kc += 128) {
        __syncthreads();
#pragma unroll
        for (int c = 0; c < 27; c++) {
            int oc = half * 27 + c;
            ws[c * 128 + tid] = (oc < 18) ? cw[oc * 512 + kc + tid] : bw[(oc - 18) * 512 + kc + tid];
        }
        __syncthreads();
        for (int k = 0; k < 128; k++) {
            float rv = pv ? g_rpn[(size_t)(kc + k) * HW + p] : 0.f;
#pragma unroll
            for (int c = 0; c < 27; c++) acc[c] = fmaf(rv, ws[c * 128 + k], acc[c]);
        }
    }
    if (pv) {
#pragma unroll
        for (int c = 0; c < 27; c++) {
            int oc = half * 27 + c;
            if (oc < 18) g_cls[oc * HW + p] = acc[c];
            else g_bbox[(oc - 18) * HW + p] = acc[c];
        }
    }
}

__global__ void k_fgboxes(const float* __restrict__ anchors) {
    int i = blockIdx.x * blockDim.x + threadIdx.x;
    if (i >= NANCH) return;
    int p = i / AA, a = i - p * AA;
    float s0 = g_cls[a * HW + p], s1 = g_cls[(9 + a) * HW + p];
    float m = fmaxf(s0, s1);
    float e0 = expf(s0 - m), e1 = expf(s1 - m);
    float fg = e1 / (e0 + e1);
    unsigned int u = __float_as_uint(fg);
    u = (u & 0x80000000u) ? ~u : (u | 0x80000000u);
    g_key[i] = u;
    atomicAdd(&g_hist[u >> 16], 1);
    float ax1 = anchors[i * 4], ay1 = anchors[i * 4 + 1];
    float ax2 = anchors[i * 4 + 2], ay2 = anchors[i * 4 + 3];
    float aw = ax2 - ax1 + 1.f, ah = ay2 - ay1 + 1.f;
    float acx = ax1 + 0.5f * aw, acy = ay1 + 0.5f * ah;
    float dx = g_bbox[(4 * a) * HW + p], dy = g_bbox[(4 * a + 1) * HW + p];
    float dw = g_bbox[(4 * a + 2) * HW + p], dh = g_bbox[(4 * a + 3) * HW + p];
    float pcx = dx * aw + acx, pcy = dy * ah + acy;
    float pw = expf(dw) * aw, ph = expf(dh) * ah;
    g_boxes[i * 4 + 0] = fminf(fmaxf(pcx - 0.5f * pw, 0.f), 1919.f);
    g_boxes[i * 4 + 1] = fminf(fmaxf(pcy - 0.5f * ph, 0.f), 1215.f);
    g_boxes[i * 4 + 2] = fminf(fmaxf(pcx + 0.5f * pw, 0.f), 1919.f);
    g_boxes[i * 4 + 3] = fminf(fmaxf(pcy + 0.5f * ph, 0.f), 1215.f);
}

__global__ void k_scan() {
    __shared__ int cs[256];
    int t = threadIdx.x;
    int s = 0;
    for (int j = 0; j < 256; j++) s += g_hist[t * 256 + j];
    cs[t] = s;
    __syncthreads();
    if (t == 0) {
        int acc = 0, chunk = 0;
        for (int i = 255; i >= 0; i--) {
            if (acc + cs[i] >= TOPN) { chunk = i; break; }
            acc += cs[i];
        }
        int T = chunk * 256;
        for (int b = chunk * 256 + 255; b >= chunk * 256; b--) {
            if (acc + g_hist[b] >= TOPN) { T = b; break; }
            acc += g_hist[b];
        }
        g_thr_bin = T;
    }
}

__global__ void k_compact() {
    int i = blockIdx.x * blockDim.x + threadIdx.x;
    if (i >= NANCH) return;
    unsigned int u = g_key[i];
    if ((int)(u >> 16) >= g_thr_bin) {
        int pos = atomicAdd(&g_cand_cnt, 1);
        g_ckey[pos] = u;
        g_cidx[pos] = i;
    }
}

__global__ void k_rank() {
    int c = g_cand_cnt;
    int i = blockIdx.x * blockDim.x + threadIdx.x;
    if (i >= c) return;
    unsigned int ki = g_ckey[i];
    int di = g_cidx[i];
    int rank = 0;
    for (int j = 0; j < c; j++) {
        unsigned int kj = g_ckey[j];
        if (kj > ki || (kj == ki && g_cidx[j] < di)) rank++;
    }
    if (rank < TOPN) {
        g_rois[rank * 4 + 0] = g_boxes[di * 4 + 0];
        g_rois[rank * 4 + 1] = g_boxes[di * 4 + 1];
        g_rois[rank * 4 + 2] = g_boxes[di * 4 + 2];
        g_rois[rank * 4 + 3] = g_boxes[di * 4 + 3];
    }
}

__global__ void __launch_bounds__(256) k_roialign() {
    int r = blockIdx.y, q = blockIdx.x;
    int pyy = q / 7, pxx = q - pyy * 7;
    float x1 = g_rois[r * 4 + 0] * 0.0625f, y1 = g_rois[r * 4 + 1] * 0.0625f;
    float x2 = g_rois[r * 4 + 2] * 0.0625f, y2 = g_rois[r * 4 + 3] * 0.0625f;
    float xs = fminf(fmaxf(x1 + (x2 - x1) * ((pxx + 0.5f) / 7.f), 0.f), 119.f);
    float ys = fminf(fmaxf(y1 + (y2 - y1) * ((pyy + 0.5f) / 7.f), 0.f), 75.f);
    float x0f = floorf(xs), y0f = floorf(ys);
    int x0i = (int)x0f, y0i = (int)y0f;
    int x1i = min(x0i + 1, 119), y1i = min(y0i + 1, 75);
    float wx = xs - x0f, wy = ys - y0f;
    float w00 = (1.f - wy) * (1.f - wx), w01 = (1.f - wy) * wx;
    float w10 = wy * (1.f - wx), w11 = wy * wx;
    const float* f00 = &g_feat_t[(size_t)(y0i * WW + x0i) * CIN];
    const float* f01 = &g_feat_t[(size_t)(y0i * WW + x1i) * CIN];
    const float* f10 = &g_feat_t[(size_t)(y1i * WW + x0i) * CIN];
    const float* f11 = &g_feat_t[(size_t)(y1i * WW + x1i) * CIN];
    __nv_bfloat16* outp = &g_pooledh[(size_t)r * KFC + q];
    for (int c = threadIdx.x; c < CIN; c += 256) {
        float v = f00[c] * w00 + f01[c] * w01 + f10[c] * w10 + f11[c] * w11;
        outp[c * 49] = __float2bfloat16_rn(v);
    }
}

__global__ void __launch_bounds__(256) k_fcgemm(const float* __restrict__ Bw) {
    __shared__ __nv_bfloat16 Asm[128 * 40];
    __shared__ __nv_bfloat16 Bks[32 * 132];
    int tid = threadIdx.x;
    int lane = tid & 31, warp = tid >> 5;
    int n0 = blockIdx.x * 128, m0 = blockIdx.y * 128;
    int kz = blockIdx.z * KPZ;
    int wm = (warp >> 2) * 64;
    int wn = (warp & 3) * 32;
    int g = lane >> 2, tq = lane & 3;
    float c[4][4][4];
#pragma unroll
    for (int mt = 0; mt < 4; mt++)
#pragma unroll
        for (int nt = 0; nt < 4; nt++)
#pragma unroll
            for (int u = 0; u < 4; u++) c[mt][nt][u] = 0.f;

    for (int ks = 0; ks < KPZ; ks += 32) {
#pragma unroll
        for (int u = 0; u < 2; u++) {
            int idx = tid * 2 + u;
            int r = idx >> 2, c8 = idx & 3;
            uint4 v = make_uint4(0, 0, 0, 0);
            int m = m0 + r;
            if (m < TOPN)
                v = *reinterpret_cast<const uint4*>(&g_pooledh[(size_t)m * KFC + kz + ks + c8 * 8]);
            *reinterpret_cast<uint4*>(&Asm[r * 40 + c8 * 8]) = v;
        }
#pragma unroll
        for (int i = 0; i < 4; i++) {
            int idx = i * 256 + tid;
            int k = idx >> 5, cc = idx & 31;
            float4 v = *reinterpret_cast<const float4*>(&Bw[(size_t)(kz + ks + k) * FCD + n0 + cc * 4]);
            __nv_bfloat162 p0 = __floats2bfloat162_rn(v.x, v.y);
            __nv_bfloat162 p1 = __floats2bfloat162_rn(v.z, v.w);
            uint2 st;
            st.x = *reinterpret_cast<unsigned*>(&p0);
            st.y = *reinterpret_cast<unsigned*>(&p1);
            *reinterpret_cast<uint2*>(&Bks[k * 132 + cc * 4]) = st;
        }
        __syncthreads();
#pragma unroll
        for (int ko = 0; ko < 32; ko += 16) {
            unsigned a[4][4];
#pragma unroll
            for (int mt = 0; mt < 4; mt++) {
                const __nv_bfloat16* ap = &Asm[(wm + mt * 16 + g) * 40 + ko + tq * 2];
                a[mt][0] = *reinterpret_cast<const unsigned*>(ap);
                a[mt][1] = *reinterpret_cast<const unsigned*>(ap + 8 * 40);
                a[mt][2] = *reinterpret_cast<const unsigned*>(ap + 8);
                a[mt][3] = *reinterpret_cast<const unsigned*>(ap + 8 * 40 + 8);
            }
            unsigned b[4][2];
#pragma unroll
            for (int nt = 0; nt < 4; nt++) {
                int n = wn + nt * 8 + g;
                unsigned lo0 = *reinterpret_cast<const unsigned short*>(&Bks[(ko + tq * 2) * 132 + n]);
                unsigned hi0 = *reinterpret_cast<const unsigned short*>(&Bks[(ko + tq * 2 + 1) * 132 + n]);
                b[nt][0] = lo0 | (hi0 << 16);
                unsigned lo1 = *reinterpret_cast<const unsigned short*>(&Bks[(ko + tq * 2 + 8) * 132 + n]);
                unsigned hi1 = *reinterpret_cast<const unsigned short*>(&Bks[(ko + tq * 2 + 9) * 132 + n]);
                b[nt][1] = lo1 | (hi1 << 16);
            }
#pragma unroll
            for (int mt = 0; mt < 4; mt++)
#pragma unroll
                for (int nt = 0; nt < 4; nt++) {
                    asm volatile(
                        "mma.sync.aligned.m16n8k16.row.col.f32.bf16.bf16.f32 "
                        "{%0,%1,%2,%3}, {%4,%5,%6,%7}, {%8,%9}, {%0,%1,%2,%3};"
                        : "+f"(c[mt][nt][0]), "+f"(c[mt][nt][1]),
                          "+f"(c[mt][nt][2]), "+f"(c[mt][nt][3])
                        : "r"(a[mt][0]), "r"(a[mt][1]), "r"(a[mt][2]), "r"(a[mt][3]),
                          "r"(b[nt][0]), "r"(b[nt][1]));
                }
        }
        __syncthreads();
    }
#pragma unroll
    for (int mt = 0; mt < 4; mt++) {
#pragma unroll
        for (int nt = 0; nt < 4; nt++) {
            int m = m0 + wm + mt * 16 + g;
            int n = n0 + wn + nt * 8 + tq * 2;
            if (m < TOPN) {
                float2 v = make_float2(c[mt][nt][0], c[mt][nt][1]);
                *reinterpret_cast<float2*>(&g_fcp[((size_t)blockIdx.z * 384 + m) * FCD + n]) = v;
            }
            if (m + 8 < TOPN) {
                float2 v = make_float2(c[mt][nt][2], c[mt][nt][3]);
                *reinterpret_cast<float2*>(&g_fcp[((size_t)blockIdx.z * 384 + m + 8) * FCD + n]) = v;
            }
        }
    }
}

__global__ void k_fcreduce(const float* __restrict__ fb) {
    int i = blockIdx.x * blockDim.x + threadIdx.x;
    if (i >= TOPN * FCD) return;
    int m = i / FCD, n = i - m * FCD;
    float s = fb[n];
#pragma unroll
    for (int z = 0; z < ZSPLIT; z++) s += g_fcp[((size_t)z * 384 + m) * FCD + n];
    g_fc7[i] = s > 0.f ? s : 0.f;
}

__global__ void __launch_bounds__(128) k_heads(const float* __restrict__ cw, const float* __restrict__ cb,
                                               const float* __restrict__ bw, const float* __restrict__ bb,
                                               const float* __restrict__ tgt, const float* __restrict__ biw,
                                               const float* __restrict__ bow, const int* __restrict__ lab) {
    __shared__ float sf[FCD];
    __shared__ float so[105];
    int r = blockIdx.x, t = threadIdx.x;
    for (int k = t; k < FCD; k += 128) sf[k] = g_fc7[(size_t)r * FCD + k];
    __syncthreads();
    if (t < 105) {
        float acc = (t < 21) ? cb[t] : bb[t - 21];
        if (t < 21) {
            for (int k = 0; k < FCD; k++) acc = fmaf(sf[k], cw[k * 21 + t], acc);
        } else {
            int o = t - 21;
            for (int k = 0; k < FCD; k++) acc = fmaf(sf[k], bw[k * 84 + o], acc);
        }
        so[t] = acc;
    }
    __syncthreads();
    if (t == 0) {
        float m = so[0];
        for (int c = 1; c < 21; c++) m = fmaxf(m, so[c]);
        float se = 0.f;
        for (int c = 0; c < 21; c++) se += expf(so[c] - m);
        float lse = m + logf(se);
        g_ce2[r] = lse - so[lab[r]];
        float lb = 0.f;
        for (int o = 0; o < 84; o++) {
            int idx = r * 84 + o;
            float d = biw[idx] * (so[21 + o] - tgt[idx]);
            float ad = fabsf(d);
            float loss = (ad < 1.f) ? d * d * 0.5f : (ad - 0.5f);
            lb += bow[idx] * loss;
        }
        g_lbrow[r] = lb;
    }
}

__global__ void __launch_bounds__(256) k_loss1(const int* __restrict__ lab, const float* __restrict__ tgt,
                                               const float* __restrict__ biw, const float* __restrict__ bow) {
    __shared__ float sce[256], scn[256], slb[256];
    int t = threadIdx.x;
    int gid = blockIdx.x * 256 + t;
    int stride = NB_RED * 256;
    float ce = 0.f, cn = 0.f, lb = 0.f;
    for (int e = gid; e < 36 * HW; e += stride) {
        int p = e / 36, c = e - p * 36;
        float d = biw[e] * (g_bbox[c * HW + p] - tgt[e]);
        float ad = fabsf(d);
        float loss = (ad < (1.f / 9.f)) ? d * d * 4.5f : (ad - 1.f / 18.f);
        lb += bow[e] * loss;
        if (e < NANCH) {
            int L = lab[e];
            if (L != -1) {
                int a = e / HW, pp = e - a * HW;
                float s0 = g_cls[a * HW + pp], s1 = g_cls[(9 + a) * HW + pp];
                float m = fmaxf(s0, s1);
                float lse = m + logf(expf(s0 - m) + expf(s1 - m));
                ce += lse - (L ? s1 : s0);
                cn += 1.f;
            }
        }
    }
    sce[t] = ce; scn[t] = cn; slb[t] = lb;
    __syncthreads();
    for (int o = 128; o > 0; o >>= 1) {
        if (t < o) { sce[t] += sce[t + o]; scn[t] += scn[t + o]; slb[t] += slb[t + o]; }
        __syncthreads();
    }
    if (t == 0) {
        g_red_ce[blockIdx.x] = sce[0];
        g_red_cnt[blockIdx.x] = scn[0];
        g_red_lb[blockIdx.x] = slb[0];
    }
}

__global__ void k_final(float* out) {
    if (threadIdx.x != 0) return;
    float ce = 0.f, cn = 0.f, lb = 0.f;
    for (int i = 0; i < NB_RED; i++) { ce += g_red_ce[i]; cn += g_red_cnt[i]; lb += g_red_lb[i]; }
    float ce2 = 0.f, lb2 = 0.f;
    for (int r = 0; r < TOPN; r++) { ce2 += g_ce2[r]; lb2 += g_lbrow[r]; }
    out[0] = ce / fmaxf(cn, 1.f) + lb + ce2 / TOPN + lb2 / TOPN;
}

extern "C" void kernel_launch(void* const* d_in, const int* in_sizes, int n_in,
                              void* d_out, int out_size) {
    const float* net_conv = (const float*)d_in[0];
    const float* rpn_w = (const float*)d_in[1];
    const float* rpn_b = (const float*)d_in[2];
    const float* rpn_cls_w = (const float*)d_in[3];
    const float* rpn_cls_b = (const float*)d_in[4];
    const float* rpn_bbox_w = (const float*)d_in[5];
    const float* rpn_bbox_b = (const float*)d_in[6];
    const float* fc_w = (const float*)d_in[7];
    const float* fc_b = (const float*)d_in[8];
    const float* cls_w = (const float*)d_in[9];
    const float* cls_b = (const float*)d_in[10];
    const float* bbox_w = (const float*)d_in[11];
    const float* bbox_b = (const float*)d_in[12];
    const float* anchors = (const float*)d_in[13];
    const float* rpn_tgt = (const float*)d_in[14];
    const float* rpn_biw = (const float*)d_in[15];
    const float* rpn_bow = (const float*)d_in[16];
    const float* roi_tgt = (const float*)d_in[17];
    const float* roi_biw = (const float*)d_in[18];
    const float* roi_bow = (const float*)d_in[19];
    const int* rpn_lab = (const int*)d_in[20];
    const int* roi_lab = (const int*)d_in[21];
    float* out = (float*)d_out;

    cudaFuncSetAttribute(k_conv3x3_mma, cudaFuncAttributeMaxDynamicSharedMemorySize, CONV_SMEM);

    k_zero<<<256, 256>>>();
    k_prep_w<<<(512 * KC + 255) / 256, 256>>>(rpn_w);
    k_prep_x<<<dim3(285, 32), dim3(32, 8)>>>(net_conv);
    k_conv3x3_mma<<<dim3(36, 4), 256, CONV_SMEM>>>(rpn_b);
    k_conv1x1<<<dim3(72, 2), 128>>>(rpn_cls_w, rpn_cls_b, rpn_bbox_w, rpn_bbox_b);
    k_fgboxes<<<321, 256>>>(anchors);
    k_scan<<<1, 256>>>();
    k_compact<<<321, 256>>>();
    k_rank<<<321, 256>>>();
    k_roialign<<<dim3(49, TOPN), 256>>>();
    k_fcgemm<<<dim3(16, 3, ZSPLIT), 256>>>(fc_w);
    k_fcreduce<<<(TOPN * FCD + 255) / 256, 256>>>(fc_b);
    k_heads<<<TOPN, 128>>>(cls_w, cls_b, bbox_w, bbox_b, roi_tgt, roi_biw, roi_bow, roi_lab);
    k_loss1<<<NB_RED, 256>>>(rpn_lab, rpn_tgt, rpn_biw, rpn_bow);
    k_final<<<1, 32>>>(out);
}

// round 9
// speedup vs baseline: 2.4220x; 1.0923x over previous
#include <cuda_runtime.h>
#include <cuda_bf16.h>
#include <math.h>

#define HH 76
#define WW 120
#define HW 9120
#define AA 9
#define NANCH 82080
#define CIN 1024
#define KC 9216
#define KW 18432
#define TOPN 300
#define FCD 2048
#define KFC 50176
#define ZSPLIT 4
#define KPZ (KFC / ZSPLIT)
#define NB_RED 256
#define CSTR 72
#define ASZE 9216              /* 128*72 elems */
#define STGE 36864             /* 2*ASZE + 256*72 elems */
#define STGB (STGE * 2)
#define CONV_SMEM (2 * STGB)

__device__ float g_rpn[512 * HW];
__device__ float g_cls[18 * HW];
__device__ float g_bbox[36 * HW];
__device__ unsigned int g_key[NANCH];
__device__ float g_boxes[NANCH * 4];
__device__ int g_hist[65536];
__device__ int g_thr_bin;
__device__ int g_cand_cnt;
__device__ unsigned int g_ckey[NANCH];
__device__ int g_cidx[NANCH];
__device__ float g_rois[TOPN * 4];
__device__ float g_feat_t[HW * CIN];
__device__ __nv_bfloat16 g_pooledh[TOPN * KFC];
__device__ float g_fcp[ZSPLIT * 384 * FCD];
__device__ float g_fc7[TOPN * FCD];
__device__ float g_ce2[TOPN];
__device__ float g_lbrow[TOPN];
__device__ float g_red_ce[NB_RED];
__device__ float g_red_cnt[NB_RED];
__device__ float g_red_lb[NB_RED];
__device__ __nv_bfloat16 g_wsplit[512 * KW];
__device__ __nv_bfloat16 g_xhi_t[HW * CIN];
__device__ __nv_bfloat16 g_xlo_t[HW * CIN];

__device__ __forceinline__ void cp16(unsigned dst, const void* src, int srcsize) {
    asm volatile("cp.async.cg.shared.global [%0], [%1], 16, %2;" :: "r"(dst), "l"(src), "r"(srcsize));
}

__global__ void k_zero() {
    int i = blockIdx.x * blockDim.x + threadIdx.x;
    if (i < 65536) g_hist[i] = 0;
    if (i == 0) g_cand_cnt = 0;
}

// weight split, tap-major K: k = slot*KC + t9*CIN + ci  (2 slots: hi, lo)
__global__ void k_prep_w(const float* __restrict__ Wt) {
    int i = blockIdx.x * blockDim.x + threadIdx.x;
    if (i >= 512 * KC) return;
    int m = i / KC, r = i - m * KC;
    int t9 = r >> 10, ci = r & 1023;
    float w = Wt[(size_t)m * KC + ci * 9 + t9];
    __nv_bfloat16 hi = __float2bfloat16_rn(w);
    __nv_bfloat16 lo = __float2bfloat16_rn(w - __bfloat162float(hi));
    size_t base = (size_t)m * KW;
    g_wsplit[base + r] = hi;
    g_wsplit[base + KC + r] = lo;
}

__global__ void k_prep_x(const float* __restrict__ X) {
    __shared__ float tile[32][33];
    int tx = threadIdx.x, ty = threadIdx.y;
    int p0 = blockIdx.x * 32, c0 = blockIdx.y * 32;
#pragma unroll
    for (int j = 0; j < 32; j += 8) tile[ty + j][tx] = X[(size_t)(c0 + ty + j) * HW + p0 + tx];
    __syncthreads();
#pragma unroll
    for (int j = 0; j < 32; j += 8) {
        float v = tile[tx][ty + j];
        size_t o = (size_t)(p0 + ty + j) * CIN + c0 + tx;
        g_feat_t[o] = v;
        __nv_bfloat16 hi = __float2bfloat16_rn(v);
        g_xhi_t[o] = hi;
        g_xlo_t[o] = __float2bfloat16_rn(v - __bfloat162float(hi));
    }
}

// conv3x3 implicit GEMM: block 128x256, warp 64x64, BK=64, cp.async 2-stage.
// 288 chunks: ch<144 -> B=x_hi shared by A slices (w_hi, w_lo); ch>=144 -> B=x_lo, A=w_hi.
__global__ void __launch_bounds__(256, 1) k_conv3x3_mma(const float* __restrict__ bias) {
    extern __shared__ __nv_bfloat16 sm[];
    unsigned smb = (unsigned)__cvta_generic_to_shared(sm);
    int tid = threadIdx.x;
    int lane = tid & 31, warp = tid >> 5;
    int n0 = blockIdx.x * 256, m0 = blockIdx.y * 128;
    int wm = (warp & 1) * 64, wn = (warp >> 1) * 64;
    int g = lane >> 2, tq = lane & 3;
    int p = n0 + tid;
    bool pv = p < HW;
    int py = p / WW, px = p - py * WW;
    float c[4][8][4];
#pragma unroll
    for (int mt = 0; mt < 4; mt++)
#pragma unroll
        for (int nt = 0; nt < 8; nt++)
#pragma unroll
            for (int u = 0; u < 4; u++) c[mt][nt][u] = 0.f;

    const int NCH = 288;

    auto fill = [&](int ch, int st) {
        bool hi = ch < 144;
        int rem = hi ? ch : ch - 144;
        int tap = rem >> 4;
        int ci0 = (rem & 15) << 6;
        int k = tap * 1024 + ci0;
        unsigned ab = smb + (unsigned)(st * STGB);
        unsigned a1b = ab + ASZE * 2;
        unsigned bb = ab + 2 * ASZE * 2;
        // A0: 128 rows x 64 bf16 of w_hi
#pragma unroll
        for (int u = 0; u < 4; u++) {
            int idx = u * 256 + tid;
            int m = idx >> 3, oct = idx & 7;
            cp16(ab + (unsigned)(m * CSTR + oct * 8) * 2,
                 &g_wsplit[(size_t)(m0 + m) * KW + k + oct * 8], 16);
        }
        // A1: w_lo slice (only for hi chunks)
        if (hi) {
#pragma unroll
            for (int u = 0; u < 4; u++) {
                int idx = u * 256 + tid;
                int m = idx >> 3, oct = idx & 7;
                cp16(a1b + (unsigned)(m * CSTR + oct * 8) * 2,
                     &g_wsplit[(size_t)(m0 + m) * KW + KC + k + oct * 8], 16);
            }
        }
        // B: 256 pixels x 64 bf16 from x_hi (hi chunks) or x_lo
        const __nv_bfloat16* Xp = hi ? g_xhi_t : g_xlo_t;
        int t3 = tap / 3;
        int yy = py + t3 - 1, xx = px + (tap - t3 * 3 - 1);
        bool v = pv && (unsigned)yy < HH && (unsigned)xx < WW;
        const __nv_bfloat16* src = v ? &Xp[(size_t)(yy * WW + xx) * CIN + ci0] : Xp;
        int sz = v ? 16 : 0;
        unsigned brow = bb + (unsigned)(tid * CSTR) * 2;
#pragma unroll
        for (int u = 0; u < 8; u++) cp16(brow + u * 16, src + u * 8, sz);
    };

    fill(0, 0);
    asm volatile("cp.async.commit_group;");

    for (int ch = 0; ch < NCH; ch++) {
        int st = ch & 1;
        if (ch + 1 < NCH) {
            fill(ch + 1, st ^ 1);
            asm volatile("cp.async.commit_group;");
            asm volatile("cp.async.wait_group 1;");
        } else {
            asm volatile("cp.async.wait_group 0;");
        }
        __syncthreads();
        const __nv_bfloat16* As0 = sm + st * STGE;
        const __nv_bfloat16* As1 = As0 + ASZE;
        const __nv_bfloat16* Bs = As0 + 2 * ASZE;
        bool hi = ch < 144;
#pragma unroll
        for (int ko = 0; ko < 64; ko += 16) {
            unsigned b[8][2];
#pragma unroll
            for (int nt = 0; nt < 8; nt++) {
                const __nv_bfloat16* bp = &Bs[(wn + nt * 8 + g) * CSTR + ko + tq * 2];
                b[nt][0] = *reinterpret_cast<const unsigned*>(bp);
                b[nt][1] = *reinterpret_cast<const unsigned*>(bp + 8);
            }
            unsigned a[4][4];
#pragma unroll
            for (int mt = 0; mt < 4; mt++) {
                const __nv_bfloat16* ap = &As0[(wm + mt * 16 + g) * CSTR + ko + tq * 2];
                a[mt][0] = *reinterpret_cast<const unsigned*>(ap);
                a[mt][1] = *reinterpret_cast<const unsigned*>(ap + 8 * CSTR);
                a[mt][2] = *reinterpret_cast<const unsigned*>(ap + 8);
                a[mt][3] = *reinterpret_cast<const unsigned*>(ap + 8 * CSTR + 8);
            }
#pragma unroll
            for (int mt = 0; mt < 4; mt++)
#pragma unroll
                for (int nt = 0; nt < 8; nt++) {
                    asm volatile(
                        "mma.sync.aligned.m16n8k16.row.col.f32.bf16.bf16.f32 "
                        "{%0,%1,%2,%3}, {%4,%5,%6,%7}, {%8,%9}, {%0,%1,%2,%3};"
                        : "+f"(c[mt][nt][0]), "+f"(c[mt][nt][1]),
                          "+f"(c[mt][nt][2]), "+f"(c[mt][nt][3])
                        : "r"(a[mt][0]), "r"(a[mt][1]), "r"(a[mt][2]), "r"(a[mt][3]),
                          "r"(b[nt][0]), "r"(b[nt][1]));
                }
            if (hi) {
#pragma unroll
                for (int mt = 0; mt < 4; mt++) {
                    const __nv_bfloat16* ap = &As1[(wm + mt * 16 + g) * CSTR + ko + tq * 2];
                    a[mt][0] = *reinterpret_cast<const unsigned*>(ap);
                    a[mt][1] = *reinterpret_cast<const unsigned*>(ap + 8 * CSTR);
                    a[mt][2] = *reinterpret_cast<const unsigned*>(ap + 8);
                    a[mt][3] = *reinterpret_cast<const unsigned*>(ap + 8 * CSTR + 8);
                }
#pragma unroll
                for (int mt = 0; mt < 4; mt++)
#pragma unroll
                    for (int nt = 0; nt < 8; nt++) {
                        asm volatile(
                            "mma.sync.aligned.m16n8k16.row.col.f32.bf16.bf16.f32 "
                            "{%0,%1,%2,%3}, {%4,%5,%6,%7}, {%8,%9}, {%0,%1,%2,%3};"
                            : "+f"(c[mt][nt][0]), "+f"(c[mt][nt][1]),
                              "+f"(c[mt][nt][2]), "+f"(c[mt][nt][3])
                            : "r"(a[mt][0]), "r"(a[mt][1]), "r"(a[mt][2]), "r"(a[mt][3]),
                              "r"(b[nt][0]), "r"(b[nt][1]));
                    }
            }
        }
        __syncthreads();
    }
#pragma unroll
    for (int mt = 0; mt < 4; mt++) {
#pragma unroll
        for (int nt = 0; nt < 8; nt++) {
            int m = m0 + wm + mt * 16 + g;
            int pp = n0 + wn + nt * 8 + tq * 2;
            float bv0 = bias[m], bv1 = bias[m + 8];
            float v0 = fmaxf(c[mt][nt][0] + bv0, 0.f);
            float v1 = fmaxf(c[mt][nt][1] + bv0, 0.f);
            float v2 = fmaxf(c[mt][nt][2] + bv1, 0.f);
            float v3 = fmaxf(c[mt][nt][3] + bv1, 0.f);
            if (pp + 1 < HW) {
                *reinterpret_cast<float2*>(&g_rpn[(size_t)m * HW + pp]) = make_float2(v0, v1);
                *reinterpret_cast<float2*>(&g_rpn[(size_t)(m + 8) * HW + pp]) = make_float2(v2, v3);
            } else if (pp < HW) {
                g_rpn[(size_t)m * HW + pp] = v0;
                g_rpn[(size_t)(m + 8) * HW + pp] = v2;
            }
        }
    }
}

__global__ void __launch_bounds__(128) k_conv1x1(const float* __restrict__ cw,
                                                 const float* __restrict__ cb,
                                                 const float* __restrict__ bw,
                                                 const float* __restrict__ bb) {
    __shared__ float ws[27 * 128];
    int tid = threadIdx.x;
    int p = blockIdx.x * 128 + tid;
    bool pv = p < HW;
    int half = blockIdx.y;
    float acc[27];
#pragma unroll
    for (int c = 0; c < 27; c++) {
        int oc = half * 27 + c;
        acc[c] = (oc < 18) ? cb[oc] : bb[oc - 18];
    }
    for (int kc = 0; kc < 512; kc += 128) {
        __syncthreads();
#pragma unroll
        for (int c = 0; c < 27; c++) {
            int oc = half * 27 + c;
            ws[c * 128 + tid] = (oc < 18) ? cw[oc * 512 + kc + tid] : bw[(oc - 18) * 512 + kc + tid];
        }
        __syncthreads();
        for (int k = 0; k < 128; k++) {
            float rv = pv ? g_rpn[(size_t)(kc + k) * HW + p] : 0.f;
#pragma unroll
            for (int c = 0; c < 27; c++) acc[c] = fmaf(rv, ws[c * 128 + k], acc[c]);
        }
    }
    if (pv) {
#pragma unroll
        for (int c = 0; c < 27; c++) {
            int oc = half * 27 + c;
            if (oc < 18) g_cls[oc * HW + p] = acc[c];
            else g_bbox[(oc - 18) * HW + p] = acc[c];
        }
    }
}

__global__ void k_fgboxes(const float* __restrict__ anchors) {
    int i = blockIdx.x * blockDim.x + threadIdx.x;
    if (i >= NANCH) return;
    int p = i / AA, a = i - p * AA;
    float s0 = g_cls[a * HW + p], s1 = g_cls[(9 + a) * HW + p];
    float m = fmaxf(s0, s1);
    float e0 = expf(s0 - m), e1 = expf(s1 - m);
    float fg = e1 / (e0 + e1);
    unsigned int u = __float_as_uint(fg);
    u = (u & 0x80000000u) ? ~u : (u | 0x80000000u);
    g_key[i] = u;
    atomicAdd(&g_hist[u >> 16], 1);
    float ax1 = anchors[i * 4], ay1 = anchors[i * 4 + 1];
    float ax2 = anchors[i * 4 + 2], ay2 = anchors[i * 4 + 3];
    float aw = ax2 - ax1 + 1.f, ah = ay2 - ay1 + 1.f;
    float acx = ax1 + 0.5f * aw, acy = ay1 + 0.5f * ah;
    float dx = g_bbox[(4 * a) * HW + p], dy = g_bbox[(4 * a + 1) * HW + p];
    float dw = g_bbox[(4 * a + 2) * HW + p], dh = g_bbox[(4 * a + 3) * HW + p];
    float pcx = dx * aw + acx, pcy = dy * ah + acy;
    float pw = expf(dw) * aw, ph = expf(dh) * ah;
    g_boxes[i * 4 + 0] = fminf(fmaxf(pcx - 0.5f * pw, 0.f), 1919.f);
    g_boxes[i * 4 + 1] = fminf(fmaxf(pcy - 0.5f * ph, 0.f), 1215.f);
    g_boxes[i * 4 + 2] = fminf(fmaxf(pcx + 0.5f * pw, 0.f), 1919.f);
    g_boxes[i * 4 + 3] = fminf(fmaxf(pcy + 0.5f * ph, 0.f), 1215.f);
}

__global__ void k_scan() {
    __shared__ int cs[256];
    int t = threadIdx.x;
    int s = 0;
    for (int j = 0; j < 256; j++) s += g_hist[t * 256 + j];
    cs[t] = s;
    __syncthreads();
    if (t == 0) {
        int acc = 0, chunk = 0;
        for (int i = 255; i >= 0; i--) {
            if (acc + cs[i] >= TOPN) { chunk = i; break; }
            acc += cs[i];
        }
        int T = chunk * 256;
        for (int b = chunk * 256 + 255; b >= chunk * 256; b--) {
            if (acc + g_hist[b] >= TOPN) { T = b; break; }
            acc += g_hist[b];
        }
        g_thr_bin = T;
    }
}

__global__ void k_compact() {
    int i = blockIdx.x * blockDim.x + threadIdx.x;
    if (i >= NANCH) return;
    unsigned int u = g_key[i];
    if ((int)(u >> 16) >= g_thr_bin) {
        int pos = atomicAdd(&g_cand_cnt, 1);
        g_ckey[pos] = u;
        g_cidx[pos] = i;
    }
}

__global__ void k_rank() {
    int c = g_cand_cnt;
    int i = blockIdx.x * blockDim.x + threadIdx.x;
    if (i >= c) return;
    unsigned int ki = g_ckey[i];
    int di = g_cidx[i];
    int rank = 0;
    for (int j = 0; j < c; j++) {
        unsigned int kj = g_ckey[j];
        if (kj > ki || (kj == ki && g_cidx[j] < di)) rank++;
    }
    if (rank < TOPN) {
        g_rois[rank * 4 + 0] = g_boxes[di * 4 + 0];
        g_rois[rank * 4 + 1] = g_boxes[di * 4 + 1];
        g_rois[rank * 4 + 2] = g_boxes[di * 4 + 2];
        g_rois[rank * 4 + 3] = g_boxes[di * 4 + 3];
    }
}

__global__ void __launch_bounds__(256) k_roialign() {
    int r = blockIdx.y, q = blockIdx.x;
    int pyy = q / 7, pxx = q - pyy * 7;
    float x1 = g_rois[r * 4 + 0] * 0.0625f, y1 = g_rois[r * 4 + 1] * 0.0625f;
    float x2 = g_rois[r * 4 + 2] * 0.0625f, y2 = g_rois[r * 4 + 3] * 0.0625f;
    float xs = fminf(fmaxf(x1 + (x2 - x1) * ((pxx + 0.5f) / 7.f), 0.f), 119.f);
    float ys = fminf(fmaxf(y1 + (y2 - y1) * ((pyy + 0.5f) / 7.f), 0.f), 75.f);
    float x0f = floorf(xs), y0f = floorf(ys);
    int x0i = (int)x0f, y0i = (int)y0f;
    int x1i = min(x0i + 1, 119), y1i = min(y0i + 1, 75);
    float wx = xs - x0f, wy = ys - y0f;
    float w00 = (1.f - wy) * (1.f - wx), w01 = (1.f - wy) * wx;
    float w10 = wy * (1.f - wx), w11 = wy * wx;
    const float* f00 = &g_feat_t[(size_t)(y0i * WW + x0i) * CIN];
    const float* f01 = &g_feat_t[(size_t)(y0i * WW + x1i) * CIN];
    const float* f10 = &g_feat_t[(size_t)(y1i * WW + x0i) * CIN];
    const float* f11 = &g_feat_t[(size_t)(y1i * WW + x1i) * CIN];
    __nv_bfloat16* outp = &g_pooledh[(size_t)r * KFC + q];
    for (int c = threadIdx.x; c < CIN; c += 256) {
        float v = f00[c] * w00 + f01[c] * w01 + f10[c] * w10 + f11[c] * w11;
        outp[c * 49] = __float2bfloat16_rn(v);
    }
}

__global__ void __launch_bounds__(256) k_fcgemm(const float* __restrict__ Bw) {
    __shared__ __nv_bfloat16 Asm[128 * 40];
    __shared__ __nv_bfloat16 Bks[32 * 132];
    int tid = threadIdx.x;
    int lane = tid & 31, warp = tid >> 5;
    int n0 = blockIdx.x * 128, m0 = blockIdx.y * 128;
    int kz = blockIdx.z * KPZ;
    int wm = (warp >> 2) * 64;
    int wn = (warp & 3) * 32;
    int g = lane >> 2, tq = lane & 3;
    float c[4][4][4];
#pragma unroll
    for (int mt = 0; mt < 4; mt++)
#pragma unroll
        for (int nt = 0; nt < 4; nt++)
#pragma unroll
            for (int u = 0; u < 4; u++) c[mt][nt][u] = 0.f;

    for (int ks = 0; ks < KPZ; ks += 32) {
#pragma unroll
        for (int u = 0; u < 2; u++) {
            int idx = tid * 2 + u;
            int r = idx >> 2, c8 = idx & 3;
            uint4 v = make_uint4(0, 0, 0, 0);
            int m = m0 + r;
            if (m < TOPN)
                v = *reinterpret_cast<const uint4*>(&g_pooledh[(size_t)m * KFC + kz + ks + c8 * 8]);
            *reinterpret_cast<uint4*>(&Asm[r * 40 + c8 * 8]) = v;
        }
#pragma unroll
        for (int i = 0; i < 4; i++) {
            int idx = i * 256 + tid;
            int k = idx >> 5, cc = idx & 31;
            float4 v = *reinterpret_cast<const float4*>(&Bw[(size_t)(kz + ks + k) * FCD + n0 + cc * 4]);
            __nv_bfloat162 p0 = __floats2bfloat162_rn(v.x, v.y);
            __nv_bfloat162 p1 = __floats2bfloat162_rn(v.z, v.w);
            uint2 st;
            st.x = *reinterpret_cast<unsigned*>(&p0);
            st.y = *reinterpret_cast<unsigned*>(&p1);
            *reinterpret_cast<uint2*>(&Bks[k * 132 + cc * 4]) = st;
        }
        __syncthreads();
#pragma unroll
        for (int ko = 0; ko < 32; ko += 16) {
            unsigned a[4][4];
#pragma unroll
            for (int mt = 0; mt < 4; mt++) {
                const __nv_bfloat16* ap = &Asm[(wm + mt * 16 + g) * 40 + ko + tq * 2];
                a[mt][0] = *reinterpret_cast<const unsigned*>(ap);
                a[mt][1] = *reinterpret_cast<const unsigned*>(ap + 8 * 40);
                a[mt][2] = *reinterpret_cast<const unsigned*>(ap + 8);
                a[mt][3] = *reinterpret_cast<const unsigned*>(ap + 8 * 40 + 8);
            }
            unsigned b[4][2];
#pragma unroll
            for (int nt = 0; nt < 4; nt++) {
                int n = wn + nt * 8 + g;
                unsigned lo0 = *reinterpret_cast<const unsigned short*>(&Bks[(ko + tq * 2) * 132 + n]);
                unsigned hi0 = *reinterpret_cast<const unsigned short*>(&Bks[(ko + tq * 2 + 1) * 132 + n]);
                b[nt][0] = lo0 | (hi0 << 16);
                unsigned lo1 = *reinterpret_cast<const unsigned short*>(&Bks[(ko + tq * 2 + 8) * 132 + n]);
                unsigned hi1 = *reinterpret_cast<const unsigned short*>(&Bks[(ko + tq * 2 + 9) * 132 + n]);
                b[nt][1] = lo1 | (hi1 << 16);
            }
#pragma unroll
            for (int mt = 0; mt < 4; mt++)
#pragma unroll
                for (int nt = 0; nt < 4; nt++) {
                    asm volatile(
                        "mma.sync.aligned.m16n8k16.row.col.f32.bf16.bf16.f32 "
                        "{%0,%1,%2,%3}, {%4,%5,%6,%7}, {%8,%9}, {%0,%1,%2,%3};"
                        : "+f"(c[mt][nt][0]), "+f"(c[mt][nt][1]),
                          "+f"(c[mt][nt][2]), "+f"(c[mt][nt][3])
                        : "r"(a[mt][0]), "r"(a[mt][1]), "r"(a[mt][2]), "r"(a[mt][3]),
                          "r"(b[nt][0]), "r"(b[nt][1]));
                }
        }
        __syncthreads();
    }
#pragma unroll
    for (int mt = 0; mt < 4; mt++) {
#pragma unroll
        for (int nt = 0; nt < 4; nt++) {
            int m = m0 + wm + mt * 16 + g;
            int n = n0 + wn + nt * 8 + tq * 2;
            if (m < TOPN) {
                float2 v = make_float2(c[mt][nt][0], c[mt][nt][1]);
                *reinterpret_cast<float2*>(&g_fcp[((size_t)blockIdx.z * 384 + m) * FCD + n]) = v;
            }
            if (m + 8 < TOPN) {
                float2 v = make_float2(c[mt][nt][2], c[mt][nt][3]);
                *reinterpret_cast<float2*>(&g_fcp[((size_t)blockIdx.z * 384 + m + 8) * FCD + n]) = v;
            }
        }
    }
}

__global__ void k_fcreduce(const float* __restrict__ fb) {
    int i = blockIdx.x * blockDim.x + threadIdx.x;
    if (i >= TOPN * FCD) return;
    int m = i / FCD, n = i - m * FCD;
    float s = fb[n];
#pragma unroll
    for (int z = 0; z < ZSPLIT; z++) s += g_fcp[((size_t)z * 384 + m) * FCD + n];
    g_fc7[i] = s > 0.f ? s : 0.f;
}

__global__ void __launch_bounds__(128) k_heads(const float* __restrict__ cw, const float* __restrict__ cb,
                                               const float* __restrict__ bw, const float* __restrict__ bb,
                                               const float* __restrict__ tgt, const float* __restrict__ biw,
                                               const float* __restrict__ bow, const int* __restrict__ lab) {
    __shared__ float sf[FCD];
    __shared__ float so[105];
    int r = blockIdx.x, t = threadIdx.x;
    for (int k = t; k < FCD; k += 128) sf[k] = g_fc7[(size_t)r * FCD + k];
    __syncthreads();
    if (t < 105) {
        float acc = (t < 21) ? cb[t] : bb[t - 21];
        if (t < 21) {
            for (int k = 0; k < FCD; k++) acc = fmaf(sf[k], cw[k * 21 + t], acc);
        } else {
            int o = t - 21;
            for (int k = 0; k < FCD; k++) acc = fmaf(sf[k], bw[k * 84 + o], acc);
        }
        so[t] = acc;
    }
    __syncthreads();
    if (t == 0) {
        float m = so[0];
        for (int c = 1; c < 21; c++) m = fmaxf(m, so[c]);
        float se = 0.f;
        for (int c = 0; c < 21; c++) se += expf(so[c] - m);
        float lse = m + logf(se);
        g_ce2[r] = lse - so[lab[r]];
        float lb = 0.f;
        for (int o = 0; o < 84; o++) {
            int idx = r * 84 + o;
            float d = biw[idx] * (so[21 + o] - tgt[idx]);
            float ad = fabsf(d);
            float loss = (ad < 1.f) ? d * d * 0.5f : (ad - 0.5f);
            lb += bow[idx] * loss;
        }
        g_lbrow[r] = lb;
    }
}

__global__ void __launch_bounds__(256) k_loss1(const int* __restrict__ lab, const float* __restrict__ tgt,
                                               const float* __restrict__ biw, const float* __restrict__ bow) {
    __shared__ float sce[256], scn[256], slb[256];
    int t = threadIdx.x;
    int gid = blockIdx.x * 256 + t;
    int stride = NB_RED * 256;
    float ce = 0.f, cn = 0.f, lb = 0.f;
    for (int e = gid; e < 36 * HW; e += stride) {
        int p = e / 36, c = e - p * 36;
        float d = biw[e] * (g_bbox[c * HW + p] - tgt[e]);
        float ad = fabsf(d);
        float loss = (ad < (1.f / 9.f)) ? d * d * 4.5f : (ad - 1.f / 18.f);
        lb += bow[e] * loss;
        if (e < NANCH) {
            int L = lab[e];
            if (L != -1) {
                int a = e / HW, pp = e - a * HW;
                float s0 = g_cls[a * HW + pp], s1 = g_cls[(9 + a) * HW + pp];
                float m = fmaxf(s0, s1);
                float lse = m + logf(expf(s0 - m) + expf(s1 - m));
                ce += lse - (L ? s1 : s0);
                cn += 1.f;
            }
        }
    }
    sce[t] = ce; scn[t] = cn; slb[t] = lb;
    __syncthreads();
    for (int o = 128; o > 0; o >>= 1) {
        if (t < o) { sce[t] += sce[t + o]; scn[t] += scn[t + o]; slb[t] += slb[t + o]; }
        __syncthreads();
    }
    if (t == 0) {
        g_red_ce[blockIdx.x] = sce[0];
        g_red_cnt[blockIdx.x] = scn[0];
        g_red_lb[blockIdx.x] = slb[0];
    }
}

__global__ void k_final(float* out) {
    if (threadIdx.x != 0) return;
    float ce = 0.f, cn = 0.f, lb = 0.f;
    for (int i = 0; i < NB_RED; i++) { ce += g_red_ce[i]; cn += g_red_cnt[i]; lb += g_red_lb[i]; }
    float ce2 = 0.f, lb2 = 0.f;
    for (int r = 0; r < TOPN; r++) { ce2 += g_ce2[r]; lb2 += g_lbrow[r]; }
    out[0] = ce / fmaxf(cn, 1.f) + lb + ce2 / TOPN + lb2 / TOPN;
}

extern "C" void kernel_launch(void* const* d_in, const int* in_sizes, int n_in,
                              void* d_out, int out_size) {
    const float* net_conv = (const float*)d_in[0];
    const float* rpn_w = (const float*)d_in[1];
    const float* rpn_b = (const float*)d_in[2];
    const float* rpn_cls_w = (const float*)d_in[3];
    const float* rpn_cls_b = (const float*)d_in[4];
    const float* rpn_bbox_w = (const float*)d_in[5];
    const float* rpn_bbox_b = (const float*)d_in[6];
    const float* fc_w = (const float*)d_in[7];
    const float* fc_b = (const float*)d_in[8];
    const float* cls_w = (const float*)d_in[9];
    const float* cls_b = (const float*)d_in[10];
    const float* bbox_w = (const float*)d_in[11];
    const float* bbox_b = (const float*)d_in[12];
    const float* anchors = (const float*)d_in[13];
    const float* rpn_tgt = (const float*)d_in[14];
    const float* rpn_biw = (const float*)d_in[15];
    const float* rpn_bow = (const float*)d_in[16];
    const float* roi_tgt = (const float*)d_in[17];
    const float* roi_biw = (const float*)d_in[18];
    const float* roi_bow = (const float*)d_in[19];
    const int* rpn_lab = (const int*)d_in[20];
    const int* roi_lab = (const int*)d_in[21];
    float* out = (float*)d_out;

    cudaFuncSetAttribute(k_conv3x3_mma, cudaFuncAttributeMaxDynamicSharedMemorySize, CONV_SMEM);

    k_zero<<<256, 256>>>();
    k_prep_w<<<(512 * KC + 255) / 256, 256>>>(rpn_w);
    k_prep_x<<<dim3(285, 32), dim3(32, 8)>>>(net_conv);
    k_conv3x3_mma<<<dim3(36, 4), 256, CONV_SMEM>>>(rpn_b);
    k_conv1x1<<<dim3(72, 2), 128>>>(rpn_cls_w, rpn_cls_b, rpn_bbox_w, rpn_bbox_b);
    k_fgboxes<<<321, 256>>>(anchors);
    k_scan<<<1, 256>>>();
    k_compact<<<321, 256>>>();
    k_rank<<<321, 256>>>();
    k_roialign<<<dim3(49, TOPN), 256>>>();
    k_fcgemm<<<dim3(16, 3, ZSPLIT), 256>>>(fc_w);
    k_fcreduce<<<(TOPN * FCD + 255) / 256, 256>>>(fc_b);
    k_heads<<<TOPN, 128>>>(cls_w, cls_b, bbox_w, bbox_b, roi_tgt, roi_biw, roi_bow, roi_lab);
    k_loss1<<<NB_RED, 256>>>(rpn_lab, rpn_tgt, rpn_biw, rpn_bow);
    k_final<<<1, 32>>>(out);
}

// round 10
// speedup vs baseline: 2.4348x; 1.0053x over previous
#include <cuda_runtime.h>
#include <cuda_bf16.h>
#include <math.h>

#define HH 76
#define WW 120
#define HW 9120
#define AA 9
#define NANCH 82080
#define CIN 1024
#define KC 9216
#define KW 18432
#define TOPN 300
#define FCD 2048
#define KFC 50176
#define ZSPLIT 4
#define KPZ (KFC / ZSPLIT)
#define NB_RED 256
#define CSTR 72
#define ASZE 9216              /* 128*72 elems */
#define STGE 36864             /* 2*ASZE + 256*72 elems */
#define STGB (STGE * 2)
#define CONV_SMEM (2 * STGB)

__device__ float g_rpn[512 * HW];
__device__ float g_cls[18 * HW];
__device__ float g_bbox[36 * HW];
__device__ unsigned int g_key[NANCH];
__device__ float g_boxes[NANCH * 4];
__device__ int g_hist[65536];
__device__ int g_thr_bin;
__device__ int g_cand_cnt;
__device__ unsigned int g_ckey[NANCH];
__device__ int g_cidx[NANCH];
__device__ float g_rois[TOPN * 4];
__device__ float g_feat_t[HW * CIN];
__device__ __nv_bfloat16 g_pooledh[TOPN * KFC];
__device__ float g_fcp[ZSPLIT * 384 * FCD];
__device__ float g_fc7[TOPN * FCD];
__device__ float g_ce2[TOPN];
__device__ float g_lbrow[TOPN];
__device__ float g_red_ce[NB_RED];
__device__ float g_red_cnt[NB_RED];
__device__ float g_red_lb[NB_RED];
__device__ __nv_bfloat16 g_wsplit[512 * KW];
__device__ __nv_bfloat16 g_xhi_t[HW * CIN];
__device__ __nv_bfloat16 g_xlo_t[HW * CIN];

__device__ __forceinline__ void cp16(unsigned dst, const void* src, int srcsize) {
    asm volatile("cp.async.cg.shared.global [%0], [%1], 16, %2;" :: "r"(dst), "l"(src), "r"(srcsize));
}

__global__ void k_zero() {
    int i = blockIdx.x * blockDim.x + threadIdx.x;
    if (i < 65536) g_hist[i] = 0;
    if (i == 0) g_cand_cnt = 0;
}

// weight split, tap-major K: k = slot*KC + t9*CIN + ci  (2 slots: hi, lo)
__global__ void k_prep_w(const float* __restrict__ Wt) {
    int i = blockIdx.x * blockDim.x + threadIdx.x;
    if (i >= 512 * KC) return;
    int m = i / KC, r = i - m * KC;
    int t9 = r >> 10, ci = r & 1023;
    float w = Wt[(size_t)m * KC + ci * 9 + t9];
    __nv_bfloat16 hi = __float2bfloat16_rn(w);
    __nv_bfloat16 lo = __float2bfloat16_rn(w - __bfloat162float(hi));
    size_t base = (size_t)m * KW;
    g_wsplit[base + r] = hi;
    g_wsplit[base + KC + r] = lo;
}

__global__ void k_prep_x(const float* __restrict__ X) {
    __shared__ float tile[32][33];
    int tx = threadIdx.x, ty = threadIdx.y;
    int p0 = blockIdx.x * 32, c0 = blockIdx.y * 32;
#pragma unroll
    for (int j = 0; j < 32; j += 8) tile[ty + j][tx] = X[(size_t)(c0 + ty + j) * HW + p0 + tx];
    __syncthreads();
#pragma unroll
    for (int j = 0; j < 32; j += 8) {
        float v = tile[tx][ty + j];
        size_t o = (size_t)(p0 + ty + j) * CIN + c0 + tx;
        g_feat_t[o] = v;
        __nv_bfloat16 hi = __float2bfloat16_rn(v);
        g_xhi_t[o] = hi;
        g_xlo_t[o] = __float2bfloat16_rn(v - __bfloat162float(hi));
    }
}

// conv3x3 implicit GEMM: block 128x256, 16 warps (warp tile 64x32), BK=64,
// cp.async 2-stage. 288 chunks: ch<144 -> B=x_hi shared by A slices (w_hi, w_lo);
// ch>=144 -> B=x_lo, A=w_hi.
__global__ void __launch_bounds__(512, 1) k_conv3x3_mma(const float* __restrict__ bias) {
    extern __shared__ __nv_bfloat16 sm[];
    unsigned smb = (unsigned)__cvta_generic_to_shared(sm);
    int tid = threadIdx.x;
    int lane = tid & 31, warp = tid >> 5;
    int n0 = blockIdx.x * 256, m0 = blockIdx.y * 128;
    int wm = (warp & 1) * 64, wn = (warp >> 1) * 32;
    int g = lane >> 2, tq = lane & 3;
    int pix = tid >> 1, half = tid & 1;
    int p = n0 + pix;
    bool pv = p < HW;
    int py = p / WW, px = p - py * WW;
    float c[4][4][4];
#pragma unroll
    for (int mt = 0; mt < 4; mt++)
#pragma unroll
        for (int nt = 0; nt < 4; nt++)
#pragma unroll
            for (int u = 0; u < 4; u++) c[mt][nt][u] = 0.f;

    const int NCH = 288;

    auto fill = [&](int ch, int st) {
        bool hi = ch < 144;
        int rem = hi ? ch : ch - 144;
        int tap = rem >> 4;
        int ci0 = (rem & 15) << 6;
        int k = tap * 1024 + ci0;
        unsigned ab = smb + (unsigned)(st * STGB);
        unsigned a1b = ab + ASZE * 2;
        unsigned bb = ab + 2 * ASZE * 2;
        // A0: 128 rows x 64 bf16 of w_hi (1024 uint4, 2 per thread)
#pragma unroll
        for (int u = 0; u < 2; u++) {
            int idx = u * 512 + tid;
            int m = idx >> 3, oct = idx & 7;
            cp16(ab + (unsigned)(m * CSTR + oct * 8) * 2,
                 &g_wsplit[(size_t)(m0 + m) * KW + k + oct * 8], 16);
        }
        // A1: w_lo slice (only for hi chunks)
        if (hi) {
#pragma unroll
            for (int u = 0; u < 2; u++) {
                int idx = u * 512 + tid;
                int m = idx >> 3, oct = idx & 7;
                cp16(a1b + (unsigned)(m * CSTR + oct * 8) * 2,
                     &g_wsplit[(size_t)(m0 + m) * KW + KC + k + oct * 8], 16);
            }
        }
        // B: 256 pixels x 64 bf16; each thread fills half a row (32 elems = 64B)
        const __nv_bfloat16* Xp = hi ? g_xhi_t : g_xlo_t;
        int t3 = tap / 3;
        int yy = py + t3 - 1, xx = px + (tap - t3 * 3 - 1);
        bool v = pv && (unsigned)yy < HH && (unsigned)xx < WW;
        const __nv_bfloat16* src = v ? &Xp[(size_t)(yy * WW + xx) * CIN + ci0 + half * 32] : Xp;
        int sz = v ? 16 : 0;
        unsigned brow = bb + (unsigned)(pix * CSTR + half * 32) * 2;
#pragma unroll
        for (int u = 0; u < 4; u++) cp16(brow + u * 16, src + u * 8, sz);
    };

    fill(0, 0);
    asm volatile("cp.async.commit_group;");

    for (int ch = 0; ch < NCH; ch++) {
        int st = ch & 1;
        if (ch + 1 < NCH) {
            fill(ch + 1, st ^ 1);
            asm volatile("cp.async.commit_group;");
            asm volatile("cp.async.wait_group 1;");
        } else {
            asm volatile("cp.async.wait_group 0;");
        }
        __syncthreads();
        const __nv_bfloat16* As0 = sm + st * STGE;
        const __nv_bfloat16* As1 = As0 + ASZE;
        const __nv_bfloat16* Bs = As0 + 2 * ASZE;
        bool hi = ch < 144;
#pragma unroll
        for (int ko = 0; ko < 64; ko += 16) {
            unsigned b[4][2];
#pragma unroll
            for (int nt = 0; nt < 4; nt++) {
                const __nv_bfloat16* bp = &Bs[(wn + nt * 8 + g) * CSTR + ko + tq * 2];
                b[nt][0] = *reinterpret_cast<const unsigned*>(bp);
                b[nt][1] = *reinterpret_cast<const unsigned*>(bp + 8);
            }
            unsigned a[4][4];
#pragma unroll
            for (int mt = 0; mt < 4; mt++) {
                const __nv_bfloat16* ap = &As0[(wm + mt * 16 + g) * CSTR + ko + tq * 2];
                a[mt][0] = *reinterpret_cast<const unsigned*>(ap);
                a[mt][1] = *reinterpret_cast<const unsigned*>(ap + 8 * CSTR);
                a[mt][2] = *reinterpret_cast<const unsigned*>(ap + 8);
                a[mt][3] = *reinterpret_cast<const unsigned*>(ap + 8 * CSTR + 8);
            }
#pragma unroll
            for (int mt = 0; mt < 4; mt++)
#pragma unroll
                for (int nt = 0; nt < 4; nt++) {
                    asm volatile(
                        "mma.sync.aligned.m16n8k16.row.col.f32.bf16.bf16.f32 "
                        "{%0,%1,%2,%3}, {%4,%5,%6,%7}, {%8,%9}, {%0,%1,%2,%3};"
                        : "+f"(c[mt][nt][0]), "+f"(c[mt][nt][1]),
                          "+f"(c[mt][nt][2]), "+f"(c[mt][nt][3])
                        : "r"(a[mt][0]), "r"(a[mt][1]), "r"(a[mt][2]), "r"(a[mt][3]),
                          "r"(b[nt][0]), "r"(b[nt][1]));
                }
            if (hi) {
#pragma unroll
                for (int mt = 0; mt < 4; mt++) {
                    const __nv_bfloat16* ap = &As1[(wm + mt * 16 + g) * CSTR + ko + tq * 2];
                    a[mt][0] = *reinterpret_cast<const unsigned*>(ap);
                    a[mt][1] = *reinterpret_cast<const unsigned*>(ap + 8 * CSTR);
                    a[mt][2] = *reinterpret_cast<const unsigned*>(ap + 8);
                    a[mt][3] = *reinterpret_cast<const unsigned*>(ap + 8 * CSTR + 8);
                }
#pragma unroll
                for (int mt = 0; mt < 4; mt++)
#pragma unroll
                    for (int nt = 0; nt < 4; nt++) {
                        asm volatile(
                            "mma.sync.aligned.m16n8k16.row.col.f32.bf16.bf16.f32 "
                            "{%0,%1,%2,%3}, {%4,%5,%6,%7}, {%8,%9}, {%0,%1,%2,%3};"
                            : "+f"(c[mt][nt][0]), "+f"(c[mt][nt][1]),
                              "+f"(c[mt][nt][2]), "+f"(c[mt][nt][3])
                            : "r"(a[mt][0]), "r"(a[mt][1]), "r"(a[mt][2]), "r"(a[mt][3]),
                              "r"(b[nt][0]), "r"(b[nt][1]));
                    }
            }
        }
        __syncthreads();
    }
#pragma unroll
    for (int mt = 0; mt < 4; mt++) {
#pragma unroll
        for (int nt = 0; nt < 4; nt++) {
            int m = m0 + wm + mt * 16 + g;
            int pp = n0 + wn + nt * 8 + tq * 2;
            float bv0 = bias[m], bv1 = bias[m + 8];
            float v0 = fmaxf(c[mt][nt][0] + bv0, 0.f);
            float v1 = fmaxf(c[mt][nt][1] + bv0, 0.f);
            float v2 = fmaxf(c[mt][nt][2] + bv1, 0.f);
            float v3 = fmaxf(c[mt][nt][3] + bv1, 0.f);
            if (pp + 1 < HW) {
                *reinterpret_cast<float2*>(&g_rpn[(size_t)m * HW + pp]) = make_float2(v0, v1);
                *reinterpret_cast<float2*>(&g_rpn[(size_t)(m + 8) * HW + pp]) = make_float2(v2, v3);
            } else if (pp < HW) {
                g_rpn[(size_t)m * HW + pp] = v0;
                g_rpn[(size_t)(m + 8) * HW + pp] = v2;
            }
        }
    }
}

__global__ void __launch_bounds__(128) k_conv1x1(const float* __restrict__ cw,
                                                 const float* __restrict__ cb,
                                                 const float* __restrict__ bw,
                                                 const float* __restrict__ bb) {
    __shared__ float ws[27 * 128];
    int tid = threadIdx.x;
    int p = blockIdx.x * 128 + tid;
    bool pv = p < HW;
    int half = blockIdx.y;
    float acc[27];
#pragma unroll
    for (int c = 0; c < 27; c++) {
        int oc = half * 27 + c;
        acc[c] = (oc < 18) ? cb[oc] : bb[oc - 18];
    }
    for (int kc = 0; kc < 512; kc += 128) {
        __syncthreads();
#pragma unroll
        for (int c = 0; c < 27; c++) {
            int oc = half * 27 + c;
            ws[c * 128 + tid] = (oc < 18) ? cw[oc * 512 + kc + tid] : bw[(oc - 18) * 512 + kc + tid];
        }
        __syncthreads();
        for (int k = 0; k < 128; k++) {
            float rv = pv ? g_rpn[(size_t)(kc + k) * HW + p] : 0.f;
#pragma unroll
            for (int c = 0; c < 27; c++) acc[c] = fmaf(rv, ws[c * 128 + k], acc[c]);
        }
    }
    if (pv) {
#pragma unroll
        for (int c = 0; c < 27; c++) {
            int oc = half * 27 + c;
            if (oc < 18) g_cls[oc * HW + p] = acc[c];
            else g_bbox[(oc - 18) * HW + p] = acc[c];
        }
    }
}

__global__ void k_fgboxes(const float* __restrict__ anchors) {
    int i = blockIdx.x * blockDim.x + threadIdx.x;
    if (i >= NANCH) return;
    int p = i / AA, a = i - p * AA;
    float s0 = g_cls[a * HW + p], s1 = g_cls[(9 + a) * HW + p];
    float m = fmaxf(s0, s1);
    float e0 = expf(s0 - m), e1 = expf(s1 - m);
    float fg = e1 / (e0 + e1);
    unsigned int u = __float_as_uint(fg);
    u = (u & 0x80000000u) ? ~u : (u | 0x80000000u);
    g_key[i] = u;
    atomicAdd(&g_hist[u >> 16], 1);
    float ax1 = anchors[i * 4], ay1 = anchors[i * 4 + 1];
    float ax2 = anchors[i * 4 + 2], ay2 = anchors[i * 4 + 3];
    float aw = ax2 - ax1 + 1.f, ah = ay2 - ay1 + 1.f;
    float acx = ax1 + 0.5f * aw, acy = ay1 + 0.5f * ah;
    float dx = g_bbox[(4 * a) * HW + p], dy = g_bbox[(4 * a + 1) * HW + p];
    float dw = g_bbox[(4 * a + 2) * HW + p], dh = g_bbox[(4 * a + 3) * HW + p];
    float pcx = dx * aw + acx, pcy = dy * ah + acy;
    float pw = expf(dw) * aw, ph = expf(dh) * ah;
    g_boxes[i * 4 + 0] = fminf(fmaxf(pcx - 0.5f * pw, 0.f), 1919.f);
    g_boxes[i * 4 + 1] = fminf(fmaxf(pcy - 0.5f * ph, 0.f), 1215.f);
    g_boxes[i * 4 + 2] = fminf(fmaxf(pcx + 0.5f * pw, 0.f), 1919.f);
    g_boxes[i * 4 + 3] = fminf(fmaxf(pcy + 0.5f * ph, 0.f), 1215.f);
}

__global__ void k_scan() {
    __shared__ int cs[256];
    int t = threadIdx.x;
    int s = 0;
    for (int j = 0; j < 256; j++) s += g_hist[t * 256 + j];
    cs[t] = s;
    __syncthreads();
    if (t == 0) {
        int acc = 0, chunk = 0;
        for (int i = 255; i >= 0; i--) {
            if (acc + cs[i] >= TOPN) { chunk = i; break; }
            acc += cs[i];
        }
        int T = chunk * 256;
        for (int b = chunk * 256 + 255; b >= chunk * 256; b--) {
            if (acc + g_hist[b] >= TOPN) { T = b; break; }
            acc += g_hist[b];
        }
        g_thr_bin = T;
    }
}

__global__ void k_compact() {
    int i = blockIdx.x * blockDim.x + threadIdx.x;
    if (i >= NANCH) return;
    unsigned int u = g_key[i];
    if ((int)(u >> 16) >= g_thr_bin) {
        int pos = atomicAdd(&g_cand_cnt, 1);
        g_ckey[pos] = u;
        g_cidx[pos] = i;
    }
}

__global__ void k_rank() {
    int c = g_cand_cnt;
    int i = blockIdx.x * blockDim.x + threadIdx.x;
    if (i >= c) return;
    unsigned int ki = g_ckey[i];
    int di = g_cidx[i];
    int rank = 0;
    for (int j = 0; j < c; j++) {
        unsigned int kj = g_ckey[j];
        if (kj > ki || (kj == ki && g_cidx[j] < di)) rank++;
    }
    if (rank < TOPN) {
        g_rois[rank * 4 + 0] = g_boxes[di * 4 + 0];
        g_rois[rank * 4 + 1] = g_boxes[di * 4 + 1];
        g_rois[rank * 4 + 2] = g_boxes[di * 4 + 2];
        g_rois[rank * 4 + 3] = g_boxes[di * 4 + 3];
    }
}

__global__ void __launch_bounds__(256) k_roialign() {
    int r = blockIdx.y, q = blockIdx.x;
    int pyy = q / 7, pxx = q - pyy * 7;
    float x1 = g_rois[r * 4 + 0] * 0.0625f, y1 = g_rois[r * 4 + 1] * 0.0625f;
    float x2 = g_rois[r * 4 + 2] * 0.0625f, y2 = g_rois[r * 4 + 3] * 0.0625f;
    float xs = fminf(fmaxf(x1 + (x2 - x1) * ((pxx + 0.5f) / 7.f), 0.f), 119.f);
    float ys = fminf(fmaxf(y1 + (y2 - y1) * ((pyy + 0.5f) / 7.f), 0.f), 75.f);
    float x0f = floorf(xs), y0f = floorf(ys);
    int x0i = (int)x0f, y0i = (int)y0f;
    int x1i = min(x0i + 1, 119), y1i = min(y0i + 1, 75);
    float wx = xs - x0f, wy = ys - y0f;
    float w00 = (1.f - wy) * (1.f - wx), w01 = (1.f - wy) * wx;
    float w10 = wy * (1.f - wx), w11 = wy * wx;
    const float* f00 = &g_feat_t[(size_t)(y0i * WW + x0i) * CIN];
    const float* f01 = &g_feat_t[(size_t)(y0i * WW + x1i) * CIN];
    const float* f10 = &g_feat_t[(size_t)(y1i * WW + x0i) * CIN];
    const float* f11 = &g_feat_t[(size_t)(y1i * WW + x1i) * CIN];
    __nv_bfloat16* outp = &g_pooledh[(size_t)r * KFC + q];
    for (int c = threadIdx.x; c < CIN; c += 256) {
        float v = f00[c] * w00 + f01[c] * w01 + f10[c] * w10 + f11[c] * w11;
        outp[c * 49] = __float2bfloat16_rn(v);
    }
}

__global__ void __launch_bounds__(256) k_fcgemm(const float* __restrict__ Bw) {
    __shared__ __nv_bfloat16 Asm[128 * 40];
    __shared__ __nv_bfloat16 Bks[32 * 132];
    int tid = threadIdx.x;
    int lane = tid & 31, warp = tid >> 5;
    int n0 = blockIdx.x * 128, m0 = blockIdx.y * 128;
    int kz = blockIdx.z * KPZ;
    int wm = (warp >> 2) * 64;
    int wn = (warp & 3) * 32;
    int g = lane >> 2, tq = lane & 3;
    float c[4][4][4];
#pragma unroll
    for (int mt = 0; mt < 4; mt++)
#pragma unroll
        for (int nt = 0; nt < 4; nt++)
#pragma unroll
            for (int u = 0; u < 4; u++) c[mt][nt][u] = 0.f;

    for (int ks = 0; ks < KPZ; ks += 32) {
#pragma unroll
        for (int u = 0; u < 2; u++) {
            int idx = tid * 2 + u;
            int r = idx >> 2, c8 = idx & 3;
            uint4 v = make_uint4(0, 0, 0, 0);
            int m = m0 + r;
            if (m < TOPN)
                v = *reinterpret_cast<const uint4*>(&g_pooledh[(size_t)m * KFC + kz + ks + c8 * 8]);
            *reinterpret_cast<uint4*>(&Asm[r * 40 + c8 * 8]) = v;
        }
#pragma unroll
        for (int i = 0; i < 4; i++) {
            int idx = i * 256 + tid;
            int k = idx >> 5, cc = idx & 31;
            float4 v = *reinterpret_cast<const float4*>(&Bw[(size_t)(kz + ks + k) * FCD + n0 + cc * 4]);
            __nv_bfloat162 p0 = __floats2bfloat162_rn(v.x, v.y);
            __nv_bfloat162 p1 = __floats2bfloat162_rn(v.z, v.w);
            uint2 st;
            st.x = *reinterpret_cast<unsigned*>(&p0);
            st.y = *reinterpret_cast<unsigned*>(&p1);
            *reinterpret_cast<uint2*>(&Bks[k * 132 + cc * 4]) = st;
        }
        __syncthreads();
#pragma unroll
        for (int ko = 0; ko < 32; ko += 16) {
            unsigned a[4][4];
#pragma unroll
            for (int mt = 0; mt < 4; mt++) {
                const __nv_bfloat16* ap = &Asm[(wm + mt * 16 + g) * 40 + ko + tq * 2];
                a[mt][0] = *reinterpret_cast<const unsigned*>(ap);
                a[mt][1] = *reinterpret_cast<const unsigned*>(ap + 8 * 40);
                a[mt][2] = *reinterpret_cast<const unsigned*>(ap + 8);
                a[mt][3] = *reinterpret_cast<const unsigned*>(ap + 8 * 40 + 8);
            }
            unsigned b[4][2];
#pragma unroll
            for (int nt = 0; nt < 4; nt++) {
                int n = wn + nt * 8 + g;
                unsigned lo0 = *reinterpret_cast<const unsigned short*>(&Bks[(ko + tq * 2) * 132 + n]);
                unsigned hi0 = *reinterpret_cast<const unsigned short*>(&Bks[(ko + tq * 2 + 1) * 132 + n]);
                b[nt][0] = lo0 | (hi0 << 16);
                unsigned lo1 = *reinterpret_cast<const unsigned short*>(&Bks[(ko + tq * 2 + 8) * 132 + n]);
                unsigned hi1 = *reinterpret_cast<const unsigned short*>(&Bks[(ko + tq * 2 + 9) * 132 + n]);
                b[nt][1] = lo1 | (hi1 << 16);
            }
#pragma unroll
            for (int mt = 0; mt < 4; mt++)
#pragma unroll
                for (int nt = 0; nt < 4; nt++) {
                    asm volatile(
                        "mma.sync.aligned.m16n8k16.row.col.f32.bf16.bf16.f32 "
                        "{%0,%1,%2,%3}, {%4,%5,%6,%7}, {%8,%9}, {%0,%1,%2,%3};"
                        : "+f"(c[mt][nt][0]), "+f"(c[mt][nt][1]),
                          "+f"(c[mt][nt][2]), "+f"(c[mt][nt][3])
                        : "r"(a[mt][0]), "r"(a[mt][1]), "r"(a[mt][2]), "r"(a[mt][3]),
                          "r"(b[nt][0]), "r"(b[nt][1]));
                }
        }
        __syncthreads();
    }
#pragma unroll
    for (int mt = 0; mt < 4; mt++) {
#pragma unroll
        for (int nt = 0; nt < 4; nt++) {
            int m = m0 + wm + mt * 16 + g;
            int n = n0 + wn + nt * 8 + tq * 2;
            if (m < TOPN) {
                float2 v = make_float2(c[mt][nt][0], c[mt][nt][1]);
                *reinterpret_cast<float2*>(&g_fcp[((size_t)blockIdx.z * 384 + m) * FCD + n]) = v;
            }
            if (m + 8 < TOPN) {
                float2 v = make_float2(c[mt][nt][2], c[mt][nt][3]);
                *reinterpret_cast<float2*>(&g_fcp[((size_t)blockIdx.z * 384 + m + 8) * FCD + n]) = v;
            }
        }
    }
}

__global__ void k_fcreduce(const float* __restrict__ fb) {
    int i = blockIdx.x * blockDim.x + threadIdx.x;
    if (i >= TOPN * FCD) return;
    int m = i / FCD, n = i - m * FCD;
    float s = fb[n];
#pragma unroll
    for (int z = 0; z < ZSPLIT; z++) s += g_fcp[((size_t)z * 384 + m) * FCD + n];
    g_fc7[i] = s > 0.f ? s : 0.f;
}

__global__ void __launch_bounds__(128) k_heads(const float* __restrict__ cw, const float* __restrict__ cb,
                                               const float* __restrict__ bw, const float* __restrict__ bb,
                                               const float* __restrict__ tgt, const float* __restrict__ biw,
                                               const float* __restrict__ bow, const int* __restrict__ lab) {
    __shared__ float sf[FCD];
    __shared__ float so[105];
    int r = blockIdx.x, t = threadIdx.x;
    for (int k = t; k < FCD; k += 128) sf[k] = g_fc7[(size_t)r * FCD + k];
    __syncthreads();
    if (t < 105) {
        float acc = (t < 21) ? cb[t] : bb[t - 21];
        if (t < 21) {
            for (int k = 0; k < FCD; k++) acc = fmaf(sf[k], cw[k * 21 + t], acc);
        } else {
            int o = t - 21;
            for (int k = 0; k < FCD; k++) acc = fmaf(sf[k], bw[k * 84 + o], acc);
        }
        so[t] = acc;
    }
    __syncthreads();
    if (t == 0) {
        float m = so[0];
        for (int c = 1; c < 21; c++) m = fmaxf(m, so[c]);
        float se = 0.f;
        for (int c = 0; c < 21; c++) se += expf(so[c] - m);
        float lse = m + logf(se);
        g_ce2[r] = lse - so[lab[r]];
        float lb = 0.f;
        for (int o = 0; o < 84; o++) {
            int idx = r * 84 + o;
            float d = biw[idx] * (so[21 + o] - tgt[idx]);
            float ad = fabsf(d);
            float loss = (ad < 1.f) ? d * d * 0.5f : (ad - 0.5f);
            lb += bow[idx] * loss;
        }
        g_lbrow[r] = lb;
    }
}

__global__ void __launch_bounds__(256) k_loss1(const int* __restrict__ lab, const float* __restrict__ tgt,
                                               const float* __restrict__ biw, const float* __restrict__ bow) {
    __shared__ float sce[256], scn[256], slb[256];
    int t = threadIdx.x;
    int gid = blockIdx.x * 256 + t;
    int stride = NB_RED * 256;
    float ce = 0.f, cn = 0.f, lb = 0.f;
    for (int e = gid; e < 36 * HW; e += stride) {
        int p = e / 36, c = e - p * 36;
        float d = biw[e] * (g_bbox[c * HW + p] - tgt[e]);
        float ad = fabsf(d);
        float loss = (ad < (1.f / 9.f)) ? d * d * 4.5f : (ad - 1.f / 18.f);
        lb += bow[e] * loss;
        if (e < NANCH) {
            int L = lab[e];
            if (L != -1) {
                int a = e / HW, pp = e - a * HW;
                float s0 = g_cls[a * HW + pp], s1 = g_cls[(9 + a) * HW + pp];
                float m = fmaxf(s0, s1);
                float lse = m + logf(expf(s0 - m) + expf(s1 - m));
                ce += lse - (L ? s1 : s0);
                cn += 1.f;
            }
        }
    }
    sce[t] = ce; scn[t] = cn; slb[t] = lb;
    __syncthreads();
    for (int o = 128; o > 0; o >>= 1) {
        if (t < o) { sce[t] += sce[t + o]; scn[t] += scn[t + o]; slb[t] += slb[t + o]; }
        __syncthreads();
    }
    if (t == 0) {
        g_red_ce[blockIdx.x] = sce[0];
        g_red_cnt[blockIdx.x] = scn[0];
        g_red_lb[blockIdx.x] = slb[0];
    }
}

__global__ void k_final(float* out) {
    if (threadIdx.x != 0) return;
    float ce = 0.f, cn = 0.f, lb = 0.f;
    for (int i = 0; i < NB_RED; i++) { ce += g_red_ce[i]; cn += g_red_cnt[i]; lb += g_red_lb[i]; }
    float ce2 = 0.f, lb2 = 0.f;
    for (int r = 0; r < TOPN; r++) { ce2 += g_ce2[r]; lb2 += g_lbrow[r]; }
    out[0] = ce / fmaxf(cn, 1.f) + lb + ce2 / TOPN + lb2 / TOPN;
}

extern "C" void kernel_launch(void* const* d_in, const int* in_sizes, int n_in,
                              void* d_out, int out_size) {
    const float* net_conv = (const float*)d_in[0];
    const float* rpn_w = (const float*)d_in[1];
    const float* rpn_b = (const float*)d_in[2];
    const float* rpn_cls_w = (const float*)d_in[3];
    const float* rpn_cls_b = (const float*)d_in[4];
    const float* rpn_bbox_w = (const float*)d_in[5];
    const float* rpn_bbox_b = (const float*)d_in[6];
    const float* fc_w = (const float*)d_in[7];
    const float* fc_b = (const float*)d_in[8];
    const float* cls_w = (const float*)d_in[9];
    const float* cls_b = (const float*)d_in[10];
    const float* bbox_w = (const float*)d_in[11];
    const float* bbox_b = (const float*)d_in[12];
    const float* anchors = (const float*)d_in[13];
    const float* rpn_tgt = (const float*)d_in[14];
    const float* rpn_biw = (const float*)d_in[15];
    const float* rpn_bow = (const float*)d_in[16];
    const float* roi_tgt = (const float*)d_in[17];
    const float* roi_biw = (const float*)d_in[18];
    const float* roi_bow = (const float*)d_in[19];
    const int* rpn_lab = (const int*)d_in[20];
    const int* roi_lab = (const int*)d_in[21];
    float* out = (float*)d_out;

    cudaFuncSetAttribute(k_conv3x3_mma, cudaFuncAttributeMaxDynamicSharedMemorySize, CONV_SMEM);

    k_zero<<<256, 256>>>();
    k_prep_w<<<(512 * KC + 255) / 256, 256>>>(rpn_w);
    k_prep_x<<<dim3(285, 32), dim3(32, 8)>>>(net_conv);
    k_conv3x3_mma<<<dim3(36, 4), 512, CONV_SMEM>>>(rpn_b);
    k_conv1x1<<<dim3(72, 2), 128>>>(rpn_cls_w, rpn_cls_b, rpn_bbox_w, rpn_bbox_b);
    k_fgboxes<<<321, 256>>>(anchors);
    k_scan<<<1, 256>>>();
    k_compact<<<321, 256>>>();
    k_rank<<<321, 256>>>();
    k_roialign<<<dim3(49, TOPN), 256>>>();
    k_fcgemm<<<dim3(16, 3, ZSPLIT), 256>>>(fc_w);
    k_fcreduce<<<(TOPN * FCD + 255) / 256, 256>>>(fc_b);
    k_heads<<<TOPN, 128>>>(cls_w, cls_b, bbox_w, bbox_b, roi_tgt, roi_biw, roi_bow, roi_lab);
    k_loss1<<<NB_RED, 256>>>(rpn_lab, rpn_tgt, rpn_biw, rpn_bow);
    k_final<<<1, 32>>>(out);
}

// round 11
// speedup vs baseline: 2.4732x; 1.0158x over previous
#include <cuda_runtime.h>
#include <cuda_bf16.h>
#include <math.h>

#define HH 76
#define WW 120
#define HW 9120
#define AA 9
#define NANCH 82080
#define CIN 1024
#define KC 9216
#define KW 18432
#define TOPN 300
#define FCD 2048
#define KFC 50176
#define ZSPLIT 4
#define KPZ (KFC / ZSPLIT)
#define NB_RED 256
#define CSTR 72
#define ASZE 9216              /* 128*72 elems */
#define STGE 36864             /* 2*ASZE + 256*72 elems */
#define STGB (STGE * 2)
#define CONV_SMEM (2 * STGB)

__device__ float g_rpn[512 * HW];
__device__ float g_cls[18 * HW];
__device__ float g_bbox[36 * HW];
__device__ unsigned int g_key[NANCH];
__device__ float g_boxes[NANCH * 4];
__device__ int g_hist[65536];
__device__ int g_thr_bin;
__device__ int g_cand_cnt;
__device__ unsigned int g_ckey[NANCH];
__device__ int g_cidx[NANCH];
__device__ float g_rois[TOPN * 4];
__device__ float g_feat_t[HW * CIN];
__device__ __nv_bfloat16 g_pooledh[TOPN * KFC];
__device__ float g_fcp[ZSPLIT * 384 * FCD];
__device__ float g_fc7[TOPN * FCD];
__device__ float g_ce2[TOPN];
__device__ float g_lbrow[TOPN];
__device__ float g_red_ce[NB_RED];
__device__ float g_red_cnt[NB_RED];
__device__ float g_red_lb[NB_RED];
__device__ __nv_bfloat16 g_wsplit[512 * KW];
__device__ __nv_bfloat16 g_xhi_t[HW * CIN];
__device__ __nv_bfloat16 g_xlo_t[HW * CIN];

__device__ __forceinline__ void cp16(unsigned dst, const void* src, int srcsize) {
    asm volatile("cp.async.cg.shared.global [%0], [%1], 16, %2;" :: "r"(dst), "l"(src), "r"(srcsize));
}

__global__ void k_zero() {
    int i = blockIdx.x * blockDim.x + threadIdx.x;
    if (i < 65536) g_hist[i] = 0;
    if (i == 0) g_cand_cnt = 0;
}

// weight split, tap-major K: k = slot*KC + t9*CIN + ci  (2 slots: hi, lo)
__global__ void k_prep_w(const float* __restrict__ Wt) {
    int i = blockIdx.x * blockDim.x + threadIdx.x;
    if (i >= 512 * KC) return;
    int m = i / KC, r = i - m * KC;
    int t9 = r >> 10, ci = r & 1023;
    float w = Wt[(size_t)m * KC + ci * 9 + t9];
    __nv_bfloat16 hi = __float2bfloat16_rn(w);
    __nv_bfloat16 lo = __float2bfloat16_rn(w - __bfloat162float(hi));
    size_t base = (size_t)m * KW;
    g_wsplit[base + r] = hi;
    g_wsplit[base + KC + r] = lo;
}

__global__ void k_prep_x(const float* __restrict__ X) {
    __shared__ float tile[32][33];
    int tx = threadIdx.x, ty = threadIdx.y;
    int p0 = blockIdx.x * 32, c0 = blockIdx.y * 32;
#pragma unroll
    for (int j = 0; j < 32; j += 8) tile[ty + j][tx] = X[(size_t)(c0 + ty + j) * HW + p0 + tx];
    __syncthreads();
#pragma unroll
    for (int j = 0; j < 32; j += 8) {
        float v = tile[tx][ty + j];
        size_t o = (size_t)(p0 + ty + j) * CIN + c0 + tx;
        g_feat_t[o] = v;
        __nv_bfloat16 hi = __float2bfloat16_rn(v);
        g_xhi_t[o] = hi;
        g_xlo_t[o] = __float2bfloat16_rn(v - __bfloat162float(hi));
    }
}

// conv3x3 implicit GEMM: block 128x256, 16 warps (warp tile 64x32), BK=64,
// cp.async 2-stage. 288 chunks: ch<144 -> B=x_hi shared by A slices (w_hi, w_lo);
// ch>=144 -> B=x_lo, A=w_hi.
__global__ void __launch_bounds__(512, 1) k_conv3x3_mma(const float* __restrict__ bias) {
    extern __shared__ __nv_bfloat16 sm[];
    unsigned smb = (unsigned)__cvta_generic_to_shared(sm);
    int tid = threadIdx.x;
    int lane = tid & 31, warp = tid >> 5;
    int n0 = blockIdx.x * 256, m0 = blockIdx.y * 128;
    int wm = (warp & 1) * 64, wn = (warp >> 1) * 32;
    int g = lane >> 2, tq = lane & 3;
    int pix = tid >> 1, half = tid & 1;
    int p = n0 + pix;
    bool pv = p < HW;
    int py = p / WW, px = p - py * WW;
    float c[4][4][4];
#pragma unroll
    for (int mt = 0; mt < 4; mt++)
#pragma unroll
        for (int nt = 0; nt < 4; nt++)
#pragma unroll
            for (int u = 0; u < 4; u++) c[mt][nt][u] = 0.f;

    const int NCH = 288;

    auto fill = [&](int ch, int st) {
        bool hi = ch < 144;
        int rem = hi ? ch : ch - 144;
        int tap = rem >> 4;
        int ci0 = (rem & 15) << 6;
        int k = tap * 1024 + ci0;
        unsigned ab = smb + (unsigned)(st * STGB);
        unsigned a1b = ab + ASZE * 2;
        unsigned bb = ab + 2 * ASZE * 2;
#pragma unroll
        for (int u = 0; u < 2; u++) {
            int idx = u * 512 + tid;
            int m = idx >> 3, oct = idx & 7;
            cp16(ab + (unsigned)(m * CSTR + oct * 8) * 2,
                 &g_wsplit[(size_t)(m0 + m) * KW + k + oct * 8], 16);
        }
        if (hi) {
#pragma unroll
            for (int u = 0; u < 2; u++) {
                int idx = u * 512 + tid;
                int m = idx >> 3, oct = idx & 7;
                cp16(a1b + (unsigned)(m * CSTR + oct * 8) * 2,
                     &g_wsplit[(size_t)(m0 + m) * KW + KC + k + oct * 8], 16);
            }
        }
        const __nv_bfloat16* Xp = hi ? g_xhi_t : g_xlo_t;
        int t3 = tap / 3;
        int yy = py + t3 - 1, xx = px + (tap - t3 * 3 - 1);
        bool v = pv && (unsigned)yy < HH && (unsigned)xx < WW;
        const __nv_bfloat16* src = v ? &Xp[(size_t)(yy * WW + xx) * CIN + ci0 + half * 32] : Xp;
        int sz = v ? 16 : 0;
        unsigned brow = bb + (unsigned)(pix * CSTR + half * 32) * 2;
#pragma unroll
        for (int u = 0; u < 4; u++) cp16(brow + u * 16, src + u * 8, sz);
    };

    fill(0, 0);
    asm volatile("cp.async.commit_group;");

    for (int ch = 0; ch < NCH; ch++) {
        int st = ch & 1;
        if (ch + 1 < NCH) {
            fill(ch + 1, st ^ 1);
            asm volatile("cp.async.commit_group;");
            asm volatile("cp.async.wait_group 1;");
        } else {
            asm volatile("cp.async.wait_group 0;");
        }
        __syncthreads();
        const __nv_bfloat16* As0 = sm + st * STGE;
        const __nv_bfloat16* As1 = As0 + ASZE;
        const __nv_bfloat16* Bs = As0 + 2 * ASZE;
        bool hi = ch < 144;
#pragma unroll
        for (int ko = 0; ko < 64; ko += 16) {
            unsigned b[4][2];
#pragma unroll
            for (int nt = 0; nt < 4; nt++) {
                const __nv_bfloat16* bp = &Bs[(wn + nt * 8 + g) * CSTR + ko + tq * 2];
                b[nt][0] = *reinterpret_cast<const unsigned*>(bp);
                b[nt][1] = *reinterpret_cast<const unsigned*>(bp + 8);
            }
            unsigned a[4][4];
#pragma unroll
            for (int mt = 0; mt < 4; mt++) {
                const __nv_bfloat16* ap = &As0[(wm + mt * 16 + g) * CSTR + ko + tq * 2];
                a[mt][0] = *reinterpret_cast<const unsigned*>(ap);
                a[mt][1] = *reinterpret_cast<const unsigned*>(ap + 8 * CSTR);
                a[mt][2] = *reinterpret_cast<const unsigned*>(ap + 8);
                a[mt][3] = *reinterpret_cast<const unsigned*>(ap + 8 * CSTR + 8);
            }
#pragma unroll
            for (int mt = 0; mt < 4; mt++)
#pragma unroll
                for (int nt = 0; nt < 4; nt++) {
                    asm volatile(
                        "mma.sync.aligned.m16n8k16.row.col.f32.bf16.bf16.f32 "
                        "{%0,%1,%2,%3}, {%4,%5,%6,%7}, {%8,%9}, {%0,%1,%2,%3};"
                        : "+f"(c[mt][nt][0]), "+f"(c[mt][nt][1]),
                          "+f"(c[mt][nt][2]), "+f"(c[mt][nt][3])
                        : "r"(a[mt][0]), "r"(a[mt][1]), "r"(a[mt][2]), "r"(a[mt][3]),
                          "r"(b[nt][0]), "r"(b[nt][1]));
                }
            if (hi) {
#pragma unroll
                for (int mt = 0; mt < 4; mt++) {
                    const __nv_bfloat16* ap = &As1[(wm + mt * 16 + g) * CSTR + ko + tq * 2];
                    a[mt][0] = *reinterpret_cast<const unsigned*>(ap);
                    a[mt][1] = *reinterpret_cast<const unsigned*>(ap + 8 * CSTR);
                    a[mt][2] = *reinterpret_cast<const unsigned*>(ap + 8);
                    a[mt][3] = *reinterpret_cast<const unsigned*>(ap + 8 * CSTR + 8);
                }
#pragma unroll
                for (int mt = 0; mt < 4; mt++)
#pragma unroll
                    for (int nt = 0; nt < 4; nt++) {
                        asm volatile(
                            "mma.sync.aligned.m16n8k16.row.col.f32.bf16.bf16.f32 "
                            "{%0,%1,%2,%3}, {%4,%5,%6,%7}, {%8,%9}, {%0,%1,%2,%3};"
                            : "+f"(c[mt][nt][0]), "+f"(c[mt][nt][1]),
                              "+f"(c[mt][nt][2]), "+f"(c[mt][nt][3])
                            : "r"(a[mt][0]), "r"(a[mt][1]), "r"(a[mt][2]), "r"(a[mt][3]),
                              "r"(b[nt][0]), "r"(b[nt][1]));
                    }
            }
        }
        __syncthreads();
    }
#pragma unroll
    for (int mt = 0; mt < 4; mt++) {
#pragma unroll
        for (int nt = 0; nt < 4; nt++) {
            int m = m0 + wm + mt * 16 + g;
            int pp = n0 + wn + nt * 8 + tq * 2;
            float bv0 = bias[m], bv1 = bias[m + 8];
            float v0 = fmaxf(c[mt][nt][0] + bv0, 0.f);
            float v1 = fmaxf(c[mt][nt][1] + bv0, 0.f);
            float v2 = fmaxf(c[mt][nt][2] + bv1, 0.f);
            float v3 = fmaxf(c[mt][nt][3] + bv1, 0.f);
            if (pp + 1 < HW) {
                *reinterpret_cast<float2*>(&g_rpn[(size_t)m * HW + pp]) = make_float2(v0, v1);
                *reinterpret_cast<float2*>(&g_rpn[(size_t)(m + 8) * HW + pp]) = make_float2(v2, v3);
            } else if (pp < HW) {
                g_rpn[(size_t)m * HW + pp] = v0;
                g_rpn[(size_t)(m + 8) * HW + pp] = v2;
            }
        }
    }
}

__global__ void __launch_bounds__(128) k_conv1x1(const float* __restrict__ cw,
                                                 const float* __restrict__ cb,
                                                 const float* __restrict__ bw,
                                                 const float* __restrict__ bb) {
    __shared__ float ws[27 * 128];
    int tid = threadIdx.x;
    int p = blockIdx.x * 128 + tid;
    bool pv = p < HW;
    int half = blockIdx.y;
    float acc[27];
#pragma unroll
    for (int c = 0; c < 27; c++) {
        int oc = half * 27 + c;
        acc[c] = (oc < 18) ? cb[oc] : bb[oc - 18];
    }
    for (int kc = 0; kc < 512; kc += 128) {
        __syncthreads();
#pragma unroll
        for (int c = 0; c < 27; c++) {
            int oc = half * 27 + c;
            ws[c * 128 + tid] = (oc < 18) ? cw[oc * 512 + kc + tid] : bw[(oc - 18) * 512 + kc + tid];
        }
        __syncthreads();
        for (int k = 0; k < 128; k++) {
            float rv = pv ? g_rpn[(size_t)(kc + k) * HW + p] : 0.f;
#pragma unroll
            for (int c = 0; c < 27; c++) acc[c] = fmaf(rv, ws[c * 128 + k], acc[c]);
        }
    }
    if (pv) {
#pragma unroll
        for (int c = 0; c < 27; c++) {
            int oc = half * 27 + c;
            if (oc < 18) g_cls[oc * HW + p] = acc[c];
            else g_bbox[(oc - 18) * HW + p] = acc[c];
        }
    }
}

__global__ void k_fgboxes(const float* __restrict__ anchors) {
    int i = blockIdx.x * blockDim.x + threadIdx.x;
    if (i >= NANCH) return;
    int p = i / AA, a = i - p * AA;
    float s0 = g_cls[a * HW + p], s1 = g_cls[(9 + a) * HW + p];
    float m = fmaxf(s0, s1);
    float e0 = expf(s0 - m), e1 = expf(s1 - m);
    float fg = e1 / (e0 + e1);
    unsigned int u = __float_as_uint(fg);
    u = (u & 0x80000000u) ? ~u : (u | 0x80000000u);
    g_key[i] = u;
    atomicAdd(&g_hist[u >> 16], 1);
    float ax1 = anchors[i * 4], ay1 = anchors[i * 4 + 1];
    float ax2 = anchors[i * 4 + 2], ay2 = anchors[i * 4 + 3];
    float aw = ax2 - ax1 + 1.f, ah = ay2 - ay1 + 1.f;
    float acx = ax1 + 0.5f * aw, acy = ay1 + 0.5f * ah;
    float dx = g_bbox[(4 * a) * HW + p], dy = g_bbox[(4 * a + 1) * HW + p];
    float dw = g_bbox[(4 * a + 2) * HW + p], dh = g_bbox[(4 * a + 3) * HW + p];
    float pcx = dx * aw + acx, pcy = dy * ah + acy;
    float pw = expf(dw) * aw, ph = expf(dh) * ah;
    g_boxes[i * 4 + 0] = fminf(fmaxf(pcx - 0.5f * pw, 0.f), 1919.f);
    g_boxes[i * 4 + 1] = fminf(fmaxf(pcy - 0.5f * ph, 0.f), 1215.f);
    g_boxes[i * 4 + 2] = fminf(fmaxf(pcx + 0.5f * pw, 0.f), 1919.f);
    g_boxes[i * 4 + 3] = fminf(fmaxf(pcy + 0.5f * ph, 0.f), 1215.f);
}

__global__ void k_scan() {
    __shared__ int cs[256];
    int t = threadIdx.x;
    int s = 0;
    for (int j = 0; j < 256; j++) s += g_hist[t * 256 + j];
    cs[t] = s;
    __syncthreads();
    if (t == 0) {
        int acc = 0, chunk = 0;
        for (int i = 255; i >= 0; i--) {
            if (acc + cs[i] >= TOPN) { chunk = i; break; }
            acc += cs[i];
        }
        int T = chunk * 256;
        for (int b = chunk * 256 + 255; b >= chunk * 256; b--) {
            if (acc + g_hist[b] >= TOPN) { T = b; break; }
            acc += g_hist[b];
        }
        g_thr_bin = T;
    }
}

__global__ void k_compact() {
    int i = blockIdx.x * blockDim.x + threadIdx.x;
    if (i >= NANCH) return;
    unsigned int u = g_key[i];
    if ((int)(u >> 16) >= g_thr_bin) {
        int pos = atomicAdd(&g_cand_cnt, 1);
        g_ckey[pos] = u;
        g_cidx[pos] = i;
    }
}

__global__ void k_rank() {
    int c = g_cand_cnt;
    int i = blockIdx.x * blockDim.x + threadIdx.x;
    if (i >= c) return;
    unsigned int ki = g_ckey[i];
    int di = g_cidx[i];
    int rank = 0;
    for (int j = 0; j < c; j++) {
        unsigned int kj = g_ckey[j];
        if (kj > ki || (kj == ki && g_cidx[j] < di)) rank++;
    }
    if (rank < TOPN) {
        g_rois[rank * 4 + 0] = g_boxes[di * 4 + 0];
        g_rois[rank * 4 + 1] = g_boxes[di * 4 + 1];
        g_rois[rank * 4 + 2] = g_boxes[di * 4 + 2];
        g_rois[rank * 4 + 3] = g_boxes[di * 4 + 3];
    }
}

// q-major pooled layout: k' = q*1024 + c -> fully coalesced writes
__global__ void __launch_bounds__(256) k_roialign() {
    int r = blockIdx.y, q = blockIdx.x;
    int pyy = q / 7, pxx = q - pyy * 7;
    float x1 = g_rois[r * 4 + 0] * 0.0625f, y1 = g_rois[r * 4 + 1] * 0.0625f;
    float x2 = g_rois[r * 4 + 2] * 0.0625f, y2 = g_rois[r * 4 + 3] * 0.0625f;
    float xs = fminf(fmaxf(x1 + (x2 - x1) * ((pxx + 0.5f) / 7.f), 0.f), 119.f);
    float ys = fminf(fmaxf(y1 + (y2 - y1) * ((pyy + 0.5f) / 7.f), 0.f), 75.f);
    float x0f = floorf(xs), y0f = floorf(ys);
    int x0i = (int)x0f, y0i = (int)y0f;
    int x1i = min(x0i + 1, 119), y1i = min(y0i + 1, 75);
    float wx = xs - x0f, wy = ys - y0f;
    float w00 = (1.f - wy) * (1.f - wx), w01 = (1.f - wy) * wx;
    float w10 = wy * (1.f - wx), w11 = wy * wx;
    const float* f00 = &g_feat_t[(size_t)(y0i * WW + x0i) * CIN];
    const float* f01 = &g_feat_t[(size_t)(y0i * WW + x1i) * CIN];
    const float* f10 = &g_feat_t[(size_t)(y1i * WW + x0i) * CIN];
    const float* f11 = &g_feat_t[(size_t)(y1i * WW + x1i) * CIN];
    __nv_bfloat16* outp = &g_pooledh[(size_t)r * KFC + q * 1024];
    for (int c = threadIdx.x; c < CIN; c += 256) {
        float v = f00[c] * w00 + f01[c] * w01 + f10[c] * w10 + f11[c] * w11;
        outp[c] = __float2bfloat16_rn(v);
    }
}

__global__ void __launch_bounds__(256) k_fcgemm(const float* __restrict__ Bw) {
    __shared__ __nv_bfloat16 Asm[128 * 40];
    __shared__ __nv_bfloat16 Bks[32 * 132];
    int tid = threadIdx.x;
    int lane = tid & 31, warp = tid >> 5;
    int n0 = blockIdx.x * 128, m0 = blockIdx.y * 128;
    int kz = blockIdx.z * KPZ;
    int wm = (warp >> 2) * 64;
    int wn = (warp & 3) * 32;
    int g = lane >> 2, tq = lane & 3;
    int mlim = TOPN - m0 - wm;  // valid rows in this warp's 64-row range
    float c[4][4][4];
#pragma unroll
    for (int mt = 0; mt < 4; mt++)
#pragma unroll
        for (int nt = 0; nt < 4; nt++)
#pragma unroll
            for (int u = 0; u < 4; u++) c[mt][nt][u] = 0.f;

    for (int ks = 0; ks < KPZ; ks += 32) {
#pragma unroll
        for (int u = 0; u < 2; u++) {
            int idx = tid * 2 + u;
            int r = idx >> 2, c8 = idx & 3;
            uint4 v = make_uint4(0, 0, 0, 0);
            int m = m0 + r;
            if (m < TOPN)
                v = *reinterpret_cast<const uint4*>(&g_pooledh[(size_t)m * KFC + kz + ks + c8 * 8]);
            *reinterpret_cast<uint4*>(&Asm[r * 40 + c8 * 8]) = v;
        }
#pragma unroll
        for (int i = 0; i < 4; i++) {
            int idx = i * 256 + tid;
            int k = idx >> 5, cc = idx & 31;
            int kp = kz + ks + k;
            int ok = (kp & 1023) * 49 + (kp >> 10);  // q-major -> original fc_w row
            float4 v = *reinterpret_cast<const float4*>(&Bw[(size_t)ok * FCD + n0 + cc * 4]);
            __nv_bfloat162 p0 = __floats2bfloat162_rn(v.x, v.y);
            __nv_bfloat162 p1 = __floats2bfloat162_rn(v.z, v.w);
            uint2 st;
            st.x = *reinterpret_cast<unsigned*>(&p0);
            st.y = *reinterpret_cast<unsigned*>(&p1);
            *reinterpret_cast<uint2*>(&Bks[k * 132 + cc * 4]) = st;
        }
        __syncthreads();
#pragma unroll
        for (int ko = 0; ko < 32; ko += 16) {
            unsigned a[4][4];
#pragma unroll
            for (int mt = 0; mt < 4; mt++) {
                if (mt * 16 >= mlim) continue;
                const __nv_bfloat16* ap = &Asm[(wm + mt * 16 + g) * 40 + ko + tq * 2];
                a[mt][0] = *reinterpret_cast<const unsigned*>(ap);
                a[mt][1] = *reinterpret_cast<const unsigned*>(ap + 8 * 40);
                a[mt][2] = *reinterpret_cast<const unsigned*>(ap + 8);
                a[mt][3] = *reinterpret_cast<const unsigned*>(ap + 8 * 40 + 8);
            }
            unsigned b[4][2];
#pragma unroll
            for (int nt = 0; nt < 4; nt++) {
                int n = wn + nt * 8 + g;
                unsigned lo0 = *reinterpret_cast<const unsigned short*>(&Bks[(ko + tq * 2) * 132 + n]);
                unsigned hi0 = *reinterpret_cast<const unsigned short*>(&Bks[(ko + tq * 2 + 1) * 132 + n]);
                b[nt][0] = lo0 | (hi0 << 16);
                unsigned lo1 = *reinterpret_cast<const unsigned short*>(&Bks[(ko + tq * 2 + 8) * 132 + n]);
                unsigned hi1 = *reinterpret_cast<const unsigned short*>(&Bks[(ko + tq * 2 + 9) * 132 + n]);
                b[nt][1] = lo1 | (hi1 << 16);
            }
#pragma unroll
            for (int mt = 0; mt < 4; mt++) {
                if (mt * 16 >= mlim) continue;
#pragma unroll
                for (int nt = 0; nt < 4; nt++) {
                    asm volatile(
                        "mma.sync.aligned.m16n8k16.row.col.f32.bf16.bf16.f32 "
                        "{%0,%1,%2,%3}, {%4,%5,%6,%7}, {%8,%9}, {%0,%1,%2,%3};"
                        : "+f"(c[mt][nt][0]), "+f"(c[mt][nt][1]),
                          "+f"(c[mt][nt][2]), "+f"(c[mt][nt][3])
                        : "r"(a[mt][0]), "r"(a[mt][1]), "r"(a[mt][2]), "r"(a[mt][3]),
                          "r"(b[nt][0]), "r"(b[nt][1]));
                }
            }
        }
        __syncthreads();
    }
#pragma unroll
    for (int mt = 0; mt < 4; mt++) {
#pragma unroll
        for (int nt = 0; nt < 4; nt++) {
            int m = m0 + wm + mt * 16 + g;
            int n = n0 + wn + nt * 8 + tq * 2;
            if (m < TOPN) {
                float2 v = make_float2(c[mt][nt][0], c[mt][nt][1]);
                *reinterpret_cast<float2*>(&g_fcp[((size_t)blockIdx.z * 384 + m) * FCD + n]) = v;
            }
            if (m + 8 < TOPN) {
                float2 v = make_float2(c[mt][nt][2], c[mt][nt][3]);
                *reinterpret_cast<float2*>(&g_fcp[((size_t)blockIdx.z * 384 + m + 8) * FCD + n]) = v;
            }
        }
    }
}

__global__ void k_fcreduce(const float* __restrict__ fb) {
    int i = blockIdx.x * blockDim.x + threadIdx.x;
    if (i >= TOPN * FCD) return;
    int m = i / FCD, n = i - m * FCD;
    float s = fb[n];
#pragma unroll
    for (int z = 0; z < ZSPLIT; z++) s += g_fcp[((size_t)z * 384 + m) * FCD + n];
    g_fc7[i] = s > 0.f ? s : 0.f;
}

__global__ void __launch_bounds__(128) k_heads(const float* __restrict__ cw, const float* __restrict__ cb,
                                               const float* __restrict__ bw, const float* __restrict__ bb,
                                               const float* __restrict__ tgt, const float* __restrict__ biw,
                                               const float* __restrict__ bow, const int* __restrict__ lab) {
    __shared__ float sf[FCD];
    __shared__ float so[105];
    int r = blockIdx.x, t = threadIdx.x;
    for (int k = t; k < FCD; k += 128) sf[k] = g_fc7[(size_t)r * FCD + k];
    __syncthreads();
    if (t < 105) {
        float acc = (t < 21) ? cb[t] : bb[t - 21];
        if (t < 21) {
            for (int k = 0; k < FCD; k++) acc = fmaf(sf[k], cw[k * 21 + t], acc);
        } else {
            int o = t - 21;
            for (int k = 0; k < FCD; k++) acc = fmaf(sf[k], bw[k * 84 + o], acc);
        }
        so[t] = acc;
    }
    __syncthreads();
    if (t == 0) {
        float m = so[0];
        for (int c = 1; c < 21; c++) m = fmaxf(m, so[c]);
        float se = 0.f;
        for (int c = 0; c < 21; c++) se += expf(so[c] - m);
        float lse = m + logf(se);
        g_ce2[r] = lse - so[lab[r]];
        float lb = 0.f;
        for (int o = 0; o < 84; o++) {
            int idx = r * 84 + o;
            float d = biw[idx] * (so[21 + o] - tgt[idx]);
            float ad = fabsf(d);
            float loss = (ad < 1.f) ? d * d * 0.5f : (ad - 0.5f);
            lb += bow[idx] * loss;
        }
        g_lbrow[r] = lb;
    }
}

__global__ void __launch_bounds__(256) k_loss1(const int* __restrict__ lab, const float* __restrict__ tgt,
                                               const float* __restrict__ biw, const float* __restrict__ bow) {
    __shared__ float sce[256], scn[256], slb[256];
    int t = threadIdx.x;
    int gid = blockIdx.x * 256 + t;
    int stride = NB_RED * 256;
    float ce = 0.f, cn = 0.f, lb = 0.f;
    for (int e = gid; e < 36 * HW; e += stride) {
        int p = e / 36, c = e - p * 36;
        float d = biw[e] * (g_bbox[c * HW + p] - tgt[e]);
        float ad = fabsf(d);
        float loss = (ad < (1.f / 9.f)) ? d * d * 4.5f : (ad - 1.f / 18.f);
        lb += bow[e] * loss;
        if (e < NANCH) {
            int L = lab[e];
            if (L != -1) {
                int a = e / HW, pp = e - a * HW;
                float s0 = g_cls[a * HW + pp], s1 = g_cls[(9 + a) * HW + pp];
                float m = fmaxf(s0, s1);
                float lse = m + logf(expf(s0 - m) + expf(s1 - m));
                ce += lse - (L ? s1 : s0);
                cn += 1.f;
            }
        }
    }
    sce[t] = ce; scn[t] = cn; slb[t] = lb;
    __syncthreads();
    for (int o = 128; o > 0; o >>= 1) {
        if (t < o) { sce[t] += sce[t + o]; scn[t] += scn[t + o]; slb[t] += slb[t + o]; }
        __syncthreads();
    }
    if (t == 0) {
        g_red_ce[blockIdx.x] = sce[0];
        g_red_cnt[blockIdx.x] = scn[0];
        g_red_lb[blockIdx.x] = slb[0];
    }
}

__global__ void k_final(float* out) {
    if (threadIdx.x != 0) return;
    float ce = 0.f, cn = 0.f, lb = 0.f;
    for (int i = 0; i < NB_RED; i++) { ce += g_red_ce[i]; cn += g_red_cnt[i]; lb += g_red_lb[i]; }
    float ce2 = 0.f, lb2 = 0.f;
    for (int r = 0; r < TOPN; r++) { ce2 += g_ce2[r]; lb2 += g_lbrow[r]; }
    out[0] = ce / fmaxf(cn, 1.f) + lb + ce2 / TOPN + lb2 / TOPN;
}

extern "C" void kernel_launch(void* const* d_in, const int* in_sizes, int n_in,
                              void* d_out, int out_size) {
    const float* net_conv = (const float*)d_in[0];
    const float* rpn_w = (const float*)d_in[1];
    const float* rpn_b = (const float*)d_in[2];
    const float* rpn_cls_w = (const float*)d_in[3];
    const float* rpn_cls_b = (const float*)d_in[4];
    const float* rpn_bbox_w = (const float*)d_in[5];
    const float* rpn_bbox_b = (const float*)d_in[6];
    const float* fc_w = (const float*)d_in[7];
    const float* fc_b = (const float*)d_in[8];
    const float* cls_w = (const float*)d_in[9];
    const float* cls_b = (const float*)d_in[10];
    const float* bbox_w = (const float*)d_in[11];
    const float* bbox_b = (const float*)d_in[12];
    const float* anchors = (const float*)d_in[13];
    const float* rpn_tgt = (const float*)d_in[14];
    const float* rpn_biw = (const float*)d_in[15];
    const float* rpn_bow = (const float*)d_in[16];
    const float* roi_tgt = (const float*)d_in[17];
    const float* roi_biw = (const float*)d_in[18];
    const float* roi_bow = (const float*)d_in[19];
    const int* rpn_lab = (const int*)d_in[20];
    const int* roi_lab = (const int*)d_in[21];
    float* out = (float*)d_out;

    cudaFuncSetAttribute(k_conv3x3_mma, cudaFuncAttributeMaxDynamicSharedMemorySize, CONV_SMEM);

    k_zero<<<256, 256>>>();
    k_prep_w<<<(512 * KC + 255) / 256, 256>>>(rpn_w);
    k_prep_x<<<dim3(285, 32), dim3(32, 8)>>>(net_conv);
    k_conv3x3_mma<<<dim3(36, 4), 512, CONV_SMEM>>>(rpn_b);
    k_conv1x1<<<dim3(72, 2), 128>>>(rpn_cls_w, rpn_cls_b, rpn_bbox_w, rpn_bbox_b);
    k_fgboxes<<<321, 256>>>(anchors);
    k_scan<<<1, 256>>>();
    k_compact<<<321, 256>>>();
    k_rank<<<321, 256>>>();
    k_roialign<<<dim3(49, TOPN), 256>>>();
    k_fcgemm<<<dim3(16, 3, ZSPLIT), 256>>>(fc_w);
    k_fcreduce<<<(TOPN * FCD + 255) / 256, 256>>>(fc_b);
    k_heads<<<TOPN, 128>>>(cls_w, cls_b, bbox_w, bbox_b, roi_tgt, roi_biw, roi_bow, roi_lab);
    k_loss1<<<NB_RED, 256>>>(rpn_lab, rpn_tgt, rpn_biw, rpn_bow);
    k_final<<<1, 32>>>(out);
}

// round 12
// speedup vs baseline: 2.5279x; 1.0221x over previous
#include <cuda_runtime.h>
#include <cuda_bf16.h>
#include <math.h>

#define HH 76
#define WW 120
#define HW 9120
#define AA 9
#define NANCH 82080
#define CIN 1024
#define KC 9216
#define KW 18432
#define TOPN 300
#define FCD 2048
#define KFC 50176
#define ZSPLIT 4
#define KPZ (KFC / ZSPLIT)
#define NB_RED 256
#define CSTR 72
#define ASZE 9216
#define STGE 36864
#define STGB (STGE * 2)
#define CONV_SMEM (2 * STGB)

__device__ float g_rpn[512 * HW];
__device__ float g_cls[18 * HW];
__device__ float g_bbox[36 * HW];
__device__ unsigned int g_key[NANCH];
__device__ float g_boxes[NANCH * 4];
__device__ int g_hist[65536];
__device__ int g_thr_bin;
__device__ int g_cand_cnt;
__device__ unsigned int g_ckey[NANCH];
__device__ int g_cidx[NANCH];
__device__ float g_rois[TOPN * 4];
__device__ float g_feat_t[HW * CIN];
__device__ __nv_bfloat16 g_pooledh[TOPN * KFC];
__device__ float g_fcp[ZSPLIT * 384 * FCD];
__device__ float g_fc7[TOPN * FCD];
__device__ float g_ce2[TOPN];
__device__ float g_lbrow[TOPN];
__device__ float g_red_ce[NB_RED];
__device__ float g_red_cnt[NB_RED];
__device__ float g_red_lb[NB_RED];
__device__ __nv_bfloat16 g_wsplit[512 * KW];
__device__ __nv_bfloat16 g_xhi_t[HW * CIN];
__device__ __nv_bfloat16 g_xlo_t[HW * CIN];
__device__ float g_hwT[105 * FCD];

__device__ __forceinline__ void cp16(unsigned dst, const void* src, int srcsize) {
    asm volatile("cp.async.cg.shared.global [%0], [%1], 16, %2;" :: "r"(dst), "l"(src), "r"(srcsize));
}

__global__ void k_zero() {
    int i = blockIdx.x * blockDim.x + threadIdx.x;
    if (i < 65536) g_hist[i] = 0;
    if (i == 0) g_cand_cnt = 0;
}

__global__ void k_prep_w(const float* __restrict__ Wt) {
    int i = blockIdx.x * blockDim.x + threadIdx.x;
    if (i >= 512 * KC) return;
    int m = i / KC, r = i - m * KC;
    int t9 = r >> 10, ci = r & 1023;
    float w = Wt[(size_t)m * KC + ci * 9 + t9];
    __nv_bfloat16 hi = __float2bfloat16_rn(w);
    __nv_bfloat16 lo = __float2bfloat16_rn(w - __bfloat162float(hi));
    size_t base = (size_t)m * KW;
    g_wsplit[base + r] = hi;
    g_wsplit[base + KC + r] = lo;
}

__global__ void k_prep_x(const float* __restrict__ X) {
    __shared__ float tile[32][33];
    int tx = threadIdx.x, ty = threadIdx.y;
    int p0 = blockIdx.x * 32, c0 = blockIdx.y * 32;
#pragma unroll
    for (int j = 0; j < 32; j += 8) tile[ty + j][tx] = X[(size_t)(c0 + ty + j) * HW + p0 + tx];
    __syncthreads();
#pragma unroll
    for (int j = 0; j < 32; j += 8) {
        float v = tile[tx][ty + j];
        size_t o = (size_t)(p0 + ty + j) * CIN + c0 + tx;
        g_feat_t[o] = v;
        __nv_bfloat16 hi = __float2bfloat16_rn(v);
        g_xhi_t[o] = hi;
        g_xlo_t[o] = __float2bfloat16_rn(v - __bfloat162float(hi));
    }
}

// transpose head weights: g_hwT[o][k], o<21 -> cls_w, else bbox_w
__global__ void k_prep_hw(const float* __restrict__ cw, const float* __restrict__ bw) {
    int i = blockIdx.x * blockDim.x + threadIdx.x;
    if (i >= 105 * FCD) return;
    int o = i / FCD, k = i - o * FCD;
    g_hwT[i] = (o < 21) ? cw[k * 21 + o] : bw[k * 84 + (o - 21)];
}

__global__ void __launch_bounds__(512, 1) k_conv3x3_mma(const float* __restrict__ bias) {
    extern __shared__ __nv_bfloat16 sm[];
    unsigned smb = (unsigned)__cvta_generic_to_shared(sm);
    int tid = threadIdx.x;
    int lane = tid & 31, warp = tid >> 5;
    int n0 = blockIdx.x * 256, m0 = blockIdx.y * 128;
    int wm = (warp & 1) * 64, wn = (warp >> 1) * 32;
    int g = lane >> 2, tq = lane & 3;
    int pix = tid >> 1, half = tid & 1;
    int p = n0 + pix;
    bool pv = p < HW;
    int py = p / WW, px = p - py * WW;
    float c[4][4][4];
#pragma unroll
    for (int mt = 0; mt < 4; mt++)
#pragma unroll
        for (int nt = 0; nt < 4; nt++)
#pragma unroll
            for (int u = 0; u < 4; u++) c[mt][nt][u] = 0.f;

    const int NCH = 288;

    auto fill = [&](int ch, int st) {
        bool hi = ch < 144;
        int rem = hi ? ch : ch - 144;
        int tap = rem >> 4;
        int ci0 = (rem & 15) << 6;
        int k = tap * 1024 + ci0;
        unsigned ab = smb + (unsigned)(st * STGB);
        unsigned a1b = ab + ASZE * 2;
        unsigned bb = ab + 2 * ASZE * 2;
#pragma unroll
        for (int u = 0; u < 2; u++) {
            int idx = u * 512 + tid;
            int m = idx >> 3, oct = idx & 7;
            cp16(ab + (unsigned)(m * CSTR + oct * 8) * 2,
                 &g_wsplit[(size_t)(m0 + m) * KW + k + oct * 8], 16);
        }
        if (hi) {
#pragma unroll
            for (int u = 0; u < 2; u++) {
                int idx = u * 512 + tid;
                int m = idx >> 3, oct = idx & 7;
                cp16(a1b + (unsigned)(m * CSTR + oct * 8) * 2,
                     &g_wsplit[(size_t)(m0 + m) * KW + KC + k + oct * 8], 16);
            }
        }
        const __nv_bfloat16* Xp = hi ? g_xhi_t : g_xlo_t;
        int t3 = tap / 3;
        int yy = py + t3 - 1, xx = px + (tap - t3 * 3 - 1);
        bool v = pv && (unsigned)yy < HH && (unsigned)xx < WW;
        const __nv_bfloat16* src = v ? &Xp[(size_t)(yy * WW + xx) * CIN + ci0 + half * 32] : Xp;
        int sz = v ? 16 : 0;
        unsigned brow = bb + (unsigned)(pix * CSTR + half * 32) * 2;
#pragma unroll
        for (int u = 0; u < 4; u++) cp16(brow + u * 16, src + u * 8, sz);
    };

    fill(0, 0);
    asm volatile("cp.async.commit_group;");

    for (int ch = 0; ch < NCH; ch++) {
        int st = ch & 1;
        if (ch + 1 < NCH) {
            fill(ch + 1, st ^ 1);
            asm volatile("cp.async.commit_group;");
            asm volatile("cp.async.wait_group 1;");
        } else {
            asm volatile("cp.async.wait_group 0;");
        }
        __syncthreads();
        const __nv_bfloat16* As0 = sm + st * STGE;
        const __nv_bfloat16* As1 = As0 + ASZE;
        const __nv_bfloat16* Bs = As0 + 2 * ASZE;
        bool hi = ch < 144;
#pragma unroll
        for (int ko = 0; ko < 64; ko += 16) {
            unsigned b[4][2];
#pragma unroll
            for (int nt = 0; nt < 4; nt++) {
                const __nv_bfloat16* bp = &Bs[(wn + nt * 8 + g) * CSTR + ko + tq * 2];
                b[nt][0] = *reinterpret_cast<const unsigned*>(bp);
                b[nt][1] = *reinterpret_cast<const unsigned*>(bp + 8);
            }
            unsigned a[4][4];
#pragma unroll
            for (int mt = 0; mt < 4; mt++) {
                const __nv_bfloat16* ap = &As0[(wm + mt * 16 + g) * CSTR + ko + tq * 2];
                a[mt][0] = *reinterpret_cast<const unsigned*>(ap);
                a[mt][1] = *reinterpret_cast<const unsigned*>(ap + 8 * CSTR);
                a[mt][2] = *reinterpret_cast<const unsigned*>(ap + 8);
                a[mt][3] = *reinterpret_cast<const unsigned*>(ap + 8 * CSTR + 8);
            }
#pragma unroll
            for (int mt = 0; mt < 4; mt++)
#pragma unroll
                for (int nt = 0; nt < 4; nt++) {
                    asm volatile(
                        "mma.sync.aligned.m16n8k16.row.col.f32.bf16.bf16.f32 "
                        "{%0,%1,%2,%3}, {%4,%5,%6,%7}, {%8,%9}, {%0,%1,%2,%3};"
                        : "+f"(c[mt][nt][0]), "+f"(c[mt][nt][1]),
                          "+f"(c[mt][nt][2]), "+f"(c[mt][nt][3])
                        : "r"(a[mt][0]), "r"(a[mt][1]), "r"(a[mt][2]), "r"(a[mt][3]),
                          "r"(b[nt][0]), "r"(b[nt][1]));
                }
            if (hi) {
#pragma unroll
                for (int mt = 0; mt < 4; mt++) {
                    const __nv_bfloat16* ap = &As1[(wm + mt * 16 + g) * CSTR + ko + tq * 2];
                    a[mt][0] = *reinterpret_cast<const unsigned*>(ap);
                    a[mt][1] = *reinterpret_cast<const unsigned*>(ap + 8 * CSTR);
                    a[mt][2] = *reinterpret_cast<const unsigned*>(ap + 8);
                    a[mt][3] = *reinterpret_cast<const unsigned*>(ap + 8 * CSTR + 8);
                }
#pragma unroll
                for (int mt = 0; mt < 4; mt++)
#pragma unroll
                    for (int nt = 0; nt < 4; nt++) {
                        asm volatile(
                            "mma.sync.aligned.m16n8k16.row.col.f32.bf16.bf16.f32 "
                            "{%0,%1,%2,%3}, {%4,%5,%6,%7}, {%8,%9}, {%0,%1,%2,%3};"
                            : "+f"(c[mt][nt][0]), "+f"(c[mt][nt][1]),
                              "+f"(c[mt][nt][2]), "+f"(c[mt][nt][3])
                            : "r"(a[mt][0]), "r"(a[mt][1]), "r"(a[mt][2]), "r"(a[mt][3]),
                              "r"(b[nt][0]), "r"(b[nt][1]));
                    }
            }
        }
        __syncthreads();
    }
#pragma unroll
    for (int mt = 0; mt < 4; mt++) {
#pragma unroll
        for (int nt = 0; nt < 4; nt++) {
            int m = m0 + wm + mt * 16 + g;
            int pp = n0 + wn + nt * 8 + tq * 2;
            float bv0 = bias[m], bv1 = bias[m + 8];
            float v0 = fmaxf(c[mt][nt][0] + bv0, 0.f);
            float v1 = fmaxf(c[mt][nt][1] + bv0, 0.f);
            float v2 = fmaxf(c[mt][nt][2] + bv1, 0.f);
            float v3 = fmaxf(c[mt][nt][3] + bv1, 0.f);
            if (pp + 1 < HW) {
                *reinterpret_cast<float2*>(&g_rpn[(size_t)m * HW + pp]) = make_float2(v0, v1);
                *reinterpret_cast<float2*>(&g_rpn[(size_t)(m + 8) * HW + pp]) = make_float2(v2, v3);
            } else if (pp < HW) {
                g_rpn[(size_t)m * HW + pp] = v0;
                g_rpn[(size_t)(m + 8) * HW + pp] = v2;
            }
        }
    }
}

__global__ void __launch_bounds__(128) k_conv1x1(const float* __restrict__ cw,
                                                 const float* __restrict__ cb,
                                                 const float* __restrict__ bw,
                                                 const float* __restrict__ bb) {
    __shared__ float ws[27 * 128];
    int tid = threadIdx.x;
    int p = blockIdx.x * 128 + tid;
    bool pv = p < HW;
    int half = blockIdx.y;
    float acc[27];
#pragma unroll
    for (int c = 0; c < 27; c++) {
        int oc = half * 27 + c;
        acc[c] = (oc < 18) ? cb[oc] : bb[oc - 18];
    }
    for (int kc = 0; kc < 512; kc += 128) {
        __syncthreads();
#pragma unroll
        for (int c = 0; c < 27; c++) {
            int oc = half * 27 + c;
            ws[c * 128 + tid] = (oc < 18) ? cw[oc * 512 + kc + tid] : bw[(oc - 18) * 512 + kc + tid];
        }
        __syncthreads();
        for (int k = 0; k < 128; k++) {
            float rv = pv ? g_rpn[(size_t)(kc + k) * HW + p] : 0.f;
#pragma unroll
            for (int c = 0; c < 27; c++) acc[c] = fmaf(rv, ws[c * 128 + k], acc[c]);
        }
    }
    if (pv) {
#pragma unroll
        for (int c = 0; c < 27; c++) {
            int oc = half * 27 + c;
            if (oc < 18) g_cls[oc * HW + p] = acc[c];
            else g_bbox[(oc - 18) * HW + p] = acc[c];
        }
    }
}

__global__ void k_fgboxes(const float* __restrict__ anchors) {
    int i = blockIdx.x * blockDim.x + threadIdx.x;
    if (i >= NANCH) return;
    int p = i / AA, a = i - p * AA;
    float s0 = g_cls[a * HW + p], s1 = g_cls[(9 + a) * HW + p];
    float m = fmaxf(s0, s1);
    float e0 = expf(s0 - m), e1 = expf(s1 - m);
    float fg = e1 / (e0 + e1);
    unsigned int u = __float_as_uint(fg);
    u = (u & 0x80000000u) ? ~u : (u | 0x80000000u);
    g_key[i] = u;
    atomicAdd(&g_hist[u >> 16], 1);
    float ax1 = anchors[i * 4], ay1 = anchors[i * 4 + 1];
    float ax2 = anchors[i * 4 + 2], ay2 = anchors[i * 4 + 3];
    float aw = ax2 - ax1 + 1.f, ah = ay2 - ay1 + 1.f;
    float acx = ax1 + 0.5f * aw, acy = ay1 + 0.5f * ah;
    float dx = g_bbox[(4 * a) * HW + p], dy = g_bbox[(4 * a + 1) * HW + p];
    float dw = g_bbox[(4 * a + 2) * HW + p], dh = g_bbox[(4 * a + 3) * HW + p];
    float pcx = dx * aw + acx, pcy = dy * ah + acy;
    float pw = expf(dw) * aw, ph = expf(dh) * ah;
    g_boxes[i * 4 + 0] = fminf(fmaxf(pcx - 0.5f * pw, 0.f), 1919.f);
    g_boxes[i * 4 + 1] = fminf(fmaxf(pcy - 0.5f * ph, 0.f), 1215.f);
    g_boxes[i * 4 + 2] = fminf(fmaxf(pcx + 0.5f * pw, 0.f), 1919.f);
    g_boxes[i * 4 + 3] = fminf(fmaxf(pcy + 0.5f * ph, 0.f), 1215.f);
}

__global__ void k_scan() {
    __shared__ int cs[256];
    int t = threadIdx.x;
    int s = 0;
    for (int j = 0; j < 256; j++) s += g_hist[t * 256 + j];
    cs[t] = s;
    __syncthreads();
    if (t == 0) {
        int acc = 0, chunk = 0;
        for (int i = 255; i >= 0; i--) {
            if (acc + cs[i] >= TOPN) { chunk = i; break; }
            acc += cs[i];
        }
        int T = chunk * 256;
        for (int b = chunk * 256 + 255; b >= chunk * 256; b--) {
            if (acc + g_hist[b] >= TOPN) { T = b; break; }
            acc += g_hist[b];
        }
        g_thr_bin = T;
    }
}

__global__ void k_compact() {
    int i = blockIdx.x * blockDim.x + threadIdx.x;
    if (i >= NANCH) return;
    unsigned int u = g_key[i];
    if ((int)(u >> 16) >= g_thr_bin) {
        int pos = atomicAdd(&g_cand_cnt, 1);
        g_ckey[pos] = u;
        g_cidx[pos] = i;
    }
}

__global__ void k_rank() {
    int c = g_cand_cnt;
    int i = blockIdx.x * blockDim.x + threadIdx.x;
    if (i >= c) return;
    unsigned int ki = g_ckey[i];
    int di = g_cidx[i];
    int rank = 0;
    for (int j = 0; j < c; j++) {
        unsigned int kj = g_ckey[j];
        if (kj > ki || (kj == ki && g_cidx[j] < di)) rank++;
    }
    if (rank < TOPN) {
        g_rois[rank * 4 + 0] = g_boxes[di * 4 + 0];
        g_rois[rank * 4 + 1] = g_boxes[di * 4 + 1];
        g_rois[rank * 4 + 2] = g_boxes[di * 4 + 2];
        g_rois[rank * 4 + 3] = g_boxes[di * 4 + 3];
    }
}

// q-major pooled layout: k' = q*1024 + c -> fully coalesced writes
__global__ void __launch_bounds__(256) k_roialign() {
    int r = blockIdx.y, q = blockIdx.x;
    int pyy = q / 7, pxx = q - pyy * 7;
    float x1 = g_rois[r * 4 + 0] * 0.0625f, y1 = g_rois[r * 4 + 1] * 0.0625f;
    float x2 = g_rois[r * 4 + 2] * 0.0625f, y2 = g_rois[r * 4 + 3] * 0.0625f;
    float xs = fminf(fmaxf(x1 + (x2 - x1) * ((pxx + 0.5f) / 7.f), 0.f), 119.f);
    float ys = fminf(fmaxf(y1 + (y2 - y1) * ((pyy + 0.5f) / 7.f), 0.f), 75.f);
    float x0f = floorf(xs), y0f = floorf(ys);
    int x0i = (int)x0f, y0i = (int)y0f;
    int x1i = min(x0i + 1, 119), y1i = min(y0i + 1, 75);
    float wx = xs - x0f, wy = ys - y0f;
    float w00 = (1.f - wy) * (1.f - wx), w01 = (1.f - wy) * wx;
    float w10 = wy * (1.f - wx), w11 = wy * wx;
    const float* f00 = &g_feat_t[(size_t)(y0i * WW + x0i) * CIN];
    const float* f01 = &g_feat_t[(size_t)(y0i * WW + x1i) * CIN];
    const float* f10 = &g_feat_t[(size_t)(y1i * WW + x0i) * CIN];
    const float* f11 = &g_feat_t[(size_t)(y1i * WW + x1i) * CIN];
    __nv_bfloat16* outp = &g_pooledh[(size_t)r * KFC + q * 1024];
    for (int c = threadIdx.x; c < CIN; c += 256) {
        float v = f00[c] * w00 + f01[c] * w01 + f10[c] * w10 + f11[c] * w11;
        outp[c] = __float2bfloat16_rn(v);
    }
}

__global__ void __launch_bounds__(256) k_fcgemm(const float* __restrict__ Bw) {
    __shared__ __nv_bfloat16 Asm[128 * 40];
    __shared__ __nv_bfloat16 Bks[32 * 132];
    int tid = threadIdx.x;
    int lane = tid & 31, warp = tid >> 5;
    int n0 = blockIdx.x * 128, m0 = blockIdx.y * 128;
    int kz = blockIdx.z * KPZ;
    int wm = (warp >> 2) * 64;
    int wn = (warp & 3) * 32;
    int g = lane >> 2, tq = lane & 3;
    int mlim = TOPN - m0 - wm;
    float c[4][4][4];
#pragma unroll
    for (int mt = 0; mt < 4; mt++)
#pragma unroll
        for (int nt = 0; nt < 4; nt++)
#pragma unroll
            for (int u = 0; u < 4; u++) c[mt][nt][u] = 0.f;

    for (int ks = 0; ks < KPZ; ks += 32) {
#pragma unroll
        for (int u = 0; u < 2; u++) {
            int idx = tid * 2 + u;
            int r = idx >> 2, c8 = idx & 3;
            uint4 v = make_uint4(0, 0, 0, 0);
            int m = m0 + r;
            if (m < TOPN)
                v = *reinterpret_cast<const uint4*>(&g_pooledh[(size_t)m * KFC + kz + ks + c8 * 8]);
            *reinterpret_cast<uint4*>(&Asm[r * 40 + c8 * 8]) = v;
        }
#pragma unroll
        for (int i = 0; i < 4; i++) {
            int idx = i * 256 + tid;
            int k = idx >> 5, cc = idx & 31;
            int kp = kz + ks + k;
            int ok = (kp & 1023) * 49 + (kp >> 10);
            float4 v = *reinterpret_cast<const float4*>(&Bw[(size_t)ok * FCD + n0 + cc * 4]);
            __nv_bfloat162 p0 = __floats2bfloat162_rn(v.x, v.y);
            __nv_bfloat162 p1 = __floats2bfloat162_rn(v.z, v.w);
            uint2 st;
            st.x = *reinterpret_cast<unsigned*>(&p0);
            st.y = *reinterpret_cast<unsigned*>(&p1);
            *reinterpret_cast<uint2*>(&Bks[k * 132 + cc * 4]) = st;
        }
        __syncthreads();
#pragma unroll
        for (int ko = 0; ko < 32; ko += 16) {
            unsigned a[4][4];
#pragma unroll
            for (int mt = 0; mt < 4; mt++) {
                if (mt * 16 >= mlim) continue;
                const __nv_bfloat16* ap = &Asm[(wm + mt * 16 + g) * 40 + ko + tq * 2];
                a[mt][0] = *reinterpret_cast<const unsigned*>(ap);
                a[mt][1] = *reinterpret_cast<const unsigned*>(ap + 8 * 40);
                a[mt][2] = *reinterpret_cast<const unsigned*>(ap + 8);
                a[mt][3] = *reinterpret_cast<const unsigned*>(ap + 8 * 40 + 8);
            }
            unsigned b[4][2];
#pragma unroll
            for (int nt = 0; nt < 4; nt++) {
                int n = wn + nt * 8 + g;
                unsigned lo0 = *reinterpret_cast<const unsigned short*>(&Bks[(ko + tq * 2) * 132 + n]);
                unsigned hi0 = *reinterpret_cast<const unsigned short*>(&Bks[(ko + tq * 2 + 1) * 132 + n]);
                b[nt][0] = lo0 | (hi0 << 16);
                unsigned lo1 = *reinterpret_cast<const unsigned short*>(&Bks[(ko + tq * 2 + 8) * 132 + n]);
                unsigned hi1 = *reinterpret_cast<const unsigned short*>(&Bks[(ko + tq * 2 + 9) * 132 + n]);
                b[nt][1] = lo1 | (hi1 << 16);
            }
#pragma unroll
            for (int mt = 0; mt < 4; mt++) {
                if (mt * 16 >= mlim) continue;
#pragma unroll
                for (int nt = 0; nt < 4; nt++) {
                    asm volatile(
                        "mma.sync.aligned.m16n8k16.row.col.f32.bf16.bf16.f32 "
                        "{%0,%1,%2,%3}, {%4,%5,%6,%7}, {%8,%9}, {%0,%1,%2,%3};"
                        : "+f"(c[mt][nt][0]), "+f"(c[mt][nt][1]),
                          "+f"(c[mt][nt][2]), "+f"(c[mt][nt][3])
                        : "r"(a[mt][0]), "r"(a[mt][1]), "r"(a[mt][2]), "r"(a[mt][3]),
                          "r"(b[nt][0]), "r"(b[nt][1]));
                }
            }
        }
        __syncthreads();
    }
#pragma unroll
    for (int mt = 0; mt < 4; mt++) {
#pragma unroll
        for (int nt = 0; nt < 4; nt++) {
            int m = m0 + wm + mt * 16 + g;
            int n = n0 + wn + nt * 8 + tq * 2;
            if (m < TOPN) {
                float2 v = make_float2(c[mt][nt][0], c[mt][nt][1]);
                *reinterpret_cast<float2*>(&g_fcp[((size_t)blockIdx.z * 384 + m) * FCD + n]) = v;
            }
            if (m + 8 < TOPN) {
                float2 v = make_float2(c[mt][nt][2], c[mt][nt][3]);
                *reinterpret_cast<float2*>(&g_fcp[((size_t)blockIdx.z * 384 + m + 8) * FCD + n]) = v;
            }
        }
    }
}

__global__ void k_fcreduce(const float* __restrict__ fb) {
    int i = blockIdx.x * blockDim.x + threadIdx.x;
    if (i >= TOPN * FCD) return;
    int m = i / FCD, n = i - m * FCD;
    float s = fb[n];
#pragma unroll
    for (int z = 0; z < ZSPLIT; z++) s += g_fcp[((size_t)z * 384 + m) * FCD + n];
    g_fc7[i] = s > 0.f ? s : 0.f;
}

// heads: warp-per-output with transposed weights (coalesced), shuffle reduce
__global__ void __launch_bounds__(128) k_heads(const float* __restrict__ cb, const float* __restrict__ bb,
                                               const float* __restrict__ tgt, const float* __restrict__ biw,
                                               const float* __restrict__ bow, const int* __restrict__ lab) {
    __shared__ float sf[FCD];
    __shared__ float so[112];
    int r = blockIdx.x, t = threadIdx.x;
    int warp = t >> 5, lane = t & 31;
    for (int k = t; k < FCD; k += 128) sf[k] = g_fc7[(size_t)r * FCD + k];
    __syncthreads();
    for (int o = warp; o < 105; o += 4) {
        const float* wp = &g_hwT[(size_t)o * FCD];
        float acc = 0.f;
        for (int k = lane; k < FCD; k += 32) acc = fmaf(sf[k], wp[k], acc);
#pragma unroll
        for (int off = 16; off > 0; off >>= 1)
            acc += __shfl_xor_sync(0xffffffffu, acc, off);
        if (lane == 0) so[o] = acc + ((o < 21) ? cb[o] : bb[o - 21]);
    }
    __syncthreads();
    if (t == 0) {
        float m = so[0];
        for (int c = 1; c < 21; c++) m = fmaxf(m, so[c]);
        float se = 0.f;
        for (int c = 0; c < 21; c++) se += expf(so[c] - m);
        float lse = m + logf(se);
        g_ce2[r] = lse - so[lab[r]];
        float lb = 0.f;
        for (int o = 0; o < 84; o++) {
            int idx = r * 84 + o;
            float d = biw[idx] * (so[21 + o] - tgt[idx]);
            float ad = fabsf(d);
            float loss = (ad < 1.f) ? d * d * 0.5f : (ad - 0.5f);
            lb += bow[idx] * loss;
        }
        g_lbrow[r] = lb;
    }
}

__global__ void __launch_bounds__(256) k_loss1(const int* __restrict__ lab, const float* __restrict__ tgt,
                                               const float* __restrict__ biw, const float* __restrict__ bow) {
    __shared__ float sce[256], scn[256], slb[256];
    int t = threadIdx.x;
    int gid = blockIdx.x * 256 + t;
    int stride = NB_RED * 256;
    float ce = 0.f, cn = 0.f, lb = 0.f;
    for (int e = gid; e < 36 * HW; e += stride) {
        int p = e / 36, c = e - p * 36;
        float d = biw[e] * (g_bbox[c * HW + p] - tgt[e]);
        float ad = fabsf(d);
        float loss = (ad < (1.f / 9.f)) ? d * d * 4.5f : (ad - 1.f / 18.f);
        lb += bow[e] * loss;
        if (e < NANCH) {
            int L = lab[e];
            if (L != -1) {
                int a = e / HW, pp = e - a * HW;
                float s0 = g_cls[a * HW + pp], s1 = g_cls[(9 + a) * HW + pp];
                float m = fmaxf(s0, s1);
                float lse = m + logf(expf(s0 - m) + expf(s1 - m));
                ce += lse - (L ? s1 : s0);
                cn += 1.f;
            }
        }
    }
    sce[t] = ce; scn[t] = cn; slb[t] = lb;
    __syncthreads();
    for (int o = 128; o > 0; o >>= 1) {
        if (t < o) { sce[t] += sce[t + o]; scn[t] += scn[t + o]; slb[t] += slb[t + o]; }
        __syncthreads();
    }
    if (t == 0) {
        g_red_ce[blockIdx.x] = sce[0];
        g_red_cnt[blockIdx.x] = scn[0];
        g_red_lb[blockIdx.x] = slb[0];
    }
}

__global__ void k_final(float* out) {
    if (threadIdx.x != 0) return;
    float ce = 0.f, cn = 0.f, lb = 0.f;
    for (int i = 0; i < NB_RED; i++) { ce += g_red_ce[i]; cn += g_red_cnt[i]; lb += g_red_lb[i]; }
    float ce2 = 0.f, lb2 = 0.f;
    for (int r = 0; r < TOPN; r++) { ce2 += g_ce2[r]; lb2 += g_lbrow[r]; }
    out[0] = ce / fmaxf(cn, 1.f) + lb + ce2 / TOPN + lb2 / TOPN;
}

extern "C" void kernel_launch(void* const* d_in, const int* in_sizes, int n_in,
                              void* d_out, int out_size) {
    const float* net_conv = (const float*)d_in[0];
    const float* rpn_w = (const float*)d_in[1];
    const float* rpn_b = (const float*)d_in[2];
    const float* rpn_cls_w = (const float*)d_in[3];
    const float* rpn_cls_b = (const float*)d_in[4];
    const float* rpn_bbox_w = (const float*)d_in[5];
    const float* rpn_bbox_b = (const float*)d_in[6];
    const float* fc_w = (const float*)d_in[7];
    const float* fc_b = (const float*)d_in[8];
    const float* cls_w = (const float*)d_in[9];
    const float* cls_b = (const float*)d_in[10];
    const float* bbox_w = (const float*)d_in[11];
    const float* bbox_b = (const float*)d_in[12];
    const float* anchors = (const float*)d_in[13];
    const float* rpn_tgt = (const float*)d_in[14];
    const float* rpn_biw = (const float*)d_in[15];
    const float* rpn_bow = (const float*)d_in[16];
    const float* roi_tgt = (const float*)d_in[17];
    const float* roi_biw = (const float*)d_in[18];
    const float* roi_bow = (const float*)d_in[19];
    const int* rpn_lab = (const int*)d_in[20];
    const int* roi_lab = (const int*)d_in[21];
    float* out = (float*)d_out;

    cudaFuncSetAttribute(k_conv3x3_mma, cudaFuncAttributeMaxDynamicSharedMemorySize, CONV_SMEM);

    k_zero<<<256, 256>>>();
    k_prep_w<<<(512 * KC + 255) / 256, 256>>>(rpn_w);
    k_prep_x<<<dim3(285, 32), dim3(32, 8)>>>(net_conv);
    k_conv3x3_mma<<<dim3(36, 4), 512, CONV_SMEM>>>(rpn_b);
    k_prep_hw<<<(105 * FCD + 255) / 256, 256>>>(cls_w, bbox_w);
    k_conv1x1<<<dim3(72, 2), 128>>>(rpn_cls_w, rpn_cls_b, rpn_bbox_w, rpn_bbox_b);
    k_fgboxes<<<321, 256>>>(anchors);
    k_scan<<<1, 256>>>();
    k_compact<<<321, 256>>>();
    k_rank<<<321, 256>>>();
    k_roialign<<<dim3(49, TOPN), 256>>>();
    k_fcgemm<<<dim3(16, 3, ZSPLIT), 256>>>(fc_w);
    k_fcreduce<<<(TOPN * FCD + 255) / 256, 256>>>(fc_b);
    k_heads<<<TOPN, 128>>>(cls_b, bbox_b, roi_tgt, roi_biw, roi_bow, roi_lab);
    k_loss1<<<NB_RED, 256>>>(rpn_lab, rpn_tgt, rpn_biw, rpn_bow);
    k_final<<<1, 32>>>(out);
}

// round 13
// speedup vs baseline: 2.6217x; 1.0371x over previous
#include <cuda_runtime.h>
#include <cuda_bf16.h>
#include <math.h>

#define HH 76
#define WW 120
#define HW 9120
#define AA 9
#define NANCH 82080
#define CIN 1024
#define KC 9216
#define KW 18432
#define TOPN 300
#define FCD 2048
#define KFC 50176
#define ZSPLIT 4
#define KPZ (KFC / ZSPLIT)
#define NB_RED 256
#define CSTR 72
#define ASZE 9216
#define STGE 36864
#define STGB (STGE * 2)
#define CONV_SMEM (2 * STGB)

__device__ float g_rpn[512 * HW];
__device__ float g_cls[18 * HW];
__device__ float g_bbox[36 * HW];
__device__ unsigned int g_key[NANCH];
__device__ float g_boxes[NANCH * 4];
__device__ int g_hist[65536];
__device__ int g_thr_bin;
__device__ int g_cand_cnt;
__device__ unsigned int g_ckey[NANCH];
__device__ int g_cidx[NANCH];
__device__ float g_rois[TOPN * 4];
__device__ float g_feat_t[HW * CIN];
__device__ __nv_bfloat16 g_pooledh[TOPN * KFC];
__device__ float g_fcp[ZSPLIT * 384 * FCD];
__device__ float g_fc7[TOPN * FCD];
__device__ float g_ce2[TOPN];
__device__ float g_lbrow[TOPN];
__device__ float g_red_ce[NB_RED];
__device__ float g_red_cnt[NB_RED];
__device__ float g_red_lb[NB_RED];
__device__ __nv_bfloat16 g_wsplit[512 * KW];
__device__ __nv_bfloat16 g_xhi_t[HW * CIN];
__device__ __nv_bfloat16 g_xlo_t[HW * CIN];
__device__ float g_hwT[105 * FCD];

__device__ __forceinline__ void cp16(unsigned dst, const void* src, int srcsize) {
    asm volatile("cp.async.cg.shared.global [%0], [%1], 16, %2;" :: "r"(dst), "l"(src), "r"(srcsize));
}

__device__ __forceinline__ void ldsm4(unsigned& r0, unsigned& r1, unsigned& r2, unsigned& r3,
                                      unsigned addr) {
    asm volatile("ldmatrix.sync.aligned.m8n8.x4.shared.b16 {%0,%1,%2,%3}, [%4];"
                 : "=r"(r0), "=r"(r1), "=r"(r2), "=r"(r3) : "r"(addr));
}

__global__ void k_zero() {
    int i = blockIdx.x * blockDim.x + threadIdx.x;
    if (i < 65536) g_hist[i] = 0;
    if (i == 0) g_cand_cnt = 0;
}

__global__ void k_prep_w(const float* __restrict__ Wt) {
    int i = blockIdx.x * blockDim.x + threadIdx.x;
    if (i >= 512 * KC) return;
    int m = i / KC, r = i - m * KC;
    int t9 = r >> 10, ci = r & 1023;
    float w = Wt[(size_t)m * KC + ci * 9 + t9];
    __nv_bfloat16 hi = __float2bfloat16_rn(w);
    __nv_bfloat16 lo = __float2bfloat16_rn(w - __bfloat162float(hi));
    size_t base = (size_t)m * KW;
    g_wsplit[base + r] = hi;
    g_wsplit[base + KC + r] = lo;
}

__global__ void k_prep_x(const float* __restrict__ X) {
    __shared__ float tile[32][33];
    int tx = threadIdx.x, ty = threadIdx.y;
    int p0 = blockIdx.x * 32, c0 = blockIdx.y * 32;
#pragma unroll
    for (int j = 0; j < 32; j += 8) tile[ty + j][tx] = X[(size_t)(c0 + ty + j) * HW + p0 + tx];
    __syncthreads();
#pragma unroll
    for (int j = 0; j < 32; j += 8) {
        float v = tile[tx][ty + j];
        size_t o = (size_t)(p0 + ty + j) * CIN + c0 + tx;
        g_feat_t[o] = v;
        __nv_bfloat16 hi = __float2bfloat16_rn(v);
        g_xhi_t[o] = hi;
        g_xlo_t[o] = __float2bfloat16_rn(v - __bfloat162float(hi));
    }
}

__global__ void k_prep_hw(const float* __restrict__ cw, const float* __restrict__ bw) {
    int i = blockIdx.x * blockDim.x + threadIdx.x;
    if (i >= 105 * FCD) return;
    int o = i / FCD, k = i - o * FCD;
    g_hwT[i] = (o < 21) ? cw[k * 21 + o] : bw[k * 84 + (o - 21)];
}

// conv3x3 implicit GEMM: block 128x256, 16 warps (warp tile 64x32), BK=64,
// cp.async 2-stage, ldmatrix fragment loads. 288 chunks (B-shared hi/lo scheme).
__global__ void __launch_bounds__(512, 1) k_conv3x3_mma(const float* __restrict__ bias) {
    extern __shared__ __nv_bfloat16 sm[];
    unsigned smb = (unsigned)__cvta_generic_to_shared(sm);
    int tid = threadIdx.x;
    int lane = tid & 31, warp = tid >> 5;
    int n0 = blockIdx.x * 256, m0 = blockIdx.y * 128;
    int wm = (warp & 1) * 64, wn = (warp >> 1) * 32;
    int g = lane >> 2, tq = lane & 3;
    int pix = tid >> 1, half = tid & 1;
    int p = n0 + pix;
    bool pv = p < HW;
    int py = p / WW, px = p - py * WW;

    // ldmatrix per-lane source rows
    int arow = (lane & 7) + ((lane >> 3) & 1) * 8;
    int ak = (lane >> 4) * 8;
    int brow = (lane & 7) + (lane >> 4) * 8;
    int bk = ((lane >> 3) & 1) * 8;
    unsigned aBase = smb + (unsigned)((wm + arow) * CSTR + ak) * 2;
    unsigned bBase = smb + (unsigned)(2 * ASZE) * 2 + (unsigned)((wn + brow) * CSTR + bk) * 2;

    float c[4][4][4];
#pragma unroll
    for (int mt = 0; mt < 4; mt++)
#pragma unroll
        for (int nt = 0; nt < 4; nt++)
#pragma unroll
            for (int u = 0; u < 4; u++) c[mt][nt][u] = 0.f;

    const int NCH = 288;

    auto fill = [&](int ch, int st) {
        bool hi = ch < 144;
        int rem = hi ? ch : ch - 144;
        int tap = rem >> 4;
        int ci0 = (rem & 15) << 6;
        int k = tap * 1024 + ci0;
        unsigned ab = smb + (unsigned)(st * STGB);
        unsigned a1b = ab + ASZE * 2;
        unsigned bb = ab + 2 * ASZE * 2;
#pragma unroll
        for (int u = 0; u < 2; u++) {
            int idx = u * 512 + tid;
            int m = idx >> 3, oct = idx & 7;
            cp16(ab + (unsigned)(m * CSTR + oct * 8) * 2,
                 &g_wsplit[(size_t)(m0 + m) * KW + k + oct * 8], 16);
        }
        if (hi) {
#pragma unroll
            for (int u = 0; u < 2; u++) {
                int idx = u * 512 + tid;
                int m = idx >> 3, oct = idx & 7;
                cp16(a1b + (unsigned)(m * CSTR + oct * 8) * 2,
                     &g_wsplit[(size_t)(m0 + m) * KW + KC + k + oct * 8], 16);
            }
        }
        const __nv_bfloat16* Xp = hi ? g_xhi_t : g_xlo_t;
        int t3 = tap / 3;
        int yy = py + t3 - 1, xx = px + (tap - t3 * 3 - 1);
        bool v = pv && (unsigned)yy < HH && (unsigned)xx < WW;
        const __nv_bfloat16* src = v ? &Xp[(size_t)(yy * WW + xx) * CIN + ci0 + half * 32] : Xp;
        int sz = v ? 16 : 0;
        unsigned brw = bb + (unsigned)(pix * CSTR + half * 32) * 2;
#pragma unroll
        for (int u = 0; u < 4; u++) cp16(brw + u * 16, src + u * 8, sz);
    };

    fill(0, 0);
    asm volatile("cp.async.commit_group;");

    for (int ch = 0; ch < NCH; ch++) {
        int st = ch & 1;
        if (ch + 1 < NCH) {
            fill(ch + 1, st ^ 1);
            asm volatile("cp.async.commit_group;");
            asm volatile("cp.async.wait_group 1;");
        } else {
            asm volatile("cp.async.wait_group 0;");
        }
        __syncthreads();
        unsigned sb = (unsigned)(st * STGB);
        bool hi = ch < 144;
#pragma unroll
        for (int ko = 0; ko < 64; ko += 16) {
            unsigned kb = (unsigned)(ko * 2);
            unsigned b[4][2];
            ldsm4(b[0][0], b[0][1], b[1][0], b[1][1], bBase + sb + kb);
            ldsm4(b[2][0], b[2][1], b[3][0], b[3][1], bBase + sb + kb + 16 * CSTR * 2);
            unsigned a[4][4];
#pragma unroll
            for (int mt = 0; mt < 4; mt++)
                ldsm4(a[mt][0], a[mt][1], a[mt][2], a[mt][3],
                      aBase + sb + kb + (unsigned)(mt * 16 * CSTR) * 2);
#pragma unroll
            for (int mt = 0; mt < 4; mt++)
#pragma unroll
                for (int nt = 0; nt < 4; nt++) {
                    asm volatile(
                        "mma.sync.aligned.m16n8k16.row.col.f32.bf16.bf16.f32 "
                        "{%0,%1,%2,%3}, {%4,%5,%6,%7}, {%8,%9}, {%0,%1,%2,%3};"
                        : "+f"(c[mt][nt][0]), "+f"(c[mt][nt][1]),
                          "+f"(c[mt][nt][2]), "+f"(c[mt][nt][3])
                        : "r"(a[mt][0]), "r"(a[mt][1]), "r"(a[mt][2]), "r"(a[mt][3]),
                          "r"(b[nt][0]), "r"(b[nt][1]));
                }
            if (hi) {
#pragma unroll
                for (int mt = 0; mt < 4; mt++)
                    ldsm4(a[mt][0], a[mt][1], a[mt][2], a[mt][3],
                          aBase + sb + kb + (unsigned)(ASZE * 2) + (unsigned)(mt * 16 * CSTR) * 2);
#pragma unroll
                for (int mt = 0; mt < 4; mt++)
#pragma unroll
                    for (int nt = 0; nt < 4; nt++) {
                        asm volatile(
                            "mma.sync.aligned.m16n8k16.row.col.f32.bf16.bf16.f32 "
                            "{%0,%1,%2,%3}, {%4,%5,%6,%7}, {%8,%9}, {%0,%1,%2,%3};"
                            : "+f"(c[mt][nt][0]), "+f"(c[mt][nt][1]),
                              "+f"(c[mt][nt][2]), "+f"(c[mt][nt][3])
                            : "r"(a[mt][0]), "r"(a[mt][1]), "r"(a[mt][2]), "r"(a[mt][3]),
                              "r"(b[nt][0]), "r"(b[nt][1]));
                    }
            }
        }
        __syncthreads();
    }
#pragma unroll
    for (int mt = 0; mt < 4; mt++) {
#pragma unroll
        for (int nt = 0; nt < 4; nt++) {
            int m = m0 + wm + mt * 16 + g;
            int pp = n0 + wn + nt * 8 + tq * 2;
            float bv0 = bias[m], bv1 = bias[m + 8];
            float v0 = fmaxf(c[mt][nt][0] + bv0, 0.f);
            float v1 = fmaxf(c[mt][nt][1] + bv0, 0.f);
            float v2 = fmaxf(c[mt][nt][2] + bv1, 0.f);
            float v3 = fmaxf(c[mt][nt][3] + bv1, 0.f);
            if (pp + 1 < HW) {
                *reinterpret_cast<float2*>(&g_rpn[(size_t)m * HW + pp]) = make_float2(v0, v1);
                *reinterpret_cast<float2*>(&g_rpn[(size_t)(m + 8) * HW + pp]) = make_float2(v2, v3);
            } else if (pp < HW) {
                g_rpn[(size_t)m * HW + pp] = v0;
                g_rpn[(size_t)(m + 8) * HW + pp] = v2;
            }
        }
    }
}

__global__ void __launch_bounds__(128) k_conv1x1(const float* __restrict__ cw,
                                                 const float* __restrict__ cb,
                                                 const float* __restrict__ bw,
                                                 const float* __restrict__ bb) {
    __shared__ float ws[27 * 128];
    int tid = threadIdx.x;
    int p = blockIdx.x * 128 + tid;
    bool pv = p < HW;
    int half = blockIdx.y;
    float acc[27];
#pragma unroll
    for (int c = 0; c < 27; c++) {
        int oc = half * 27 + c;
        acc[c] = (oc < 18) ? cb[oc] : bb[oc - 18];
    }
    for (int kc = 0; kc < 512; kc += 128) {
        __syncthreads();
#pragma unroll
        for (int c = 0; c < 27; c++) {
            int oc = half * 27 + c;
            ws[c * 128 + tid] = (oc < 18) ? cw[oc * 512 + kc + tid] : bw[(oc - 18) * 512 + kc + tid];
        }
        __syncthreads();
        for (int k = 0; k < 128; k++) {
            float rv = pv ? g_rpn[(size_t)(kc + k) * HW + p] : 0.f;
#pragma unroll
            for (int c = 0; c < 27; c++) acc[c] = fmaf(rv, ws[c * 128 + k], acc[c]);
        }
    }
    if (pv) {
#pragma unroll
        for (int c = 0; c < 27; c++) {
            int oc = half * 27 + c;
            if (oc < 18) g_cls[oc * HW + p] = acc[c];
            else g_bbox[(oc - 18) * HW + p] = acc[c];
        }
    }
}

__global__ void k_fgboxes(const float* __restrict__ anchors) {
    int i = blockIdx.x * blockDim.x + threadIdx.x;
    if (i >= NANCH) return;
    int p = i / AA, a = i - p * AA;
    float s0 = g_cls[a * HW + p], s1 = g_cls[(9 + a) * HW + p];
    float m = fmaxf(s0, s1);
    float e0 = expf(s0 - m), e1 = expf(s1 - m);
    float fg = e1 / (e0 + e1);
    unsigned int u = __float_as_uint(fg);
    u = (u & 0x80000000u) ? ~u : (u | 0x80000000u);
    g_key[i] = u;
    atomicAdd(&g_hist[u >> 16], 1);
    float ax1 = anchors[i * 4], ay1 = anchors[i * 4 + 1];
    float ax2 = anchors[i * 4 + 2], ay2 = anchors[i * 4 + 3];
    float aw = ax2 - ax1 + 1.f, ah = ay2 - ay1 + 1.f;
    float acx = ax1 + 0.5f * aw, acy = ay1 + 0.5f * ah;
    float dx = g_bbox[(4 * a) * HW + p], dy = g_bbox[(4 * a + 1) * HW + p];
    float dw = g_bbox[(4 * a + 2) * HW + p], dh = g_bbox[(4 * a + 3) * HW + p];
    float pcx = dx * aw + acx, pcy = dy * ah + acy;
    float pw = expf(dw) * aw, ph = expf(dh) * ah;
    g_boxes[i * 4 + 0] = fminf(fmaxf(pcx - 0.5f * pw, 0.f), 1919.f);
    g_boxes[i * 4 + 1] = fminf(fmaxf(pcy - 0.5f * ph, 0.f), 1215.f);
    g_boxes[i * 4 + 2] = fminf(fmaxf(pcx + 0.5f * pw, 0.f), 1919.f);
    g_boxes[i * 4 + 3] = fminf(fmaxf(pcy + 0.5f * ph, 0.f), 1215.f);
}

__global__ void k_scan() {
    __shared__ int cs[256];
    int t = threadIdx.x;
    int s = 0;
    for (int j = 0; j < 256; j++) s += g_hist[t * 256 + j];
    cs[t] = s;
    __syncthreads();
    if (t == 0) {
        int acc = 0, chunk = 0;
        for (int i = 255; i >= 0; i--) {
            if (acc + cs[i] >= TOPN) { chunk = i; break; }
            acc += cs[i];
        }
        int T = chunk * 256;
        for (int b = chunk * 256 + 255; b >= chunk * 256; b--) {
            if (acc + g_hist[b] >= TOPN) { T = b; break; }
            acc += g_hist[b];
        }
        g_thr_bin = T;
    }
}

__global__ void k_compact() {
    int i = blockIdx.x * blockDim.x + threadIdx.x;
    if (i >= NANCH) return;
    unsigned int u = g_key[i];
    if ((int)(u >> 16) >= g_thr_bin) {
        int pos = atomicAdd(&g_cand_cnt, 1);
        g_ckey[pos] = u;
        g_cidx[pos] = i;
    }
}

__global__ void k_rank() {
    int c = g_cand_cnt;
    int i = blockIdx.x * blockDim.x + threadIdx.x;
    if (i >= c) return;
    unsigned int ki = g_ckey[i];
    int di = g_cidx[i];
    int rank = 0;
    for (int j = 0; j < c; j++) {
        unsigned int kj = g_ckey[j];
        if (kj > ki || (kj == ki && g_cidx[j] < di)) rank++;
    }
    if (rank < TOPN) {
        g_rois[rank * 4 + 0] = g_boxes[di * 4 + 0];
        g_rois[rank * 4 + 1] = g_boxes[di * 4 + 1];
        g_rois[rank * 4 + 2] = g_boxes[di * 4 + 2];
        g_rois[rank * 4 + 3] = g_boxes[di * 4 + 3];
    }
}

__global__ void __launch_bounds__(256) k_roialign() {
    int r = blockIdx.y, q = blockIdx.x;
    int pyy = q / 7, pxx = q - pyy * 7;
    float x1 = g_rois[r * 4 + 0] * 0.0625f, y1 = g_rois[r * 4 + 1] * 0.0625f;
    float x2 = g_rois[r * 4 + 2] * 0.0625f, y2 = g_rois[r * 4 + 3] * 0.0625f;
    float xs = fminf(fmaxf(x1 + (x2 - x1) * ((pxx + 0.5f) / 7.f), 0.f), 119.f);
    float ys = fminf(fmaxf(y1 + (y2 - y1) * ((pyy + 0.5f) / 7.f), 0.f), 75.f);
    float x0f = floorf(xs), y0f = floorf(ys);
    int x0i = (int)x0f, y0i = (int)y0f;
    int x1i = min(x0i + 1, 119), y1i = min(y0i + 1, 75);
    float wx = xs - x0f, wy = ys - y0f;
    float w00 = (1.f - wy) * (1.f - wx), w01 = (1.f - wy) * wx;
    float w10 = wy * (1.f - wx), w11 = wy * wx;
    const float* f00 = &g_feat_t[(size_t)(y0i * WW + x0i) * CIN];
    const float* f01 = &g_feat_t[(size_t)(y0i * WW + x1i) * CIN];
    const float* f10 = &g_feat_t[(size_t)(y1i * WW + x0i) * CIN];
    const float* f11 = &g_feat_t[(size_t)(y1i * WW + x1i) * CIN];
    __nv_bfloat16* outp = &g_pooledh[(size_t)r * KFC + q * 1024];
    for (int c = threadIdx.x; c < CIN; c += 256) {
        float v = f00[c] * w00 + f01[c] * w01 + f10[c] * w10 + f11[c] * w11;
        outp[c] = __float2bfloat16_rn(v);
    }
}

__global__ void __launch_bounds__(256) k_fcgemm(const float* __restrict__ Bw) {
    __shared__ __nv_bfloat16 Asm[128 * 40];
    __shared__ __nv_bfloat16 Bks[32 * 132];
    int tid = threadIdx.x;
    int lane = tid & 31, warp = tid >> 5;
    int n0 = blockIdx.x * 128, m0 = blockIdx.y * 128;
    int kz = blockIdx.z * KPZ;
    int wm = (warp >> 2) * 64;
    int wn = (warp & 3) * 32;
    int g = lane >> 2, tq = lane & 3;
    int mlim = TOPN - m0 - wm;
    float c[4][4][4];
#pragma unroll
    for (int mt = 0; mt < 4; mt++)
#pragma unroll
        for (int nt = 0; nt < 4; nt++)
#pragma unroll
            for (int u = 0; u < 4; u++) c[mt][nt][u] = 0.f;

    for (int ks = 0; ks < KPZ; ks += 32) {
#pragma unroll
        for (int u = 0; u < 2; u++) {
            int idx = tid * 2 + u;
            int r = idx >> 2, c8 = idx & 3;
            uint4 v = make_uint4(0, 0, 0, 0);
            int m = m0 + r;
            if (m < TOPN)
                v = *reinterpret_cast<const uint4*>(&g_pooledh[(size_t)m * KFC + kz + ks + c8 * 8]);
            *reinterpret_cast<uint4*>(&Asm[r * 40 + c8 * 8]) = v;
        }
#pragma unroll
        for (int i = 0; i < 4; i++) {
            int idx = i * 256 + tid;
            int k = idx >> 5, cc = idx & 31;
            int kp = kz + ks + k;
            int ok = (kp & 1023) * 49 + (kp >> 10);
            float4 v = *reinterpret_cast<const float4*>(&Bw[(size_t)ok * FCD + n0 + cc * 4]);
            __nv_bfloat162 p0 = __floats2bfloat162_rn(v.x, v.y);
            __nv_bfloat162 p1 = __floats2bfloat162_rn(v.z, v.w);
            uint2 st;
            st.x = *reinterpret_cast<unsigned*>(&p0);
            st.y = *reinterpret_cast<unsigned*>(&p1);
            *reinterpret_cast<uint2*>(&Bks[k * 132 + cc * 4]) = st;
        }
        __syncthreads();
#pragma unroll
        for (int ko = 0; ko < 32; ko += 16) {
            unsigned a[4][4];
#pragma unroll
            for (int mt = 0; mt < 4; mt++) {
                if (mt * 16 >= mlim) continue;
                const __nv_bfloat16* ap = &Asm[(wm + mt * 16 + g) * 40 + ko + tq * 2];
                a[mt][0] = *reinterpret_cast<const unsigned*>(ap);
                a[mt][1] = *reinterpret_cast<const unsigned*>(ap + 8 * 40);
                a[mt][2] = *reinterpret_cast<const unsigned*>(ap + 8);
                a[mt][3] = *reinterpret_cast<const unsigned*>(ap + 8 * 40 + 8);
            }
            unsigned b[4][2];
#pragma unroll
            for (int nt = 0; nt < 4; nt++) {
                int n = wn + nt * 8 + g;
                unsigned lo0 = *reinterpret_cast<const unsigned short*>(&Bks[(ko + tq * 2) * 132 + n]);
                unsigned hi0 = *reinterpret_cast<const unsigned short*>(&Bks[(ko + tq * 2 + 1) * 132 + n]);
                b[nt][0] = lo0 | (hi0 << 16);
                unsigned lo1 = *reinterpret_cast<const unsigned short*>(&Bks[(ko + tq * 2 + 8) * 132 + n]);
                unsigned hi1 = *reinterpret_cast<const unsigned short*>(&Bks[(ko + tq * 2 + 9) * 132 + n]);
                b[nt][1] = lo1 | (hi1 << 16);
            }
#pragma unroll
            for (int mt = 0; mt < 4; mt++) {
                if (mt * 16 >= mlim) continue;
#pragma unroll
                for (int nt = 0; nt < 4; nt++) {
                    asm volatile(
                        "mma.sync.aligned.m16n8k16.row.col.f32.bf16.bf16.f32 "
                        "{%0,%1,%2,%3}, {%4,%5,%6,%7}, {%8,%9}, {%0,%1,%2,%3};"
                        : "+f"(c[mt][nt][0]), "+f"(c[mt][nt][1]),
                          "+f"(c[mt][nt][2]), "+f"(c[mt][nt][3])
                        : "r"(a[mt][0]), "r"(a[mt][1]), "r"(a[mt][2]), "r"(a[mt][3]),
                          "r"(b[nt][0]), "r"(b[nt][1]));
                }
            }
        }
        __syncthreads();
    }
#pragma unroll
    for (int mt = 0; mt < 4; mt++) {
#pragma unroll
        for (int nt = 0; nt < 4; nt++) {
            int m = m0 + wm + mt * 16 + g;
            int n = n0 + wn + nt * 8 + tq * 2;
            if (m < TOPN) {
                float2 v = make_float2(c[mt][nt][0], c[mt][nt][1]);
                *reinterpret_cast<float2*>(&g_fcp[((size_t)blockIdx.z * 384 + m) * FCD + n]) = v;
            }
            if (m + 8 < TOPN) {
                float2 v = make_float2(c[mt][nt][2], c[mt][nt][3]);
                *reinterpret_cast<float2*>(&g_fcp[((size_t)blockIdx.z * 384 + m + 8) * FCD + n]) = v;
            }
        }
    }
}

__global__ void k_fcreduce(const float* __restrict__ fb) {
    int i = blockIdx.x * blockDim.x + threadIdx.x;
    if (i >= TOPN * FCD) return;
    int m = i / FCD, n = i - m * FCD;
    float s = fb[n];
#pragma unroll
    for (int z = 0; z < ZSPLIT; z++) s += g_fcp[((size_t)z * 384 + m) * FCD + n];
    g_fc7[i] = s > 0.f ? s : 0.f;
}

__global__ void __launch_bounds__(128) k_heads(const float* __restrict__ cb, const float* __restrict__ bb,
                                               const float* __restrict__ tgt, const float* __restrict__ biw,
                                               const float* __restrict__ bow, const int* __restrict__ lab) {
    __shared__ float sf[FCD];
    __shared__ float so[112];
    int r = blockIdx.x, t = threadIdx.x;
    int warp = t >> 5, lane = t & 31;
    for (int k = t; k < FCD; k += 128) sf[k] = g_fc7[(size_t)r * FCD + k];
    __syncthreads();
    for (int o = warp; o < 105; o += 4) {
        const float* wp = &g_hwT[(size_t)o * FCD];
        float acc = 0.f;
        for (int k = lane; k < FCD; k += 32) acc = fmaf(sf[k], wp[k], acc);
#pragma unroll
        for (int off = 16; off > 0; off >>= 1)
            acc += __shfl_xor_sync(0xffffffffu, acc, off);
        if (lane == 0) so[o] = acc + ((o < 21) ? cb[o] : bb[o - 21]);
    }
    __syncthreads();
    if (t == 0) {
        float m = so[0];
        for (int c = 1; c < 21; c++) m = fmaxf(m, so[c]);
        float se = 0.f;
        for (int c = 0; c < 21; c++) se += expf(so[c] - m);
        float lse = m + logf(se);
        g_ce2[r] = lse - so[lab[r]];
        float lb = 0.f;
        for (int o = 0; o < 84; o++) {
            int idx = r * 84 + o;
            float d = biw[idx] * (so[21 + o] - tgt[idx]);
            float ad = fabsf(d);
            float loss = (ad < 1.f) ? d * d * 0.5f : (ad - 0.5f);
            lb += bow[idx] * loss;
        }
        g_lbrow[r] = lb;
    }
}

__global__ void __launch_bounds__(256) k_loss1(const int* __restrict__ lab, const float* __restrict__ tgt,
                                               const float* __restrict__ biw, const float* __restrict__ bow) {
    __shared__ float sce[256], scn[256], slb[256];
    int t = threadIdx.x;
    int gid = blockIdx.x * 256 + t;
    int stride = NB_RED * 256;
    float ce = 0.f, cn = 0.f, lb = 0.f;
    for (int e = gid; e < 36 * HW; e += stride) {
        int p = e / 36, c = e - p * 36;
        float d = biw[e] * (g_bbox[c * HW + p] - tgt[e]);
        float ad = fabsf(d);
        float loss = (ad < (1.f / 9.f)) ? d * d * 4.5f : (ad - 1.f / 18.f);
        lb += bow[e] * loss;
        if (e < NANCH) {
            int L = lab[e];
            if (L != -1) {
                int a = e / HW, pp = e - a * HW;
                float s0 = g_cls[a * HW + pp], s1 = g_cls[(9 + a) * HW + pp];
                float m = fmaxf(s0, s1);
                float lse = m + logf(expf(s0 - m) + expf(s1 - m));
                ce += lse - (L ? s1 : s0);
                cn += 1.f;
            }
        }
    }
    sce[t] = ce; scn[t] = cn; slb[t] = lb;
    __syncthreads();
    for (int o = 128; o > 0; o >>= 1) {
        if (t < o) { sce[t] += sce[t + o]; scn[t] += scn[t + o]; slb[t] += slb[t + o]; }
        __syncthreads();
    }
    if (t == 0) {
        g_red_ce[blockIdx.x] = sce[0];
        g_red_cnt[blockIdx.x] = scn[0];
        g_red_lb[blockIdx.x] = slb[0];
    }
}

__global__ void k_final(float* out) {
    if (threadIdx.x != 0) return;
    float ce = 0.f, cn = 0.f, lb = 0.f;
    for (int i = 0; i < NB_RED; i++) { ce += g_red_ce[i]; cn += g_red_cnt[i]; lb += g_red_lb[i]; }
    float ce2 = 0.f, lb2 = 0.f;
    for (int r = 0; r < TOPN; r++) { ce2 += g_ce2[r]; lb2 += g_lbrow[r]; }
    out[0] = ce / fmaxf(cn, 1.f) + lb + ce2 / TOPN + lb2 / TOPN;
}

extern "C" void kernel_launch(void* const* d_in, const int* in_sizes, int n_in,
                              void* d_out, int out_size) {
    const float* net_conv = (const float*)d_in[0];
    const float* rpn_w = (const float*)d_in[1];
    const float* rpn_b = (const float*)d_in[2];
    const float* rpn_cls_w = (const float*)d_in[3];
    const float* rpn_cls_b = (const float*)d_in[4];
    const float* rpn_bbox_w = (const float*)d_in[5];
    const float* rpn_bbox_b = (const float*)d_in[6];
    const float* fc_w = (const float*)d_in[7];
    const float* fc_b = (const float*)d_in[8];
    const float* cls_w = (const float*)d_in[9];
    const float* cls_b = (const float*)d_in[10];
    const float* bbox_w = (const float*)d_in[11];
    const float* bbox_b = (const float*)d_in[12];
    const float* anchors = (const float*)d_in[13];
    const float* rpn_tgt = (const float*)d_in[14];
    const float* rpn_biw = (const float*)d_in[15];
    const float* rpn_bow = (const float*)d_in[16];
    const float* roi_tgt = (const float*)d_in[17];
    const float* roi_biw = (const float*)d_in[18];
    const float* roi_bow = (const float*)d_in[19];
    const int* rpn_lab = (const int*)d_in[20];
    const int* roi_lab = (const int*)d_in[21];
    float* out = (float*)d_out;

    cudaFuncSetAttribute(k_conv3x3_mma, cudaFuncAttributeMaxDynamicSharedMemorySize, CONV_SMEM);

    k_zero<<<256, 256>>>();
    k_prep_w<<<(512 * KC + 255) / 256, 256>>>(rpn_w);
    k_prep_x<<<dim3(285, 32), dim3(32, 8)>>>(net_conv);
    k_conv3x3_mma<<<dim3(36, 4), 512, CONV_SMEM>>>(rpn_b);
    k_prep_hw<<<(105 * FCD + 255) / 256, 256>>>(cls_w, bbox_w);
    k_conv1x1<<<dim3(72, 2), 128>>>(rpn_cls_w, rpn_cls_b, rpn_bbox_w, rpn_bbox_b);
    k_fgboxes<<<321, 256>>>(anchors);
    k_scan<<<1, 256>>>();
    k_compact<<<321, 256>>>();
    k_rank<<<321, 256>>>();
    k_roialign<<<dim3(49, TOPN), 256>>>();
    k_fcgemm<<<dim3(16, 3, ZSPLIT), 256>>>(fc_w);
    k_fcreduce<<<(TOPN * FCD + 255) / 256, 256>>>(fc_b);
    k_heads<<<TOPN, 128>>>(cls_b, bbox_b, roi_tgt, roi_biw, roi_bow, roi_lab);
    k_loss1<<<NB_RED, 256>>>(rpn_lab, rpn_tgt, rpn_biw, rpn_bow);
    k_final<<<1, 32>>>(out);
}

// round 14
// speedup vs baseline: 2.7117x; 1.0343x over previous
#include <cuda_runtime.h>
#include <cuda_bf16.h>
#include <math.h>

#define HH 76
#define WW 120
#define HW 9120
#define AA 9
#define NANCH 82080
#define CIN 1024
#define KC 9216
#define KW 18432
#define TOPN 300
#define FCD 2048
#define KFC 50176
#define ZSPLIT 4
#define KPZ (KFC / ZSPLIT)
#define NB_RED 256
#define CSTR 72
#define ASZE 9216
#define STGE 36864
#define STGB (STGE * 2)
#define CONV_SMEM (3 * STGB)

__device__ float g_rpn[512 * HW];
__device__ float g_cls[18 * HW];
__device__ float g_bbox[36 * HW];
__device__ unsigned int g_key[NANCH];
__device__ float g_boxes[NANCH * 4];
__device__ int g_hist[65536];
__device__ int g_thr_bin;
__device__ int g_cand_cnt;
__device__ unsigned int g_ckey[NANCH];
__device__ int g_cidx[NANCH];
__device__ float g_rois[TOPN * 4];
__device__ float g_feat_t[HW * CIN];
__device__ __nv_bfloat16 g_pooledh[TOPN * KFC];
__device__ float g_fcp[ZSPLIT * 384 * FCD];
__device__ float g_fc7[TOPN * FCD];
__device__ float g_ce2[TOPN];
__device__ float g_lbrow[TOPN];
__device__ float g_red_ce[NB_RED];
__device__ float g_red_cnt[NB_RED];
__device__ float g_red_lb[NB_RED];
__device__ __nv_bfloat16 g_wsplit[512 * KW];
__device__ __nv_bfloat16 g_xhi_t[HW * CIN];
__device__ __nv_bfloat16 g_xlo_t[HW * CIN];
__device__ float g_hwT[105 * FCD];

__device__ __forceinline__ void cp16(unsigned dst, const void* src, int srcsize) {
    asm volatile("cp.async.cg.shared.global [%0], [%1], 16, %2;" :: "r"(dst), "l"(src), "r"(srcsize));
}

__device__ __forceinline__ void ldsm4(unsigned& r0, unsigned& r1, unsigned& r2, unsigned& r3,
                                      unsigned addr) {
    asm volatile("ldmatrix.sync.aligned.m8n8.x4.shared.b16 {%0,%1,%2,%3}, [%4];"
                 : "=r"(r0), "=r"(r1), "=r"(r2), "=r"(r3) : "r"(addr));
}

__global__ void k_zero() {
    int i = blockIdx.x * blockDim.x + threadIdx.x;
    if (i < 65536) g_hist[i] = 0;
    if (i == 0) g_cand_cnt = 0;
}

__global__ void k_prep_w(const float* __restrict__ Wt) {
    int i = blockIdx.x * blockDim.x + threadIdx.x;
    if (i >= 512 * KC) return;
    int m = i / KC, r = i - m * KC;
    int t9 = r >> 10, ci = r & 1023;
    float w = Wt[(size_t)m * KC + ci * 9 + t9];
    __nv_bfloat16 hi = __float2bfloat16_rn(w);
    __nv_bfloat16 lo = __float2bfloat16_rn(w - __bfloat162float(hi));
    size_t base = (size_t)m * KW;
    g_wsplit[base + r] = hi;
    g_wsplit[base + KC + r] = lo;
}

__global__ void k_prep_x(const float* __restrict__ X) {
    __shared__ float tile[32][33];
    int tx = threadIdx.x, ty = threadIdx.y;
    int p0 = blockIdx.x * 32, c0 = blockIdx.y * 32;
#pragma unroll
    for (int j = 0; j < 32; j += 8) tile[ty + j][tx] = X[(size_t)(c0 + ty + j) * HW + p0 + tx];
    __syncthreads();
#pragma unroll
    for (int j = 0; j < 32; j += 8) {
        float v = tile[tx][ty + j];
        size_t o = (size_t)(p0 + ty + j) * CIN + c0 + tx;
        g_feat_t[o] = v;
        __nv_bfloat16 hi = __float2bfloat16_rn(v);
        g_xhi_t[o] = hi;
        g_xlo_t[o] = __float2bfloat16_rn(v - __bfloat162float(hi));
    }
}

__global__ void k_prep_hw(const float* __restrict__ cw, const float* __restrict__ bw) {
    int i = blockIdx.x * blockDim.x + threadIdx.x;
    if (i >= 105 * FCD) return;
    int o = i / FCD, k = i - o * FCD;
    g_hwT[i] = (o < 21) ? cw[k * 21 + o] : bw[k * 84 + (o - 21)];
}

// conv3x3 implicit GEMM: block 128x256, 16 warps (64x32 warp tile), BK=64,
// ldmatrix fragments, 3-stage cp.async pipeline with ONE sync per chunk.
__global__ void __launch_bounds__(512, 1) k_conv3x3_mma(const float* __restrict__ bias) {
    extern __shared__ __nv_bfloat16 sm[];
    unsigned smb = (unsigned)__cvta_generic_to_shared(sm);
    int tid = threadIdx.x;
    int lane = tid & 31, warp = tid >> 5;
    int n0 = blockIdx.x * 256, m0 = blockIdx.y * 128;
    int wm = (warp & 1) * 64, wn = (warp >> 1) * 32;
    int g = lane >> 2, tq = lane & 3;
    int pix = tid >> 1, half = tid & 1;
    int p = n0 + pix;
    bool pv = p < HW;
    int py = p / WW, px = p - py * WW;

    int arow = (lane & 7) + ((lane >> 3) & 1) * 8;
    int ak = (lane >> 4) * 8;
    int brow = (lane & 7) + (lane >> 4) * 8;
    int bk = ((lane >> 3) & 1) * 8;
    unsigned aBase = smb + (unsigned)((wm + arow) * CSTR + ak) * 2;
    unsigned bBase = smb + (unsigned)(2 * ASZE) * 2 + (unsigned)((wn + brow) * CSTR + bk) * 2;

    float c[4][4][4];
#pragma unroll
    for (int mt = 0; mt < 4; mt++)
#pragma unroll
        for (int nt = 0; nt < 4; nt++)
#pragma unroll
            for (int u = 0; u < 4; u++) c[mt][nt][u] = 0.f;

    const int NCH = 288;

    auto fill = [&](int ch, int st) {
        bool hi = ch < 144;
        int rem = hi ? ch : ch - 144;
        int tap = rem >> 4;
        int ci0 = (rem & 15) << 6;
        int k = tap * 1024 + ci0;
        unsigned ab = smb + (unsigned)(st * STGB);
        unsigned a1b = ab + ASZE * 2;
        unsigned bb = ab + 2 * ASZE * 2;
#pragma unroll
        for (int u = 0; u < 2; u++) {
            int idx = u * 512 + tid;
            int m = idx >> 3, oct = idx & 7;
            cp16(ab + (unsigned)(m * CSTR + oct * 8) * 2,
                 &g_wsplit[(size_t)(m0 + m) * KW + k + oct * 8], 16);
        }
        if (hi) {
#pragma unroll
            for (int u = 0; u < 2; u++) {
                int idx = u * 512 + tid;
                int m = idx >> 3, oct = idx & 7;
                cp16(a1b + (unsigned)(m * CSTR + oct * 8) * 2,
                     &g_wsplit[(size_t)(m0 + m) * KW + KC + k + oct * 8], 16);
            }
        }
        const __nv_bfloat16* Xp = hi ? g_xhi_t : g_xlo_t;
        int t3 = tap / 3;
        int yy = py + t3 - 1, xx = px + (tap - t3 * 3 - 1);
        bool v = pv && (unsigned)yy < HH && (unsigned)xx < WW;
        const __nv_bfloat16* src = v ? &Xp[(size_t)(yy * WW + xx) * CIN + ci0 + half * 32] : Xp;
        int sz = v ? 16 : 0;
        unsigned brw = bb + (unsigned)(pix * CSTR + half * 32) * 2;
#pragma unroll
        for (int u = 0; u < 4; u++) cp16(brw + u * 16, src + u * 8, sz);
    };

    // prologue: 2 chunks in flight across 3 stages
    fill(0, 0);
    asm volatile("cp.async.commit_group;");
    fill(1, 1);
    asm volatile("cp.async.commit_group;");

    for (int ch = 0; ch < NCH; ch++) {
        int st = ch % 3;
        if (ch + 1 < NCH) asm volatile("cp.async.wait_group 1;");
        else asm volatile("cp.async.wait_group 0;");
        __syncthreads();
        if (ch + 2 < NCH) {
            fill(ch + 2, (ch + 2) % 3);
            asm volatile("cp.async.commit_group;");
        }
        unsigned sb = (unsigned)(st * STGB);
        bool hi = ch < 144;
#pragma unroll
        for (int ko = 0; ko < 64; ko += 16) {
            unsigned kb = (unsigned)(ko * 2);
            unsigned b[4][2];
            ldsm4(b[0][0], b[0][1], b[1][0], b[1][1], bBase + sb + kb);
            ldsm4(b[2][0], b[2][1], b[3][0], b[3][1], bBase + sb + kb + 16 * CSTR * 2);
            unsigned a[4][4];
#pragma unroll
            for (int mt = 0; mt < 4; mt++)
                ldsm4(a[mt][0], a[mt][1], a[mt][2], a[mt][3],
                      aBase + sb + kb + (unsigned)(mt * 16 * CSTR) * 2);
#pragma unroll
            for (int mt = 0; mt < 4; mt++)
#pragma unroll
                for (int nt = 0; nt < 4; nt++) {
                    asm volatile(
                        "mma.sync.aligned.m16n8k16.row.col.f32.bf16.bf16.f32 "
                        "{%0,%1,%2,%3}, {%4,%5,%6,%7}, {%8,%9}, {%0,%1,%2,%3};"
                        : "+f"(c[mt][nt][0]), "+f"(c[mt][nt][1]),
                          "+f"(c[mt][nt][2]), "+f"(c[mt][nt][3])
                        : "r"(a[mt][0]), "r"(a[mt][1]), "r"(a[mt][2]), "r"(a[mt][3]),
                          "r"(b[nt][0]), "r"(b[nt][1]));
                }
            if (hi) {
#pragma unroll
                for (int mt = 0; mt < 4; mt++)
                    ldsm4(a[mt][0], a[mt][1], a[mt][2], a[mt][3],
                          aBase + sb + kb + (unsigned)(ASZE * 2) + (unsigned)(mt * 16 * CSTR) * 2);
#pragma unroll
                for (int mt = 0; mt < 4; mt++)
#pragma unroll
                    for (int nt = 0; nt < 4; nt++) {
                        asm volatile(
                            "mma.sync.aligned.m16n8k16.row.col.f32.bf16.bf16.f32 "
                            "{%0,%1,%2,%3}, {%4,%5,%6,%7}, {%8,%9}, {%0,%1,%2,%3};"
                            : "+f"(c[mt][nt][0]), "+f"(c[mt][nt][1]),
                              "+f"(c[mt][nt][2]), "+f"(c[mt][nt][3])
                            : "r"(a[mt][0]), "r"(a[mt][1]), "r"(a[mt][2]), "r"(a[mt][3]),
                              "r"(b[nt][0]), "r"(b[nt][1]));
                    }
            }
        }
    }
    __syncthreads();
#pragma unroll
    for (int mt = 0; mt < 4; mt++) {
#pragma unroll
        for (int nt = 0; nt < 4; nt++) {
            int m = m0 + wm + mt * 16 + g;
            int pp = n0 + wn + nt * 8 + tq * 2;
            float bv0 = bias[m], bv1 = bias[m + 8];
            float v0 = fmaxf(c[mt][nt][0] + bv0, 0.f);
            float v1 = fmaxf(c[mt][nt][1] + bv0, 0.f);
            float v2 = fmaxf(c[mt][nt][2] + bv1, 0.f);
            float v3 = fmaxf(c[mt][nt][3] + bv1, 0.f);
            if (pp + 1 < HW) {
                *reinterpret_cast<float2*>(&g_rpn[(size_t)m * HW + pp]) = make_float2(v0, v1);
                *reinterpret_cast<float2*>(&g_rpn[(size_t)(m + 8) * HW + pp]) = make_float2(v2, v3);
            } else if (pp < HW) {
                g_rpn[(size_t)m * HW + pp] = v0;
                g_rpn[(size_t)(m + 8) * HW + pp] = v2;
            }
        }
    }
}

__global__ void __launch_bounds__(128) k_conv1x1(const float* __restrict__ cw,
                                                 const float* __restrict__ cb,
                                                 const float* __restrict__ bw,
                                                 const float* __restrict__ bb) {
    __shared__ float ws[27 * 128];
    int tid = threadIdx.x;
    int p = blockIdx.x * 128 + tid;
    bool pv = p < HW;
    int half = blockIdx.y;
    float acc[27];
#pragma unroll
    for (int c = 0; c < 27; c++) {
        int oc = half * 27 + c;
        acc[c] = (oc < 18) ? cb[oc] : bb[oc - 18];
    }
    for (int kc = 0; kc < 512; kc += 128) {
        __syncthreads();
#pragma unroll
        for (int c = 0; c < 27; c++) {
            int oc = half * 27 + c;
            ws[c * 128 + tid] = (oc < 18) ? cw[oc * 512 + kc + tid] : bw[(oc - 18) * 512 + kc + tid];
        }
        __syncthreads();
        for (int k = 0; k < 128; k++) {
            float rv = pv ? g_rpn[(size_t)(kc + k) * HW + p] : 0.f;
#pragma unroll
            for (int c = 0; c < 27; c++) acc[c] = fmaf(rv, ws[c * 128 + k], acc[c]);
        }
    }
    if (pv) {
#pragma unroll
        for (int c = 0; c < 27; c++) {
            int oc = half * 27 + c;
            if (oc < 18) g_cls[oc * HW + p] = acc[c];
            else g_bbox[(oc - 18) * HW + p] = acc[c];
        }
    }
}

__global__ void k_fgboxes(const float* __restrict__ anchors) {
    int i = blockIdx.x * blockDim.x + threadIdx.x;
    if (i >= NANCH) return;
    int p = i / AA, a = i - p * AA;
    float s0 = g_cls[a * HW + p], s1 = g_cls[(9 + a) * HW + p];
    float m = fmaxf(s0, s1);
    float e0 = expf(s0 - m), e1 = expf(s1 - m);
    float fg = e1 / (e0 + e1);
    unsigned int u = __float_as_uint(fg);
    u = (u & 0x80000000u) ? ~u : (u | 0x80000000u);
    g_key[i] = u;
    atomicAdd(&g_hist[u >> 16], 1);
    float ax1 = anchors[i * 4], ay1 = anchors[i * 4 + 1];
    float ax2 = anchors[i * 4 + 2], ay2 = anchors[i * 4 + 3];
    float aw = ax2 - ax1 + 1.f, ah = ay2 - ay1 + 1.f;
    float acx = ax1 + 0.5f * aw, acy = ay1 + 0.5f * ah;
    float dx = g_bbox[(4 * a) * HW + p], dy = g_bbox[(4 * a + 1) * HW + p];
    float dw = g_bbox[(4 * a + 2) * HW + p], dh = g_bbox[(4 * a + 3) * HW + p];
    float pcx = dx * aw + acx, pcy = dy * ah + acy;
    float pw = expf(dw) * aw, ph = expf(dh) * ah;
    g_boxes[i * 4 + 0] = fminf(fmaxf(pcx - 0.5f * pw, 0.f), 1919.f);
    g_boxes[i * 4 + 1] = fminf(fmaxf(pcy - 0.5f * ph, 0.f), 1215.f);
    g_boxes[i * 4 + 2] = fminf(fmaxf(pcx + 0.5f * pw, 0.f), 1919.f);
    g_boxes[i * 4 + 3] = fminf(fmaxf(pcy + 0.5f * ph, 0.f), 1215.f);
}

__global__ void k_scan() {
    __shared__ int cs[256];
    int t = threadIdx.x;
    int s = 0;
    for (int j = 0; j < 256; j++) s += g_hist[t * 256 + j];
    cs[t] = s;
    __syncthreads();
    if (t == 0) {
        int acc = 0, chunk = 0;
        for (int i = 255; i >= 0; i--) {
            if (acc + cs[i] >= TOPN) { chunk = i; break; }
            acc += cs[i];
        }
        int T = chunk * 256;
        for (int b = chunk * 256 + 255; b >= chunk * 256; b--) {
            if (acc + g_hist[b] >= TOPN) { T = b; break; }
            acc += g_hist[b];
        }
        g_thr_bin = T;
    }
}

__global__ void k_compact() {
    int i = blockIdx.x * blockDim.x + threadIdx.x;
    if (i >= NANCH) return;
    unsigned int u = g_key[i];
    if ((int)(u >> 16) >= g_thr_bin) {
        int pos = atomicAdd(&g_cand_cnt, 1);
        g_ckey[pos] = u;
        g_cidx[pos] = i;
    }
}

__global__ void k_rank() {
    int c = g_cand_cnt;
    int i = blockIdx.x * blockDim.x + threadIdx.x;
    if (i >= c) return;
    unsigned int ki = g_ckey[i];
    int di = g_cidx[i];
    int rank = 0;
    for (int j = 0; j < c; j++) {
        unsigned int kj = g_ckey[j];
        if (kj > ki || (kj == ki && g_cidx[j] < di)) rank++;
    }
    if (rank < TOPN) {
        g_rois[rank * 4 + 0] = g_boxes[di * 4 + 0];
        g_rois[rank * 4 + 1] = g_boxes[di * 4 + 1];
        g_rois[rank * 4 + 2] = g_boxes[di * 4 + 2];
        g_rois[rank * 4 + 3] = g_boxes[di * 4 + 3];
    }
}

__global__ void __launch_bounds__(256) k_roialign() {
    int r = blockIdx.y, q = blockIdx.x;
    int pyy = q / 7, pxx = q - pyy * 7;
    float x1 = g_rois[r * 4 + 0] * 0.0625f, y1 = g_rois[r * 4 + 1] * 0.0625f;
    float x2 = g_rois[r * 4 + 2] * 0.0625f, y2 = g_rois[r * 4 + 3] * 0.0625f;
    float xs = fminf(fmaxf(x1 + (x2 - x1) * ((pxx + 0.5f) / 7.f), 0.f), 119.f);
    float ys = fminf(fmaxf(y1 + (y2 - y1) * ((pyy + 0.5f) / 7.f), 0.f), 75.f);
    float x0f = floorf(xs), y0f = floorf(ys);
    int x0i = (int)x0f, y0i = (int)y0f;
    int x1i = min(x0i + 1, 119), y1i = min(y0i + 1, 75);
    float wx = xs - x0f, wy = ys - y0f;
    float w00 = (1.f - wy) * (1.f - wx), w01 = (1.f - wy) * wx;
    float w10 = wy * (1.f - wx), w11 = wy * wx;
    const float* f00 = &g_feat_t[(size_t)(y0i * WW + x0i) * CIN];
    const float* f01 = &g_feat_t[(size_t)(y0i * WW + x1i) * CIN];
    const float* f10 = &g_feat_t[(size_t)(y1i * WW + x0i) * CIN];
    const float* f11 = &g_feat_t[(size_t)(y1i * WW + x1i) * CIN];
    __nv_bfloat16* outp = &g_pooledh[(size_t)r * KFC + q * 1024];
    for (int c = threadIdx.x; c < CIN; c += 256) {
        float v = f00[c] * w00 + f01[c] * w01 + f10[c] * w10 + f11[c] * w11;
        outp[c] = __float2bfloat16_rn(v);
    }
}

__global__ void __launch_bounds__(256) k_fcgemm(const float* __restrict__ Bw) {
    __shared__ __nv_bfloat16 Asm[128 * 40];
    __shared__ __nv_bfloat16 Bks[32 * 132];
    int tid = threadIdx.x;
    int lane = tid & 31, warp = tid >> 5;
    int n0 = blockIdx.x * 128, m0 = blockIdx.y * 128;
    int kz = blockIdx.z * KPZ;
    int wm = (warp >> 2) * 64;
    int wn = (warp & 3) * 32;
    int g = lane >> 2, tq = lane & 3;
    int mlim = TOPN - m0 - wm;
    float c[4][4][4];
#pragma unroll
    for (int mt = 0; mt < 4; mt++)
#pragma unroll
        for (int nt = 0; nt < 4; nt++)
#pragma unroll
            for (int u = 0; u < 4; u++) c[mt][nt][u] = 0.f;

    for (int ks = 0; ks < KPZ; ks += 32) {
#pragma unroll
        for (int u = 0; u < 2; u++) {
            int idx = tid * 2 + u;
            int r = idx >> 2, c8 = idx & 3;
            uint4 v = make_uint4(0, 0, 0, 0);
            int m = m0 + r;
            if (m < TOPN)
                v = *reinterpret_cast<const uint4*>(&g_pooledh[(size_t)m * KFC + kz + ks + c8 * 8]);
            *reinterpret_cast<uint4*>(&Asm[r * 40 + c8 * 8]) = v;
        }
#pragma unroll
        for (int i = 0; i < 4; i++) {
            int idx = i * 256 + tid;
            int k = idx >> 5, cc = idx & 31;
            int kp = kz + ks + k;
            int ok = (kp & 1023) * 49 + (kp >> 10);
            float4 v = *reinterpret_cast<const float4*>(&Bw[(size_t)ok * FCD + n0 + cc * 4]);
            __nv_bfloat162 p0 = __floats2bfloat162_rn(v.x, v.y);
            __nv_bfloat162 p1 = __floats2bfloat162_rn(v.z, v.w);
            uint2 st;
            st.x = *reinterpret_cast<unsigned*>(&p0);
            st.y = *reinterpret_cast<unsigned*>(&p1);
            *reinterpret_cast<uint2*>(&Bks[k * 132 + cc * 4]) = st;
        }
        __syncthreads();
#pragma unroll
        for (int ko = 0; ko < 32; ko += 16) {
            unsigned a[4][4];
#pragma unroll
            for (int mt = 0; mt < 4; mt++) {
                if (mt * 16 >= mlim) continue;
                const __nv_bfloat16* ap = &Asm[(wm + mt * 16 + g) * 40 + ko + tq * 2];
                a[mt][0] = *reinterpret_cast<const unsigned*>(ap);
                a[mt][1] = *reinterpret_cast<const unsigned*>(ap + 8 * 40);
                a[mt][2] = *reinterpret_cast<const unsigned*>(ap + 8);
                a[mt][3] = *reinterpret_cast<const unsigned*>(ap + 8 * 40 + 8);
            }
            unsigned b[4][2];
#pragma unroll
            for (int nt = 0; nt < 4; nt++) {
                int n = wn + nt * 8 + g;
                unsigned lo0 = *reinterpret_cast<const unsigned short*>(&Bks[(ko + tq * 2) * 132 + n]);
                unsigned hi0 = *reinterpret_cast<const unsigned short*>(&Bks[(ko + tq * 2 + 1) * 132 + n]);
                b[nt][0] = lo0 | (hi0 << 16);
                unsigned lo1 = *reinterpret_cast<const unsigned short*>(&Bks[(ko + tq * 2 + 8) * 132 + n]);
                unsigned hi1 = *reinterpret_cast<const unsigned short*>(&Bks[(ko + tq * 2 + 9) * 132 + n]);
                b[nt][1] = lo1 | (hi1 << 16);
            }
#pragma unroll
            for (int mt = 0; mt < 4; mt++) {
                if (mt * 16 >= mlim) continue;
#pragma unroll
                for (int nt = 0; nt < 4; nt++) {
                    asm volatile(
                        "mma.sync.aligned.m16n8k16.row.col.f32.bf16.bf16.f32 "
                        "{%0,%1,%2,%3}, {%4,%5,%6,%7}, {%8,%9}, {%0,%1,%2,%3};"
                        : "+f"(c[mt][nt][0]), "+f"(c[mt][nt][1]),
                          "+f"(c[mt][nt][2]), "+f"(c[mt][nt][3])
                        : "r"(a[mt][0]), "r"(a[mt][1]), "r"(a[mt][2]), "r"(a[mt][3]),
                          "r"(b[nt][0]), "r"(b[nt][1]));
                }
            }
        }
        __syncthreads();
    }
#pragma unroll
    for (int mt = 0; mt < 4; mt++) {
#pragma unroll
        for (int nt = 0; nt < 4; nt++) {
            int m = m0 + wm + mt * 16 + g;
            int n = n0 + wn + nt * 8 + tq * 2;
            if (m < TOPN) {
                float2 v = make_float2(c[mt][nt][0], c[mt][nt][1]);
                *reinterpret_cast<float2*>(&g_fcp[((size_t)blockIdx.z * 384 + m) * FCD + n]) = v;
            }
            if (m + 8 < TOPN) {
                float2 v = make_float2(c[mt][nt][2], c[mt][nt][3]);
                *reinterpret_cast<float2*>(&g_fcp[((size_t)blockIdx.z * 384 + m + 8) * FCD + n]) = v;
            }
        }
    }
}

__global__ void k_fcreduce(const float* __restrict__ fb) {
    int i = blockIdx.x * blockDim.x + threadIdx.x;
    if (i >= TOPN * FCD) return;
    int m = i / FCD, n = i - m * FCD;
    float s = fb[n];
#pragma unroll
    for (int z = 0; z < ZSPLIT; z++) s += g_fcp[((size_t)z * 384 + m) * FCD + n];
    g_fc7[i] = s > 0.f ? s : 0.f;
}

__global__ void __launch_bounds__(128) k_heads(const float* __restrict__ cb, const float* __restrict__ bb,
                                               const float* __restrict__ tgt, const float* __restrict__ biw,
                                               const float* __restrict__ bow, const int* __restrict__ lab) {
    __shared__ float sf[FCD];
    __shared__ float so[112];
    int r = blockIdx.x, t = threadIdx.x;
    int warp = t >> 5, lane = t & 31;
    for (int k = t; k < FCD; k += 128) sf[k] = g_fc7[(size_t)r * FCD + k];
    __syncthreads();
    for (int o = warp; o < 105; o += 4) {
        const float* wp = &g_hwT[(size_t)o * FCD];
        float acc = 0.f;
        for (int k = lane; k < FCD; k += 32) acc = fmaf(sf[k], wp[k], acc);
#pragma unroll
        for (int off = 16; off > 0; off >>= 1)
            acc += __shfl_xor_sync(0xffffffffu, acc, off);
        if (lane == 0) so[o] = acc + ((o < 21) ? cb[o] : bb[o - 21]);
    }
    __syncthreads();
    if (t == 0) {
        float m = so[0];
        for (int c = 1; c < 21; c++) m = fmaxf(m, so[c]);
        float se = 0.f;
        for (int c = 0; c < 21; c++) se += expf(so[c] - m);
        float lse = m + logf(se);
        g_ce2[r] = lse - so[lab[r]];
        float lb = 0.f;
        for (int o = 0; o < 84; o++) {
            int idx = r * 84 + o;
            float d = biw[idx] * (so[21 + o] - tgt[idx]);
            float ad = fabsf(d);
            float loss = (ad < 1.f) ? d * d * 0.5f : (ad - 0.5f);
            lb += bow[idx] * loss;
        }
        g_lbrow[r] = lb;
    }
}

__global__ void __launch_bounds__(256) k_loss1(const int* __restrict__ lab, const float* __restrict__ tgt,
                                               const float* __restrict__ biw, const float* __restrict__ bow) {
    __shared__ float sce[256], scn[256], slb[256];
    int t = threadIdx.x;
    int gid = blockIdx.x * 256 + t;
    int stride = NB_RED * 256;
    float ce = 0.f, cn = 0.f, lb = 0.f;
    for (int e = gid; e < 36 * HW; e += stride) {
        int p = e / 36, c = e - p * 36;
        float d = biw[e] * (g_bbox[c * HW + p] - tgt[e]);
        float ad = fabsf(d);
        float loss = (ad < (1.f / 9.f)) ? d * d * 4.5f : (ad - 1.f / 18.f);
        lb += bow[e] * loss;
        if (e < NANCH) {
            int L = lab[e];
            if (L != -1) {
                int a = e / HW, pp = e - a * HW;
                float s0 = g_cls[a * HW + pp], s1 = g_cls[(9 + a) * HW + pp];
                float m = fmaxf(s0, s1);
                float lse = m + logf(expf(s0 - m) + expf(s1 - m));
                ce += lse - (L ? s1 : s0);
                cn += 1.f;
            }
        }
    }
    sce[t] = ce; scn[t] = cn; slb[t] = lb;
    __syncthreads();
    for (int o = 128; o > 0; o >>= 1) {
        if (t < o) { sce[t] += sce[t + o]; scn[t] += scn[t + o]; slb[t] += slb[t + o]; }
        __syncthreads();
    }
    if (t == 0) {
        g_red_ce[blockIdx.x] = sce[0];
        g_red_cnt[blockIdx.x] = scn[0];
        g_red_lb[blockIdx.x] = slb[0];
    }
}

__global__ void k_final(float* out) {
    if (threadIdx.x != 0) return;
    float ce = 0.f, cn = 0.f, lb = 0.f;
    for (int i = 0; i < NB_RED; i++) { ce += g_red_ce[i]; cn += g_red_cnt[i]; lb += g_red_lb[i]; }
    float ce2 = 0.f, lb2 = 0.f;
    for (int r = 0; r < TOPN; r++) { ce2 += g_ce2[r]; lb2 += g_lbrow[r]; }
    out[0] = ce / fmaxf(cn, 1.f) + lb + ce2 / TOPN + lb2 / TOPN;
}

extern "C" void kernel_launch(void* const* d_in, const int* in_sizes, int n_in,
                              void* d_out, int out_size) {
    const float* net_conv = (const float*)d_in[0];
    const float* rpn_w = (const float*)d_in[1];
    const float* rpn_b = (const float*)d_in[2];
    const float* rpn_cls_w = (const float*)d_in[3];
    const float* rpn_cls_b = (const float*)d_in[4];
    const float* rpn_bbox_w = (const float*)d_in[5];
    const float* rpn_bbox_b = (const float*)d_in[6];
    const float* fc_w = (const float*)d_in[7];
    const float* fc_b = (const float*)d_in[8];
    const float* cls_w = (const float*)d_in[9];
    const float* cls_b = (const float*)d_in[10];
    const float* bbox_w = (const float*)d_in[11];
    const float* bbox_b = (const float*)d_in[12];
    const float* anchors = (const float*)d_in[13];
    const float* rpn_tgt = (const float*)d_in[14];
    const float* rpn_biw = (const float*)d_in[15];
    const float* rpn_bow = (const float*)d_in[16];
    const float* roi_tgt = (const float*)d_in[17];
    const float* roi_biw = (const float*)d_in[18];
    const float* roi_bow = (const float*)d_in[19];
    const int* rpn_lab = (const int*)d_in[20];
    const int* roi_lab = (const int*)d_in[21];
    float* out = (float*)d_out;

    cudaFuncSetAttribute(k_conv3x3_mma, cudaFuncAttributeMaxDynamicSharedMemorySize, CONV_SMEM);

    k_zero<<<256, 256>>>();
    k_prep_w<<<(512 * KC + 255) / 256, 256>>>(rpn_w);
    k_prep_x<<<dim3(285, 32), dim3(32, 8)>>>(net_conv);
    k_conv3x3_mma<<<dim3(36, 4), 512, CONV_SMEM>>>(rpn_b);
    k_prep_hw<<<(105 * FCD + 255) / 256, 256>>>(cls_w, bbox_w);
    k_conv1x1<<<dim3(72, 2), 128>>>(rpn_cls_w, rpn_cls_b, rpn_bbox_w, rpn_bbox_b);
    k_fgboxes<<<321, 256>>>(anchors);
    k_scan<<<1, 256>>>();
    k_compact<<<321, 256>>>();
    k_rank<<<321, 256>>>();
    k_roialign<<<dim3(49, TOPN), 256>>>();
    k_fcgemm<<<dim3(16, 3, ZSPLIT), 256>>>(fc_w);
    k_fcreduce<<<(TOPN * FCD + 255) / 256, 256>>>(fc_b);
    k_heads<<<TOPN, 128>>>(cls_b, bbox_b, roi_tgt, roi_biw, roi_bow, roi_lab);
    k_loss1<<<NB_RED, 256>>>(rpn_lab, rpn_tgt, rpn_biw, rpn_bow);
    k_final<<<1, 32>>>(out);
}

// round 15
// speedup vs baseline: 3.0483x; 1.1242x over previous
#include <cuda_runtime.h>
#include <cuda_bf16.h>
#include <math.h>

#define HH 76
#define WW 120
#define HW 9120
#define AA 9
#define NANCH 82080
#define CIN 1024
#define KC 9216
#define KW 18432
#define TOPN 300
#define FCD 2048
#define KFC 50176
#define ZSPLIT 4
#define KPZ (KFC / ZSPLIT)
#define NB_RED 256
#define CSTR 72
#define ASZE 9216
#define STGE 36864
#define STGB (STGE * 2)
#define CONV_SMEM (3 * STGB)
/* FC pipeline stage: A 384x40 bf16 (30720B) + B 32x68 fp32 (8704B) */
#define FC_ASTG 30720
#define FC_STG 39424
#define FC_SMEM (3 * FC_STG)

__device__ float g_rpn[512 * HW];
__device__ float g_cls[18 * HW];
__device__ float g_bbox[36 * HW];
__device__ unsigned int g_key[NANCH];
__device__ float g_boxes[NANCH * 4];
__device__ int g_hist[65536];
__device__ int g_thr_bin;
__device__ int g_cand_cnt;
__device__ unsigned int g_ckey[NANCH];
__device__ int g_cidx[NANCH];
__device__ float g_rois[TOPN * 4];
__device__ float g_feat_t[HW * CIN];
__device__ __nv_bfloat16 g_pooledh[TOPN * KFC];
__device__ float g_fcp[ZSPLIT * 384 * FCD];
__device__ float g_fc7[TOPN * FCD];
__device__ float g_ce2[TOPN];
__device__ float g_lbrow[TOPN];
__device__ float g_red_ce[NB_RED];
__device__ float g_red_cnt[NB_RED];
__device__ float g_red_lb[NB_RED];
__device__ __nv_bfloat16 g_wsplit[512 * KW];
__device__ __nv_bfloat16 g_xhi_t[HW * CIN];
__device__ __nv_bfloat16 g_xlo_t[HW * CIN];
__device__ float g_hwT[105 * FCD];

__device__ __forceinline__ void cp16(unsigned dst, const void* src, int srcsize) {
    asm volatile("cp.async.cg.shared.global [%0], [%1], 16, %2;" :: "r"(dst), "l"(src), "r"(srcsize));
}

__device__ __forceinline__ void ldsm4(unsigned& r0, unsigned& r1, unsigned& r2, unsigned& r3,
                                      unsigned addr) {
    asm volatile("ldmatrix.sync.aligned.m8n8.x4.shared.b16 {%0,%1,%2,%3}, [%4];"
                 : "=r"(r0), "=r"(r1), "=r"(r2), "=r"(r3) : "r"(addr));
}

__global__ void k_zero() {
    int i = blockIdx.x * blockDim.x + threadIdx.x;
    if (i < 65536) g_hist[i] = 0;
    if (i == 0) g_cand_cnt = 0;
}

__global__ void k_prep_w(const float* __restrict__ Wt) {
    int i = blockIdx.x * blockDim.x + threadIdx.x;
    if (i >= 512 * KC) return;
    int m = i / KC, r = i - m * KC;
    int t9 = r >> 10, ci = r & 1023;
    float w = Wt[(size_t)m * KC + ci * 9 + t9];
    __nv_bfloat16 hi = __float2bfloat16_rn(w);
    __nv_bfloat16 lo = __float2bfloat16_rn(w - __bfloat162float(hi));
    size_t base = (size_t)m * KW;
    g_wsplit[base + r] = hi;
    g_wsplit[base + KC + r] = lo;
}

__global__ void k_prep_x(const float* __restrict__ X) {
    __shared__ float tile[32][33];
    int tx = threadIdx.x, ty = threadIdx.y;
    int p0 = blockIdx.x * 32, c0 = blockIdx.y * 32;
#pragma unroll
    for (int j = 0; j < 32; j += 8) tile[ty + j][tx] = X[(size_t)(c0 + ty + j) * HW + p0 + tx];
    __syncthreads();
#pragma unroll
    for (int j = 0; j < 32; j += 8) {
        float v = tile[tx][ty + j];
        size_t o = (size_t)(p0 + ty + j) * CIN + c0 + tx;
        g_feat_t[o] = v;
        __nv_bfloat16 hi = __float2bfloat16_rn(v);
        g_xhi_t[o] = hi;
        g_xlo_t[o] = __float2bfloat16_rn(v - __bfloat162float(hi));
    }
}

__global__ void k_prep_hw(const float* __restrict__ cw, const float* __restrict__ bw) {
    int i = blockIdx.x * blockDim.x + threadIdx.x;
    if (i >= 105 * FCD) return;
    int o = i / FCD, k = i - o * FCD;
    g_hwT[i] = (o < 21) ? cw[k * 21 + o] : bw[k * 84 + (o - 21)];
}

// conv3x3 implicit GEMM (round-14, unchanged)
__global__ void __launch_bounds__(512, 1) k_conv3x3_mma(const float* __restrict__ bias) {
    extern __shared__ __nv_bfloat16 sm[];
    unsigned smb = (unsigned)__cvta_generic_to_shared(sm);
    int tid = threadIdx.x;
    int lane = tid & 31, warp = tid >> 5;
    int n0 = blockIdx.x * 256, m0 = blockIdx.y * 128;
    int wm = (warp & 1) * 64, wn = (warp >> 1) * 32;
    int g = lane >> 2, tq = lane & 3;
    int pix = tid >> 1, half = tid & 1;
    int p = n0 + pix;
    bool pv = p < HW;
    int py = p / WW, px = p - py * WW;

    int arow = (lane & 7) + ((lane >> 3) & 1) * 8;
    int ak = (lane >> 4) * 8;
    int brow = (lane & 7) + (lane >> 4) * 8;
    int bk = ((lane >> 3) & 1) * 8;
    unsigned aBase = smb + (unsigned)((wm + arow) * CSTR + ak) * 2;
    unsigned bBase = smb + (unsigned)(2 * ASZE) * 2 + (unsigned)((wn + brow) * CSTR + bk) * 2;

    float c[4][4][4];
#pragma unroll
    for (int mt = 0; mt < 4; mt++)
#pragma unroll
        for (int nt = 0; nt < 4; nt++)
#pragma unroll
            for (int u = 0; u < 4; u++) c[mt][nt][u] = 0.f;

    const int NCH = 288;

    auto fill = [&](int ch, int st) {
        bool hi = ch < 144;
        int rem = hi ? ch : ch - 144;
        int tap = rem >> 4;
        int ci0 = (rem & 15) << 6;
        int k = tap * 1024 + ci0;
        unsigned ab = smb + (unsigned)(st * STGB);
        unsigned a1b = ab + ASZE * 2;
        unsigned bb = ab + 2 * ASZE * 2;
#pragma unroll
        for (int u = 0; u < 2; u++) {
            int idx = u * 512 + tid;
            int m = idx >> 3, oct = idx & 7;
            cp16(ab + (unsigned)(m * CSTR + oct * 8) * 2,
                 &g_wsplit[(size_t)(m0 + m) * KW + k + oct * 8], 16);
        }
        if (hi) {
#pragma unroll
            for (int u = 0; u < 2; u++) {
                int idx = u * 512 + tid;
                int m = idx >> 3, oct = idx & 7;
                cp16(a1b + (unsigned)(m * CSTR + oct * 8) * 2,
                     &g_wsplit[(size_t)(m0 + m) * KW + KC + k + oct * 8], 16);
            }
        }
        const __nv_bfloat16* Xp = hi ? g_xhi_t : g_xlo_t;
        int t3 = tap / 3;
        int yy = py + t3 - 1, xx = px + (tap - t3 * 3 - 1);
        bool v = pv && (unsigned)yy < HH && (unsigned)xx < WW;
        const __nv_bfloat16* src = v ? &Xp[(size_t)(yy * WW + xx) * CIN + ci0 + half * 32] : Xp;
        int sz = v ? 16 : 0;
        unsigned brw = bb + (unsigned)(pix * CSTR + half * 32) * 2;
#pragma unroll
        for (int u = 0; u < 4; u++) cp16(brw + u * 16, src + u * 8, sz);
    };

    fill(0, 0);
    asm volatile("cp.async.commit_group;");
    fill(1, 1);
    asm volatile("cp.async.commit_group;");

    for (int ch = 0; ch < NCH; ch++) {
        int st = ch % 3;
        if (ch + 1 < NCH) asm volatile("cp.async.wait_group 1;");
        else asm volatile("cp.async.wait_group 0;");
        __syncthreads();
        if (ch + 2 < NCH) {
            fill(ch + 2, (ch + 2) % 3);
            asm volatile("cp.async.commit_group;");
        }
        unsigned sb = (unsigned)(st * STGB);
        bool hi = ch < 144;
#pragma unroll
        for (int ko = 0; ko < 64; ko += 16) {
            unsigned kb = (unsigned)(ko * 2);
            unsigned b[4][2];
            ldsm4(b[0][0], b[0][1], b[1][0], b[1][1], bBase + sb + kb);
            ldsm4(b[2][0], b[2][1], b[3][0], b[3][1], bBase + sb + kb + 16 * CSTR * 2);
            unsigned a[4][4];
#pragma unroll
            for (int mt = 0; mt < 4; mt++)
                ldsm4(a[mt][0], a[mt][1], a[mt][2], a[mt][3],
                      aBase + sb + kb + (unsigned)(mt * 16 * CSTR) * 2);
#pragma unroll
            for (int mt = 0; mt < 4; mt++)
#pragma unroll
                for (int nt = 0; nt < 4; nt++) {
                    asm volatile(
                        "mma.sync.aligned.m16n8k16.row.col.f32.bf16.bf16.f32 "
                        "{%0,%1,%2,%3}, {%4,%5,%6,%7}, {%8,%9}, {%0,%1,%2,%3};"
                        : "+f"(c[mt][nt][0]), "+f"(c[mt][nt][1]),
                          "+f"(c[mt][nt][2]), "+f"(c[mt][nt][3])
                        : "r"(a[mt][0]), "r"(a[mt][1]), "r"(a[mt][2]), "r"(a[mt][3]),
                          "r"(b[nt][0]), "r"(b[nt][1]));
                }
            if (hi) {
#pragma unroll
                for (int mt = 0; mt < 4; mt++)
                    ldsm4(a[mt][0], a[mt][1], a[mt][2], a[mt][3],
                          aBase + sb + kb + (unsigned)(ASZE * 2) + (unsigned)(mt * 16 * CSTR) * 2);
#pragma unroll
                for (int mt = 0; mt < 4; mt++)
#pragma unroll
                    for (int nt = 0; nt < 4; nt++) {
                        asm volatile(
                            "mma.sync.aligned.m16n8k16.row.col.f32.bf16.bf16.f32 "
                            "{%0,%1,%2,%3}, {%4,%5,%6,%7}, {%8,%9}, {%0,%1,%2,%3};"
                            : "+f"(c[mt][nt][0]), "+f"(c[mt][nt][1]),
                              "+f"(c[mt][nt][2]), "+f"(c[mt][nt][3])
                            : "r"(a[mt][0]), "r"(a[mt][1]), "r"(a[mt][2]), "r"(a[mt][3]),
                              "r"(b[nt][0]), "r"(b[nt][1]));
                    }
            }
        }
    }
    __syncthreads();
#pragma unroll
    for (int mt = 0; mt < 4; mt++) {
#pragma unroll
        for (int nt = 0; nt < 4; nt++) {
            int m = m0 + wm + mt * 16 + g;
            int pp = n0 + wn + nt * 8 + tq * 2;
            float bv0 = bias[m], bv1 = bias[m + 8];
            float v0 = fmaxf(c[mt][nt][0] + bv0, 0.f);
            float v1 = fmaxf(c[mt][nt][1] + bv0, 0.f);
            float v2 = fmaxf(c[mt][nt][2] + bv1, 0.f);
            float v3 = fmaxf(c[mt][nt][3] + bv1, 0.f);
            if (pp + 1 < HW) {
                *reinterpret_cast<float2*>(&g_rpn[(size_t)m * HW + pp]) = make_float2(v0, v1);
                *reinterpret_cast<float2*>(&g_rpn[(size_t)(m + 8) * HW + pp]) = make_float2(v2, v3);
            } else if (pp < HW) {
                g_rpn[(size_t)m * HW + pp] = v0;
                g_rpn[(size_t)(m + 8) * HW + pp] = v2;
            }
        }
    }
}

__global__ void __launch_bounds__(128) k_conv1x1(const float* __restrict__ cw,
                                                 const float* __restrict__ cb,
                                                 const float* __restrict__ bw,
                                                 const float* __restrict__ bb) {
    __shared__ float ws[27 * 128];
    int tid = threadIdx.x;
    int p = blockIdx.x * 128 + tid;
    bool pv = p < HW;
    int half = blockIdx.y;
    float acc[27];
#pragma unroll
    for (int c = 0; c < 27; c++) {
        int oc = half * 27 + c;
        acc[c] = (oc < 18) ? cb[oc] : bb[oc - 18];
    }
    for (int kc = 0; kc < 512; kc += 128) {
        __syncthreads();
#pragma unroll
        for (int c = 0; c < 27; c++) {
            int oc = half * 27 + c;
            ws[c * 128 + tid] = (oc < 18) ? cw[oc * 512 + kc + tid] : bw[(oc - 18) * 512 + kc + tid];
        }
        __syncthreads();
        for (int k = 0; k < 128; k++) {
            float rv = pv ? g_rpn[(size_t)(kc + k) * HW + p] : 0.f;
#pragma unroll
            for (int c = 0; c < 27; c++) acc[c] = fmaf(rv, ws[c * 128 + k], acc[c]);
        }
    }
    if (pv) {
#pragma unroll
        for (int c = 0; c < 27; c++) {
            int oc = half * 27 + c;
            if (oc < 18) g_cls[oc * HW + p] = acc[c];
            else g_bbox[(oc - 18) * HW + p] = acc[c];
        }
    }
}

__global__ void k_fgboxes(const float* __restrict__ anchors) {
    int i = blockIdx.x * blockDim.x + threadIdx.x;
    if (i >= NANCH) return;
    int p = i / AA, a = i - p * AA;
    float s0 = g_cls[a * HW + p], s1 = g_cls[(9 + a) * HW + p];
    float m = fmaxf(s0, s1);
    float e0 = expf(s0 - m), e1 = expf(s1 - m);
    float fg = e1 / (e0 + e1);
    unsigned int u = __float_as_uint(fg);
    u = (u & 0x80000000u) ? ~u : (u | 0x80000000u);
    g_key[i] = u;
    atomicAdd(&g_hist[u >> 16], 1);
    float ax1 = anchors[i * 4], ay1 = anchors[i * 4 + 1];
    float ax2 = anchors[i * 4 + 2], ay2 = anchors[i * 4 + 3];
    float aw = ax2 - ax1 + 1.f, ah = ay2 - ay1 + 1.f;
    float acx = ax1 + 0.5f * aw, acy = ay1 + 0.5f * ah;
    float dx = g_bbox[(4 * a) * HW + p], dy = g_bbox[(4 * a + 1) * HW + p];
    float dw = g_bbox[(4 * a + 2) * HW + p], dh = g_bbox[(4 * a + 3) * HW + p];
    float pcx = dx * aw + acx, pcy = dy * ah + acy;
    float pw = expf(dw) * aw, ph = expf(dh) * ah;
    g_boxes[i * 4 + 0] = fminf(fmaxf(pcx - 0.5f * pw, 0.f), 1919.f);
    g_boxes[i * 4 + 1] = fminf(fmaxf(pcy - 0.5f * ph, 0.f), 1215.f);
    g_boxes[i * 4 + 2] = fminf(fmaxf(pcx + 0.5f * pw, 0.f), 1919.f);
    g_boxes[i * 4 + 3] = fminf(fmaxf(pcy + 0.5f * ph, 0.f), 1215.f);
}

__global__ void k_scan() {
    __shared__ int cs[256];
    int t = threadIdx.x;
    int s = 0;
    for (int j = 0; j < 256; j++) s += g_hist[t * 256 + j];
    cs[t] = s;
    __syncthreads();
    if (t == 0) {
        int acc = 0, chunk = 0;
        for (int i = 255; i >= 0; i--) {
            if (acc + cs[i] >= TOPN) { chunk = i; break; }
            acc += cs[i];
        }
        int T = chunk * 256;
        for (int b = chunk * 256 + 255; b >= chunk * 256; b--) {
            if (acc + g_hist[b] >= TOPN) { T = b; break; }
            acc += g_hist[b];
        }
        g_thr_bin = T;
    }
}

__global__ void k_compact() {
    int i = blockIdx.x * blockDim.x + threadIdx.x;
    if (i >= NANCH) return;
    unsigned int u = g_key[i];
    if ((int)(u >> 16) >= g_thr_bin) {
        int pos = atomicAdd(&g_cand_cnt, 1);
        g_ckey[pos] = u;
        g_cidx[pos] = i;
    }
}

__global__ void k_rank() {
    int c = g_cand_cnt;
    int i = blockIdx.x * blockDim.x + threadIdx.x;
    if (i >= c) return;
    unsigned int ki = g_ckey[i];
    int di = g_cidx[i];
    int rank = 0;
    for (int j = 0; j < c; j++) {
        unsigned int kj = g_ckey[j];
        if (kj > ki || (kj == ki && g_cidx[j] < di)) rank++;
    }
    if (rank < TOPN) {
        g_rois[rank * 4 + 0] = g_boxes[di * 4 + 0];
        g_rois[rank * 4 + 1] = g_boxes[di * 4 + 1];
        g_rois[rank * 4 + 2] = g_boxes[di * 4 + 2];
        g_rois[rank * 4 + 3] = g_boxes[di * 4 + 3];
    }
}

__global__ void __launch_bounds__(256) k_roialign() {
    int r = blockIdx.y, q = blockIdx.x;
    int pyy = q / 7, pxx = q - pyy * 7;
    float x1 = g_rois[r * 4 + 0] * 0.0625f, y1 = g_rois[r * 4 + 1] * 0.0625f;
    float x2 = g_rois[r * 4 + 2] * 0.0625f, y2 = g_rois[r * 4 + 3] * 0.0625f;
    float xs = fminf(fmaxf(x1 + (x2 - x1) * ((pxx + 0.5f) / 7.f), 0.f), 119.f);
    float ys = fminf(fmaxf(y1 + (y2 - y1) * ((pyy + 0.5f) / 7.f), 0.f), 75.f);
    float x0f = floorf(xs), y0f = floorf(ys);
    int x0i = (int)x0f, y0i = (int)y0f;
    int x1i = min(x0i + 1, 119), y1i = min(y0i + 1, 75);
    float wx = xs - x0f, wy = ys - y0f;
    float w00 = (1.f - wy) * (1.f - wx), w01 = (1.f - wy) * wx;
    float w10 = wy * (1.f - wx), w11 = wy * wx;
    const float* f00 = &g_feat_t[(size_t)(y0i * WW + x0i) * CIN];
    const float* f01 = &g_feat_t[(size_t)(y0i * WW + x1i) * CIN];
    const float* f10 = &g_feat_t[(size_t)(y1i * WW + x0i) * CIN];
    const float* f11 = &g_feat_t[(size_t)(y1i * WW + x1i) * CIN];
    __nv_bfloat16* outp = &g_pooledh[(size_t)r * KFC + q * 1024];
    for (int c = threadIdx.x; c < CIN; c += 256) {
        float v = f00[c] * w00 + f01[c] * w01 + f10[c] * w10 + f11[c] * w11;
        outp[c] = __float2bfloat16_rn(v);
    }
}

// FC GEMM v2: grid (32 n-blocks of 64, 4 z), 256 threads, block M=384 (warp 96x32),
// 3-stage cp.async (A bf16 + B raw fp32, cvt at fragment read), one sync/chunk.
__global__ void __launch_bounds__(256, 1) k_fcgemm(const float* __restrict__ Bw) {
    extern __shared__ char smf[];
    unsigned smb = (unsigned)__cvta_generic_to_shared(smf);
    int tid = threadIdx.x;
    int lane = tid & 31, warp = tid >> 5;
    int n0 = blockIdx.x * 64;
    int kz = blockIdx.y * KPZ;
    int wm = (warp & 3) * 96, wn = (warp >> 2) * 32;
    int g = lane >> 2, tq = lane & 3;
    int mlim = TOPN - wm;

    int arow = (lane & 7) + ((lane >> 3) & 1) * 8;
    int ak = (lane >> 4) * 8;
    unsigned aBase = smb + (unsigned)((wm + arow) * 40 + ak) * 2;

    float c[6][4][4];
#pragma unroll
    for (int mt = 0; mt < 6; mt++)
#pragma unroll
        for (int nt = 0; nt < 4; nt++)
#pragma unroll
            for (int u = 0; u < 4; u++) c[mt][nt][u] = 0.f;

    const int NCH = KPZ / 32;  // 392

    auto fill = [&](int ch, int st) {
        int ks = ch * 32;
        unsigned ab = smb + (unsigned)(st * FC_STG);
        unsigned bb = ab + FC_ASTG;
        // A: 384 rows x 32 bf16 = 1536 cp16, 6/thread
#pragma unroll
        for (int u = 0; u < 6; u++) {
            int idx = u * 256 + tid;
            int m = idx >> 2, q = idx & 3;
            int mc = m < TOPN ? m : TOPN - 1;
            cp16(ab + (unsigned)(m * 40 + q * 8) * 2,
                 &g_pooledh[(size_t)mc * KFC + kz + ks + q * 8], m < TOPN ? 16 : 0);
        }
        // B: 32 k-rows x 64 fp32 = 512 cp16, 2/thread
#pragma unroll
        for (int u = 0; u < 2; u++) {
            int idx = u * 256 + tid;
            int k = idx >> 4, q = idx & 15;
            int kp = kz + ks + k;
            int ok = (kp & 1023) * 49 + (kp >> 10);
            cp16(bb + (unsigned)(k * 68 + q * 4) * 4,
                 &Bw[(size_t)ok * FCD + n0 + q * 4], 16);
        }
    };

    fill(0, 0);
    asm volatile("cp.async.commit_group;");
    fill(1, 1);
    asm volatile("cp.async.commit_group;");

    for (int ch = 0; ch < NCH; ch++) {
        int st = ch % 3;
        if (ch + 1 < NCH) asm volatile("cp.async.wait_group 1;");
        else asm volatile("cp.async.wait_group 0;");
        __syncthreads();
        if (ch + 2 < NCH) {
            fill(ch + 2, (ch + 2) % 3);
            asm volatile("cp.async.commit_group;");
        }
        unsigned sb = (unsigned)(st * FC_STG);
        const float* Bsf = reinterpret_cast<const float*>(smf + st * FC_STG + FC_ASTG);
#pragma unroll
        for (int ko = 0; ko < 32; ko += 16) {
            unsigned b[4][2];
#pragma unroll
            for (int nt = 0; nt < 4; nt++) {
                int n = wn + nt * 8 + g;
                float f0 = Bsf[(ko + tq * 2) * 68 + n];
                float f1 = Bsf[(ko + tq * 2 + 1) * 68 + n];
                asm("cvt.rn.bf16x2.f32 %0, %1, %2;" : "=r"(b[nt][0]) : "f"(f1), "f"(f0));
                float f2 = Bsf[(ko + tq * 2 + 8) * 68 + n];
                float f3 = Bsf[(ko + tq * 2 + 9) * 68 + n];
                asm("cvt.rn.bf16x2.f32 %0, %1, %2;" : "=r"(b[nt][1]) : "f"(f3), "f"(f2));
            }
            unsigned a[6][4];
#pragma unroll
            for (int mt = 0; mt < 6; mt++) {
                if (mt * 16 >= mlim) continue;
                ldsm4(a[mt][0], a[mt][1], a[mt][2], a[mt][3],
                      aBase + sb + (unsigned)(ko * 2) + (unsigned)(mt * 16 * 40) * 2);
            }
#pragma unroll
            for (int mt = 0; mt < 6; mt++) {
                if (mt * 16 >= mlim) continue;
#pragma unroll
                for (int nt = 0; nt < 4; nt++) {
                    asm volatile(
                        "mma.sync.aligned.m16n8k16.row.col.f32.bf16.bf16.f32 "
                        "{%0,%1,%2,%3}, {%4,%5,%6,%7}, {%8,%9}, {%0,%1,%2,%3};"
                        : "+f"(c[mt][nt][0]), "+f"(c[mt][nt][1]),
                          "+f"(c[mt][nt][2]), "+f"(c[mt][nt][3])
                        : "r"(a[mt][0]), "r"(a[mt][1]), "r"(a[mt][2]), "r"(a[mt][3]),
                          "r"(b[nt][0]), "r"(b[nt][1]));
                }
            }
        }
    }
#pragma unroll
    for (int mt = 0; mt < 6; mt++) {
#pragma unroll
        for (int nt = 0; nt < 4; nt++) {
            int m = wm + mt * 16 + g;
            int n = n0 + wn + nt * 8 + tq * 2;
            if (m < TOPN) {
                float2 v = make_float2(c[mt][nt][0], c[mt][nt][1]);
                *reinterpret_cast<float2*>(&g_fcp[((size_t)blockIdx.y * 384 + m) * FCD + n]) = v;
            }
            if (m + 8 < TOPN) {
                float2 v = make_float2(c[mt][nt][2], c[mt][nt][3]);
                *reinterpret_cast<float2*>(&g_fcp[((size_t)blockIdx.y * 384 + m + 8) * FCD + n]) = v;
            }
        }
    }
}

__global__ void k_fcreduce(const float* __restrict__ fb) {
    int i = blockIdx.x * blockDim.x + threadIdx.x;
    if (i >= TOPN * FCD) return;
    int m = i / FCD, n = i - m * FCD;
    float s = fb[n];
#pragma unroll
    for (int z = 0; z < ZSPLIT; z++) s += g_fcp[((size_t)z * 384 + m) * FCD + n];
    g_fc7[i] = s > 0.f ? s : 0.f;
}

__global__ void __launch_bounds__(128) k_heads(const float* __restrict__ cb, const float* __restrict__ bb,
                                               const float* __restrict__ tgt, const float* __restrict__ biw,
                                               const float* __restrict__ bow, const int* __restrict__ lab) {
    __shared__ float sf[FCD];
    __shared__ float so[112];
    int r = blockIdx.x, t = threadIdx.x;
    int warp = t >> 5, lane = t & 31;
    for (int k = t; k < FCD; k += 128) sf[k] = g_fc7[(size_t)r * FCD + k];
    __syncthreads();
    for (int o = warp; o < 105; o += 4) {
        const float* wp = &g_hwT[(size_t)o * FCD];
        float acc = 0.f;
        for (int k = lane; k < FCD; k += 32) acc = fmaf(sf[k], wp[k], acc);
#pragma unroll
        for (int off = 16; off > 0; off >>= 1)
            acc += __shfl_xor_sync(0xffffffffu, acc, off);
        if (lane == 0) so[o] = acc + ((o < 21) ? cb[o] : bb[o - 21]);
    }
    __syncthreads();
    if (t == 0) {
        float m = so[0];
        for (int c = 1; c < 21; c++) m = fmaxf(m, so[c]);
        float se = 0.f;
        for (int c = 0; c < 21; c++) se += expf(so[c] - m);
        float lse = m + logf(se);
        g_ce2[r] = lse - so[lab[r]];
        float lb = 0.f;
        for (int o = 0; o < 84; o++) {
            int idx = r * 84 + o;
            float d = biw[idx] * (so[21 + o] - tgt[idx]);
            float ad = fabsf(d);
            float loss = (ad < 1.f) ? d * d * 0.5f : (ad - 0.5f);
            lb += bow[idx] * loss;
        }
        g_lbrow[r] = lb;
    }
}

__global__ void __launch_bounds__(256) k_loss1(const int* __restrict__ lab, const float* __restrict__ tgt,
                                               const float* __restrict__ biw, const float* __restrict__ bow) {
    __shared__ float sce[256], scn[256], slb[256];
    int t = threadIdx.x;
    int gid = blockIdx.x * 256 + t;
    int stride = NB_RED * 256;
    float ce = 0.f, cn = 0.f, lb = 0.f;
    for (int e = gid; e < 36 * HW; e += stride) {
        int p = e / 36, c = e - p * 36;
        float d = biw[e] * (g_bbox[c * HW + p] - tgt[e]);
        float ad = fabsf(d);
        float loss = (ad < (1.f / 9.f)) ? d * d * 4.5f : (ad - 1.f / 18.f);
        lb += bow[e] * loss;
        if (e < NANCH) {
            int L = lab[e];
            if (L != -1) {
                int a = e / HW, pp = e - a * HW;
                float s0 = g_cls[a * HW + pp], s1 = g_cls[(9 + a) * HW + pp];
                float m = fmaxf(s0, s1);
                float lse = m + logf(expf(s0 - m) + expf(s1 - m));
                ce += lse - (L ? s1 : s0);
                cn += 1.f;
            }
        }
    }
    sce[t] = ce; scn[t] = cn; slb[t] = lb;
    __syncthreads();
    for (int o = 128; o > 0; o >>= 1) {
        if (t < o) { sce[t] += sce[t + o]; scn[t] += scn[t + o]; slb[t] += slb[t + o]; }
        __syncthreads();
    }
    if (t == 0) {
        g_red_ce[blockIdx.x] = sce[0];
        g_red_cnt[blockIdx.x] = scn[0];
        g_red_lb[blockIdx.x] = slb[0];
    }
}

__global__ void k_final(float* out) {
    if (threadIdx.x != 0) return;
    float ce = 0.f, cn = 0.f, lb = 0.f;
    for (int i = 0; i < NB_RED; i++) { ce += g_red_ce[i]; cn += g_red_cnt[i]; lb += g_red_lb[i]; }
    float ce2 = 0.f, lb2 = 0.f;
    for (int r = 0; r < TOPN; r++) { ce2 += g_ce2[r]; lb2 += g_lbrow[r]; }
    out[0] = ce / fmaxf(cn, 1.f) + lb + ce2 / TOPN + lb2 / TOPN;
}

extern "C" void kernel_launch(void* const* d_in, const int* in_sizes, int n_in,
                              void* d_out, int out_size) {
    const float* net_conv = (const float*)d_in[0];
    const float* rpn_w = (const float*)d_in[1];
    const float* rpn_b = (const float*)d_in[2];
    const float* rpn_cls_w = (const float*)d_in[3];
    const float* rpn_cls_b = (const float*)d_in[4];
    const float* rpn_bbox_w = (const float*)d_in[5];
    const float* rpn_bbox_b = (const float*)d_in[6];
    const float* fc_w = (const float*)d_in[7];
    const float* fc_b = (const float*)d_in[8];
    const float* cls_w = (const float*)d_in[9];
    const float* cls_b = (const float*)d_in[10];
    const float* bbox_w = (const float*)d_in[11];
    const float* bbox_b = (const float*)d_in[12];
    const float* anchors = (const float*)d_in[13];
    const float* rpn_tgt = (const float*)d_in[14];
    const float* rpn_biw = (const float*)d_in[15];
    const float* rpn_bow = (const float*)d_in[16];
    const float* roi_tgt = (const float*)d_in[17];
    const float* roi_biw = (const float*)d_in[18];
    const float* roi_bow = (const float*)d_in[19];
    const int* rpn_lab = (const int*)d_in[20];
    const int* roi_lab = (const int*)d_in[21];
    float* out = (float*)d_out;

    cudaFuncSetAttribute(k_conv3x3_mma, cudaFuncAttributeMaxDynamicSharedMemorySize, CONV_SMEM);
    cudaFuncSetAttribute(k_fcgemm, cudaFuncAttributeMaxDynamicSharedMemorySize, FC_SMEM);

    k_zero<<<256, 256>>>();
    k_prep_w<<<(512 * KC + 255) / 256, 256>>>(rpn_w);
    k_prep_x<<<dim3(285, 32), dim3(32, 8)>>>(net_conv);
    k_conv3x3_mma<<<dim3(36, 4), 512, CONV_SMEM>>>(rpn_b);
    k_prep_hw<<<(105 * FCD + 255) / 256, 256>>>(cls_w, bbox_w);
    k_conv1x1<<<dim3(72, 2), 128>>>(rpn_cls_w, rpn_cls_b, rpn_bbox_w, rpn_bbox_b);
    k_fgboxes<<<321, 256>>>(anchors);
    k_scan<<<1, 256>>>();
    k_compact<<<321, 256>>>();
    k_rank<<<321, 256>>>();
    k_roialign<<<dim3(49, TOPN), 256>>>();
    k_fcgemm<<<dim3(32, ZSPLIT), 256, FC_SMEM>>>(fc_w);
    k_fcreduce<<<(TOPN * FCD + 255) / 256, 256>>>(fc_b);
    k_heads<<<TOPN, 128>>>(cls_b, bbox_b, roi_tgt, roi_biw, roi_bow, roi_lab);
    k_loss1<<<NB_RED, 256>>>(rpn_lab, rpn_tgt, rpn_biw, rpn_bow);
    k_final<<<1, 32>>>(out);
}